// round 2
// baseline (speedup 1.0000x reference)
#include <cuda_runtime.h>
#include <cuda_bf16.h>

// ---------------------------------------------------------------------------
// Swin-style 3D block: LN1 -> roll(-2) -> box partition -> QKV -> windowed
// attention(+mask) -> proj -> box reverse -> roll(+2) -> 0.5x + residual ->
// LN2 -> MLP(gelu) -> 0.5x + residual.
// B=4, R=32, C=96, W=4, HEADS=4, dh=24, N=64 tokens/window, 2048 windows.
// T = 131072 tokens total.
// ---------------------------------------------------------------------------

#define T_TOKENS 131072

// Scratch (device globals; allocation-free per harness rules)
__device__ float g_boxes[131072 * 96];   // LN1'd, box-partitioned  (also reused as LN2 out)
__device__ float g_qkv[131072 * 288];    // qkv in box layout
__device__ float g_att[131072 * 96];     // attention output, box layout
__device__ float g_x[131072 * 96];       // residual after attention, token layout
__device__ float g_h1[131072 * 384];     // mlp hidden

// Map box-layout row r = w*64+n  ->  token index (includes the +2 roll both ways,
// since partition gathers from roll(-2) and reverse scatters through roll(+2)).
__device__ __forceinline__ int box_to_token(int r) {
    int w = r >> 6, n = r & 63;
    int b  = w >> 9;
    int bi = (w >> 6) & 7, bj = (w >> 3) & 7, bk = w & 7;
    int wi = n >> 4, wj = (n >> 2) & 3, wk = n & 3;
    int i = (bi * 4 + wi + 2) & 31;
    int j = (bj * 4 + wj + 2) & 31;
    int k = (bk * 4 + wk + 2) & 31;
    return ((b * 32 + i) * 32 + j) * 32 + k;
}

__device__ __forceinline__ float gelu_tanh(float x) {
    // matches jax.nn.gelu(approximate=True)
    const float k0 = 0.7978845608028654f;  // sqrt(2/pi)
    const float k1 = 0.044715f;
    float x3 = x * x * x;
    float t = tanhf(k0 * (x + k1 * x3));
    return 0.5f * x * (1.0f + t);
}

// ---------------------------------------------------------------------------
// LayerNorm over C=96, warp per row. PART=true: dest row is box layout, source
// row is the (rolled) token. PART=false: identity mapping (LN2).
// ---------------------------------------------------------------------------
template <bool PART>
__global__ void __launch_bounds__(256) ln_kernel(const float* __restrict__ in,
                                                 const float* __restrict__ gg,
                                                 const float* __restrict__ bb,
                                                 float* __restrict__ out) {
    int warp = threadIdx.x >> 5, lane = threadIdx.x & 31;
    int r = blockIdx.x * 8 + warp;
    int s = PART ? box_to_token(r) : r;
    const float* src = in + (size_t)s * 96;
    float v0 = src[lane], v1 = src[lane + 32], v2 = src[lane + 64];
    float s1 = v0 + v1 + v2;
    float s2 = v0 * v0 + v1 * v1 + v2 * v2;
#pragma unroll
    for (int off = 16; off; off >>= 1) {
        s1 += __shfl_xor_sync(0xffffffffu, s1, off);
        s2 += __shfl_xor_sync(0xffffffffu, s2, off);
    }
    float mean = s1 * (1.0f / 96.0f);
    float var  = s2 * (1.0f / 96.0f) - mean * mean;
    float inv  = rsqrtf(var + 1e-5f);
    float* dst = out + (size_t)r * 96;
    dst[lane]      = (v0 - mean) * inv * gg[lane]      + bb[lane];
    dst[lane + 32] = (v1 - mean) * inv * gg[lane + 32] + bb[lane + 32];
    dst[lane + 64] = (v2 - mean) * inv * gg[lane + 64] + bb[lane + 64];
}

// ---------------------------------------------------------------------------
// Register-tiled fp32 GEMM: out[M,NTOT] = A[M,KTOT] @ W[KTOT,NTOT] + bias.
// Block tile: 64 rows x 96 cols. 256 threads; each warp owns 8 consecutive
// rows, each thread 8 rows x 3 cols (cols lane, lane+32, lane+64).
// W panel (96x96) staged in smem; A read as uniform (per-warp broadcast) LDGs.
// MODE: 0 plain+bias | 1 proj (box->token scatter, 0.5x + residual)
//       2 gelu | 3 final (0.5x + residual, token layout)
// ---------------------------------------------------------------------------
template <int KTOT, int NTOT, int MODE>
__global__ void __launch_bounds__(256) gemm_kernel(const float* __restrict__ A,
                                                   const float* __restrict__ W,
                                                   const float* __restrict__ bias,
                                                   float* __restrict__ out,
                                                   const float* __restrict__ res) {
    __shared__ float Ws[96 * 96];
    int warp = threadIdx.x >> 5, lane = threadIdx.x & 31;
    int rowBase = blockIdx.x * 64 + warp * 8;
    int colBase = blockIdx.y * 96;

    float acc[8][3];
#pragma unroll
    for (int i = 0; i < 8; i++) { acc[i][0] = 0.f; acc[i][1] = 0.f; acc[i][2] = 0.f; }

    const float* Ar = A + (size_t)rowBase * KTOT;

    for (int kc = 0; kc < KTOT; kc += 96) {
        for (int idx = threadIdx.x; idx < 96 * 96; idx += 256) {
            int kk = idx / 96;
            int c  = idx - kk * 96;
            Ws[idx] = W[(size_t)(kc + kk) * NTOT + colBase + c];
        }
        __syncthreads();
#pragma unroll 2
        for (int kk = 0; kk < 96; ++kk) {
            float a[8];
#pragma unroll
            for (int i = 0; i < 8; i++) a[i] = Ar[(size_t)i * KTOT + kc + kk];
            float w0 = Ws[kk * 96 + lane];
            float w1 = Ws[kk * 96 + lane + 32];
            float w2 = Ws[kk * 96 + lane + 64];
#pragma unroll
            for (int i = 0; i < 8; i++) {
                acc[i][0] = fmaf(a[i], w0, acc[i][0]);
                acc[i][1] = fmaf(a[i], w1, acc[i][1]);
                acc[i][2] = fmaf(a[i], w2, acc[i][2]);
            }
        }
        __syncthreads();
    }

    float b0 = bias[colBase + lane];
    float b1 = bias[colBase + lane + 32];
    float b2 = bias[colBase + lane + 64];

#pragma unroll
    for (int i = 0; i < 8; i++) {
        int row = rowBase + i;
        float v0 = acc[i][0] + b0, v1 = acc[i][1] + b1, v2 = acc[i][2] + b2;
        if (MODE == 0) {
            float* o = out + (size_t)row * NTOT + colBase;
            o[lane] = v0; o[lane + 32] = v1; o[lane + 64] = v2;
        } else if (MODE == 1) {
            int t = box_to_token(row);
            const float* rr = res + (size_t)t * 96;
            float* o = out + (size_t)t * 96;
            o[lane]      = 0.5f * v0 + rr[lane];
            o[lane + 32] = 0.5f * v1 + rr[lane + 32];
            o[lane + 64] = 0.5f * v2 + rr[lane + 64];
        } else if (MODE == 2) {
            float* o = out + (size_t)row * NTOT + colBase;
            o[lane]      = gelu_tanh(v0);
            o[lane + 32] = gelu_tanh(v1);
            o[lane + 64] = gelu_tanh(v2);
        } else {
            const float* rr = res + (size_t)row * 96;
            float* o = out + (size_t)row * 96;
            o[lane]      = 0.5f * v0 + rr[lane];
            o[lane + 32] = 0.5f * v1 + rr[lane + 32];
            o[lane + 64] = 0.5f * v2 + rr[lane + 64];
        }
    }
}

// ---------------------------------------------------------------------------
// Windowed attention: one block per (window, head). 64 threads = 64 query rows.
// k/v tiles and the score row buffer live in smem; softmax per thread-row.
// qkv row layout: [.., 288] = [q(4h x 24) | k(4h x 24) | v(4h x 24)].
// ---------------------------------------------------------------------------
__global__ void __launch_bounds__(64) attn_kernel(const float* __restrict__ qkv,
                                                  const float* __restrict__ mask,
                                                  float* __restrict__ out) {
    __shared__ float ks[64][24];
    __shared__ float vs[64][24];
    __shared__ float sc[64][65];

    int w = blockIdx.x >> 2;
    int h = blockIdx.x & 3;
    int n = threadIdx.x;

    const float* base = qkv + (size_t)(w * 64 + n) * 288 + h * 24;
    float q[24];
#pragma unroll
    for (int d = 0; d < 24; d++) {
        q[d]     = base[d];
        ks[n][d] = base[96 + d];
        vs[n][d] = base[192 + d];
    }
    __syncthreads();

    const float scale = 0.2041241452319315f;  // 24^-0.5
    const float* mrow = mask + (size_t)(w & 511) * 4096 + n * 64;

    float mx = -1e30f;
#pragma unroll 4
    for (int m = 0; m < 64; m++) {
        float s = 0.f;
#pragma unroll
        for (int d = 0; d < 24; d++) s = fmaf(q[d], ks[m][d], s);
        s = s * scale + mrow[m];
        sc[n][m] = s;
        mx = fmaxf(mx, s);
    }
    float sum = 0.f;
#pragma unroll 4
    for (int m = 0; m < 64; m++) {
        float e = __expf(sc[n][m] - mx);
        sc[n][m] = e;
        sum += e;
    }
    float inv = 1.0f / sum;

    float o[24];
#pragma unroll
    for (int d = 0; d < 24; d++) o[d] = 0.f;
#pragma unroll 2
    for (int m = 0; m < 64; m++) {
        float p = sc[n][m];
#pragma unroll
        for (int d = 0; d < 24; d++) o[d] = fmaf(p, vs[m][d], o[d]);
    }

    float* op = out + (size_t)(w * 64 + n) * 96 + h * 24;
#pragma unroll
    for (int d = 0; d < 24; d++) op[d] = o[d] * inv;
}

// ---------------------------------------------------------------------------
extern "C" void kernel_launch(void* const* d_in, const int* in_sizes, int n_in,
                              void* d_out, int out_size) {
    const float* inputs = (const float*)d_in[0];
    const float* n1g    = (const float*)d_in[1];
    const float* n1b    = (const float*)d_in[2];
    const float* qkv_w  = (const float*)d_in[3];
    const float* qkv_b  = (const float*)d_in[4];
    const float* proj_w = (const float*)d_in[5];
    const float* proj_b = (const float*)d_in[6];
    const float* n2g    = (const float*)d_in[7];
    const float* n2b    = (const float*)d_in[8];
    const float* w1     = (const float*)d_in[9];
    const float* b1     = (const float*)d_in[10];
    const float* w2     = (const float*)d_in[11];
    const float* b2     = (const float*)d_in[12];
    const float* mask   = (const float*)d_in[13];
    float* out = (float*)d_out;

    float *boxes, *qkv, *att, *x, *h1;
    cudaGetSymbolAddress((void**)&boxes, g_boxes);
    cudaGetSymbolAddress((void**)&qkv,   g_qkv);
    cudaGetSymbolAddress((void**)&att,   g_att);
    cudaGetSymbolAddress((void**)&x,     g_x);
    cudaGetSymbolAddress((void**)&h1,    g_h1);

    // 1. LN1 + roll(-2) + box partition  (gather)
    ln_kernel<true><<<T_TOKENS / 8, 256>>>(inputs, n1g, n1b, boxes);
    // 2. QKV GEMM: [131072,96] x [96,288]
    gemm_kernel<96, 288, 0><<<dim3(2048, 3), 256>>>(boxes, qkv_w, qkv_b, qkv, nullptr);
    // 3. Windowed attention (2048 windows x 4 heads)
    attn_kernel<<<8192, 64>>>(qkv, mask, att);
    // 4. Proj GEMM + box reverse + roll(+2) + 0.5x + shortcut -> x
    gemm_kernel<96, 96, 1><<<dim3(2048, 1), 256>>>(att, proj_w, proj_b, x, inputs);
    // 5. LN2 (token layout; reuse boxes buffer)
    ln_kernel<false><<<T_TOKENS / 8, 256>>>(x, n2g, n2b, boxes);
    // 6. MLP1 + gelu: [131072,96] x [96,384]
    gemm_kernel<96, 384, 2><<<dim3(2048, 4), 256>>>(boxes, w1, b1, h1, nullptr);
    // 7. MLP2 + 0.5x + residual -> out: [131072,384] x [384,96]
    gemm_kernel<384, 96, 3><<<dim3(2048, 1), 256>>>(h1, w2, b2, out, x);
}

// round 4
// speedup vs baseline: 1.5613x; 1.5613x over previous
#include <cuda_runtime.h>
#include <cuda_bf16.h>
#include <stdint.h>

// ---------------------------------------------------------------------------
// Swin-3D block on GB300. GEMMs via mma.sync bf16 split-precision (hi/lo).
// (tcgen05 unavailable: harness targets compute_103, not 103a.)
// B=4, R=32, C=96, W=4, HEADS=4, dh=24, N=64/window, T=131072 tokens.
// ---------------------------------------------------------------------------

#define T_TOKENS 131072

// fp32 scratch
__device__ float g_boxes[131072 * 96];
__device__ float g_qkv[131072 * 288];
__device__ float g_att[131072 * 96];
__device__ float g_x[131072 * 96];
__device__ float g_h1[131072 * 384];

// split-precision transposed weights: layout [N][K], bf16 bits
__device__ unsigned short g_wqkv_hi[288 * 96], g_wqkv_lo[288 * 96];
__device__ unsigned short g_wproj_hi[96 * 96], g_wproj_lo[96 * 96];
__device__ unsigned short g_wm1_hi[384 * 96],  g_wm1_lo[384 * 96];
__device__ unsigned short g_wm2_hi[96 * 384],  g_wm2_lo[96 * 384];

// ---------------------------------------------------------------------------
__device__ __forceinline__ int box_to_token(int r) {
    int w = r >> 6, n = r & 63;
    int b  = w >> 9;
    int bi = (w >> 6) & 7, bj = (w >> 3) & 7, bk = w & 7;
    int wi = n >> 4, wj = (n >> 2) & 3, wk = n & 3;
    int i = (bi * 4 + wi + 2) & 31;
    int j = (bj * 4 + wj + 2) & 31;
    int k = (bk * 4 + wk + 2) & 31;
    return ((b * 32 + i) * 32 + j) * 32 + k;
}

__device__ __forceinline__ float gelu_tanh(float x) {
    const float k0 = 0.7978845608028654f;
    const float k1 = 0.044715f;
    float x3 = x * x * x;
    float t = tanhf(k0 * (x + k1 * x3));
    return 0.5f * x * (1.0f + t);
}

__device__ __forceinline__ uint32_t smem_u32(const void* p) {
    uint32_t a;
    asm("{ .reg .u64 t; cvta.to.shared.u64 t, %1; cvt.u32.u64 %0, t; }"
        : "=r"(a) : "l"(p));
    return a;
}

__device__ __forceinline__ void ldmat4(uint32_t* r, uint32_t addr) {
    asm volatile("ldmatrix.sync.aligned.m8n8.x4.shared.b16 {%0,%1,%2,%3}, [%4];"
                 : "=r"(r[0]), "=r"(r[1]), "=r"(r[2]), "=r"(r[3]) : "r"(addr));
}

__device__ __forceinline__ void mma16816(float* d, const uint32_t* a,
                                         const uint32_t* b) {
    asm volatile(
        "mma.sync.aligned.m16n8k16.row.col.f32.bf16.bf16.f32 "
        "{%0,%1,%2,%3}, {%4,%5,%6,%7}, {%8,%9}, {%0,%1,%2,%3};"
        : "+f"(d[0]), "+f"(d[1]), "+f"(d[2]), "+f"(d[3])
        : "r"(a[0]), "r"(a[1]), "r"(a[2]), "r"(a[3]), "r"(b[0]), "r"(b[1]));
}

__device__ __forceinline__ void split_bf16(float x, unsigned short& h,
                                           unsigned short& l) {
    __nv_bfloat16 hb = __float2bfloat16(x);
    float r = x - __bfloat162float(hb);
    __nv_bfloat16 lb = __float2bfloat16(r);
    h = __bfloat16_as_ushort(hb);
    l = __bfloat16_as_ushort(lb);
}

// ---------------------------------------------------------------------------
// Weight prep: W[K,NTOT] fp32 -> Wt_hi/lo [NTOT][K] bf16
// ---------------------------------------------------------------------------
__global__ void prep_w(const float* __restrict__ W, int K, int NTOT,
                       unsigned short* __restrict__ hi,
                       unsigned short* __restrict__ lo) {
    int idx = blockIdx.x * 256 + threadIdx.x;
    if (idx >= NTOT * K) return;
    int n = idx / K, k = idx - n * K;
    float w = W[(size_t)k * NTOT + n];
    unsigned short h, l;
    split_bf16(w, h, l);
    hi[idx] = h;
    lo[idx] = l;
}

// ---------------------------------------------------------------------------
// LayerNorm over C=96, warp per row.
// ---------------------------------------------------------------------------
template <bool PART>
__global__ void __launch_bounds__(256) ln_kernel(const float* __restrict__ in,
                                                 const float* __restrict__ gg,
                                                 const float* __restrict__ bb,
                                                 float* __restrict__ out) {
    int warp = threadIdx.x >> 5, lane = threadIdx.x & 31;
    int r = blockIdx.x * 8 + warp;
    int s = PART ? box_to_token(r) : r;
    const float* src = in + (size_t)s * 96;
    float v0 = src[lane], v1 = src[lane + 32], v2 = src[lane + 64];
    float s1 = v0 + v1 + v2;
    float s2 = v0 * v0 + v1 * v1 + v2 * v2;
#pragma unroll
    for (int off = 16; off; off >>= 1) {
        s1 += __shfl_xor_sync(0xffffffffu, s1, off);
        s2 += __shfl_xor_sync(0xffffffffu, s2, off);
    }
    float mean = s1 * (1.0f / 96.0f);
    float var  = s2 * (1.0f / 96.0f) - mean * mean;
    float inv  = rsqrtf(var + 1e-5f);
    float* dst = out + (size_t)r * 96;
    dst[lane]      = (v0 - mean) * inv * gg[lane]      + bb[lane];
    dst[lane + 32] = (v1 - mean) * inv * gg[lane + 32] + bb[lane + 32];
    dst[lane + 64] = (v2 - mean) * inv * gg[lane + 64] + bb[lane + 64];
}

// ---------------------------------------------------------------------------
// mma.sync bf16 split-precision GEMM.
// out[M,NTOT] = A[M,KTOT] @ W[KTOT,NTOT] (+ fused epilogue)
// CTA: 128 rows x 96 cols, 256 threads (8 warps, 4x2 warp grid, 32x48 tiles).
// K chunked at 96. smem rows padded to 104 bf16 (208B) -> ldmatrix
// conflict-free. 3 passes: Ahi*Bhi + Ahi*Blo + Alo*Bhi into same fp32 accum.
// MODE: 0 bias | 1 box->token scatter, 0.5x+res | 2 bias+gelu | 3 0.5x+res
// ---------------------------------------------------------------------------
#define APAD 104
#define OFF_AHI 0
#define OFF_ALO (128 * APAD)                 // 13312 (u16 units)
#define OFF_BHI (2 * 128 * APAD)             // 26624
#define OFF_BLO (2 * 128 * APAD + 96 * APAD) // 36608
#define SMEM_U16 (2 * 128 * APAD + 2 * 96 * APAD)
#define SMEM_BYTES (SMEM_U16 * 2)            // 93184

template <int KTOT, int NTOT, int MODE>
__global__ void __launch_bounds__(256, 1) mma_gemm(
    const float* __restrict__ A,
    const unsigned short* __restrict__ Whi,
    const unsigned short* __restrict__ Wlo,
    const float* __restrict__ bias,
    float* __restrict__ out,
    const float* __restrict__ res) {
    extern __shared__ __align__(16) unsigned short sm[];
    const uint32_t sb = smem_u32(sm);

    int tid = threadIdx.x, lane = tid & 31, wid = tid >> 5;
    int warpM = wid >> 1, warpN = wid & 1;
    int rowBase = blockIdx.x * 128;
    int colBase = blockIdx.y * 96;

    float acc[2][6][4];
#pragma unroll
    for (int mt = 0; mt < 2; mt++)
#pragma unroll
        for (int nt = 0; nt < 6; nt++)
#pragma unroll
            for (int i = 0; i < 4; i++) acc[mt][nt][i] = 0.f;

    // ldmatrix lane addressing pieces
    int grp = lane >> 3, rin = lane & 7;
    int lrow = (grp & 1) * 8 + rin;     // row within 16
    int lkof = (grp >> 1) * 8;          // k offset within 16

    const int NCHUNK = KTOT / 96;
    for (int c = 0; c < NCHUNK; c++) {
        int kc = c * 96;
        __syncthreads();  // prior chunk's MMAs done before smem overwrite

        // ---- load A tile 128x96 fp32 -> hi/lo bf16 (2 elems/thread/iter) ----
#pragma unroll
        for (int it = 0; it < 24; it++) {
            int idx = it * 256 + tid;                 // 0..6143
            int r = idx / 48, kp = (idx - r * 48) * 2;
            float2 v = *(const float2*)(A + (size_t)(rowBase + r) * KTOT + kc + kp);
            unsigned short h0, l0, h1, l1;
            split_bf16(v.x, h0, l0);
            split_bf16(v.y, h1, l1);
            uint32_t hp = (uint32_t)h0 | ((uint32_t)h1 << 16);
            uint32_t lp = (uint32_t)l0 | ((uint32_t)l1 << 16);
            int off = r * APAD + kp;
            *(uint32_t*)(sm + OFF_AHI + off) = hp;
            *(uint32_t*)(sm + OFF_ALO + off) = lp;
        }
        // ---- load B tile 96x96 (already split) ----
#pragma unroll
        for (int it = 0; it < 18; it++) {
            int idx = it * 256 + tid;                 // 0..4607
            int n = idx / 48, kp = (idx - n * 48) * 2;
            size_t gi = (size_t)(colBase + n) * KTOT + kc + kp;
            uint32_t hp = *(const uint32_t*)(Whi + gi);
            uint32_t lp = *(const uint32_t*)(Wlo + gi);
            int off = n * APAD + kp;
            *(uint32_t*)(sm + OFF_BHI + off) = hp;
            *(uint32_t*)(sm + OFF_BLO + off) = lp;
        }
        __syncthreads();

        // ---- k loop: 6 steps of 16 ----
#pragma unroll
        for (int ks = 0; ks < 96; ks += 16) {
            uint32_t afh[2][4], afl[2][4];
#pragma unroll
            for (int mt = 0; mt < 2; mt++) {
                int r = warpM * 32 + mt * 16 + lrow;
                uint32_t off = (uint32_t)(r * APAD + ks + lkof) * 2;
                ldmat4(afh[mt], sb + OFF_AHI * 2 + off);
                ldmat4(afl[mt], sb + OFF_ALO * 2 + off);
            }
            uint32_t bfh[6][2], bfl[6][2];
#pragma unroll
            for (int np = 0; np < 3; np++) {
                int n = warpN * 48 + np * 16 + lrow;
                uint32_t off = (uint32_t)(n * APAD + ks + lkof) * 2;
                uint32_t t[4];
                ldmat4(t, sb + OFF_BHI * 2 + off);
                bfh[np * 2][0] = t[0]; bfh[np * 2][1] = t[2];
                bfh[np * 2 + 1][0] = t[1]; bfh[np * 2 + 1][1] = t[3];
                ldmat4(t, sb + OFF_BLO * 2 + off);
                bfl[np * 2][0] = t[0]; bfl[np * 2][1] = t[2];
                bfl[np * 2 + 1][0] = t[1]; bfl[np * 2 + 1][1] = t[3];
            }
#pragma unroll
            for (int mt = 0; mt < 2; mt++)
#pragma unroll
                for (int nt = 0; nt < 6; nt++) {
                    mma16816(acc[mt][nt], afh[mt], bfh[nt]);
                    mma16816(acc[mt][nt], afh[mt], bfl[nt]);
                    mma16816(acc[mt][nt], afl[mt], bfh[nt]);
                }
        }
    }

    // ---- epilogue: thread t of m16n8 holds rows t/4, t/4+8; cols (t%4)*2+{0,1}
    int qr = lane >> 2, qc = (lane & 3) * 2;
#pragma unroll
    for (int mt = 0; mt < 2; mt++) {
#pragma unroll
        for (int half = 0; half < 2; half++) {
            int row = rowBase + warpM * 32 + mt * 16 + qr + half * 8;
            int t = (MODE == 1) ? box_to_token(row) : row;
#pragma unroll
            for (int nt = 0; nt < 6; nt++) {
                int col = colBase + warpN * 48 + nt * 8 + qc;
                float v0 = acc[mt][nt][half * 2 + 0] + bias[col];
                float v1 = acc[mt][nt][half * 2 + 1] + bias[col + 1];
                if (MODE == 0) {
                    float2 v = {v0, v1};
                    *(float2*)(out + (size_t)row * NTOT + col) = v;
                } else if (MODE == 2) {
                    float2 v = {gelu_tanh(v0), gelu_tanh(v1)};
                    *(float2*)(out + (size_t)row * NTOT + col) = v;
                } else {
                    const float* rr = res + (size_t)t * 96 + col;
                    float2 v = {0.5f * v0 + rr[0], 0.5f * v1 + rr[1]};
                    *(float2*)(out + (size_t)t * 96 + col) = v;
                }
            }
        }
    }
}

// ---------------------------------------------------------------------------
// Windowed attention (fp32): block per (window, head), 64 threads.
// ---------------------------------------------------------------------------
__global__ void __launch_bounds__(64) attn_kernel(const float* __restrict__ qkv,
                                                  const float* __restrict__ mask,
                                                  float* __restrict__ out) {
    __shared__ float ks[64][24];
    __shared__ float vs[64][24];
    __shared__ float sc[64][65];

    int w = blockIdx.x >> 2;
    int h = blockIdx.x & 3;
    int n = threadIdx.x;

    const float* base = qkv + (size_t)(w * 64 + n) * 288 + h * 24;
    float q[24];
#pragma unroll
    for (int d = 0; d < 24; d++) {
        q[d]     = base[d];
        ks[n][d] = base[96 + d];
        vs[n][d] = base[192 + d];
    }
    __syncthreads();

    const float scale = 0.2041241452319315f;
    const float* mrow = mask + (size_t)(w & 511) * 4096 + n * 64;

    float mx = -1e30f;
#pragma unroll 4
    for (int m = 0; m < 64; m++) {
        float s = 0.f;
#pragma unroll
        for (int d = 0; d < 24; d++) s = fmaf(q[d], ks[m][d], s);
        s = s * scale + mrow[m];
        sc[n][m] = s;
        mx = fmaxf(mx, s);
    }
    float sum = 0.f;
#pragma unroll 4
    for (int m = 0; m < 64; m++) {
        float e = __expf(sc[n][m] - mx);
        sc[n][m] = e;
        sum += e;
    }
    float inv = 1.0f / sum;

    float o[24];
#pragma unroll
    for (int d = 0; d < 24; d++) o[d] = 0.f;
#pragma unroll 2
    for (int m = 0; m < 64; m++) {
        float p = sc[n][m];
#pragma unroll
        for (int d = 0; d < 24; d++) o[d] = fmaf(p, vs[m][d], o[d]);
    }

    float* op = out + (size_t)(w * 64 + n) * 96 + h * 24;
#pragma unroll
    for (int d = 0; d < 24; d++) op[d] = o[d] * inv;
}

// ---------------------------------------------------------------------------
extern "C" void kernel_launch(void* const* d_in, const int* in_sizes, int n_in,
                              void* d_out, int out_size) {
    const float* inputs = (const float*)d_in[0];
    const float* n1g    = (const float*)d_in[1];
    const float* n1b    = (const float*)d_in[2];
    const float* qkv_w  = (const float*)d_in[3];
    const float* qkv_b  = (const float*)d_in[4];
    const float* proj_w = (const float*)d_in[5];
    const float* proj_b = (const float*)d_in[6];
    const float* n2g    = (const float*)d_in[7];
    const float* n2b    = (const float*)d_in[8];
    const float* w1     = (const float*)d_in[9];
    const float* b1     = (const float*)d_in[10];
    const float* w2     = (const float*)d_in[11];
    const float* b2     = (const float*)d_in[12];
    const float* mask   = (const float*)d_in[13];
    float* out = (float*)d_out;

    float *boxes, *qkv, *att, *x, *h1;
    cudaGetSymbolAddress((void**)&boxes, g_boxes);
    cudaGetSymbolAddress((void**)&qkv,   g_qkv);
    cudaGetSymbolAddress((void**)&att,   g_att);
    cudaGetSymbolAddress((void**)&x,     g_x);
    cudaGetSymbolAddress((void**)&h1,    g_h1);

    unsigned short *wqh, *wql, *wph, *wpl, *w1h, *w1l, *w2h, *w2l;
    cudaGetSymbolAddress((void**)&wqh, g_wqkv_hi);
    cudaGetSymbolAddress((void**)&wql, g_wqkv_lo);
    cudaGetSymbolAddress((void**)&wph, g_wproj_hi);
    cudaGetSymbolAddress((void**)&wpl, g_wproj_lo);
    cudaGetSymbolAddress((void**)&w1h, g_wm1_hi);
    cudaGetSymbolAddress((void**)&w1l, g_wm1_lo);
    cudaGetSymbolAddress((void**)&w2h, g_wm2_hi);
    cudaGetSymbolAddress((void**)&w2l, g_wm2_lo);

    cudaFuncSetAttribute(mma_gemm<96, 288, 0>,
                         cudaFuncAttributeMaxDynamicSharedMemorySize, SMEM_BYTES);
    cudaFuncSetAttribute(mma_gemm<96, 96, 1>,
                         cudaFuncAttributeMaxDynamicSharedMemorySize, SMEM_BYTES);
    cudaFuncSetAttribute(mma_gemm<96, 384, 2>,
                         cudaFuncAttributeMaxDynamicSharedMemorySize, SMEM_BYTES);
    cudaFuncSetAttribute(mma_gemm<384, 96, 3>,
                         cudaFuncAttributeMaxDynamicSharedMemorySize, SMEM_BYTES);

    // 0. weight prep (split + transpose)
    prep_w<<<(288 * 96 + 255) / 256, 256>>>(qkv_w, 96, 288, wqh, wql);
    prep_w<<<(96 * 96 + 255) / 256, 256>>>(proj_w, 96, 96, wph, wpl);
    prep_w<<<(384 * 96 + 255) / 256, 256>>>(w1, 96, 384, w1h, w1l);
    prep_w<<<(96 * 384 + 255) / 256, 256>>>(w2, 384, 96, w2h, w2l);

    // 1. LN1 + roll(-2) + box partition
    ln_kernel<true><<<T_TOKENS / 8, 256>>>(inputs, n1g, n1b, boxes);
    // 2. QKV: [131072,96] x [96,288]
    mma_gemm<96, 288, 0><<<dim3(1024, 3), 256, SMEM_BYTES>>>(
        boxes, wqh, wql, qkv_b, qkv, nullptr);
    // 3. Windowed attention
    attn_kernel<<<8192, 64>>>(qkv, mask, att);
    // 4. Proj + box reverse + roll(+2) + 0.5x + shortcut
    mma_gemm<96, 96, 1><<<dim3(1024, 1), 256, SMEM_BYTES>>>(
        att, wph, wpl, proj_b, x, inputs);
    // 5. LN2
    ln_kernel<false><<<T_TOKENS / 8, 256>>>(x, n2g, n2b, boxes);
    // 6. MLP1 + gelu: [131072,96] x [96,384]
    mma_gemm<96, 384, 2><<<dim3(1024, 4), 256, SMEM_BYTES>>>(
        boxes, w1h, w1l, b1, h1, nullptr);
    // 7. MLP2 + 0.5x + residual: [131072,384] x [384,96]
    mma_gemm<384, 96, 3><<<dim3(1024, 1), 256, SMEM_BYTES>>>(
        h1, w2h, w2l, b2, out, x);
}

// round 5
// speedup vs baseline: 2.3570x; 1.5097x over previous
#include <cuda_runtime.h>
#include <cuda_bf16.h>
#include <stdint.h>

// ---------------------------------------------------------------------------
// Swin-3D block on GB300. GEMMs + attention via mma.sync bf16 split-precision.
// B=4, R=32, C=96, W=4, HEADS=4, dh=24, N=64/window, T=131072 tokens.
// ---------------------------------------------------------------------------

#define T_TOKENS 131072

// fp32 scratch
__device__ float g_boxes[131072 * 96];
__device__ float g_qkv[131072 * 288];
__device__ float g_att[131072 * 96];
__device__ float g_x[131072 * 96];
__device__ float g_h1[131072 * 384];

// split-precision transposed weights: layout [N][K], bf16 bits
__device__ unsigned short g_wqkv_hi[288 * 96], g_wqkv_lo[288 * 96];
__device__ unsigned short g_wproj_hi[96 * 96], g_wproj_lo[96 * 96];
__device__ unsigned short g_wm1_hi[384 * 96],  g_wm1_lo[384 * 96];
__device__ unsigned short g_wm2_hi[96 * 384],  g_wm2_lo[96 * 384];

// ---------------------------------------------------------------------------
__device__ __forceinline__ int box_to_token(int r) {
    int w = r >> 6, n = r & 63;
    int b  = w >> 9;
    int bi = (w >> 6) & 7, bj = (w >> 3) & 7, bk = w & 7;
    int wi = n >> 4, wj = (n >> 2) & 3, wk = n & 3;
    int i = (bi * 4 + wi + 2) & 31;
    int j = (bj * 4 + wj + 2) & 31;
    int k = (bk * 4 + wk + 2) & 31;
    return ((b * 32 + i) * 32 + j) * 32 + k;
}

__device__ __forceinline__ float gelu_tanh(float x) {
    const float k0 = 0.7978845608028654f;
    const float k1 = 0.044715f;
    float x3 = x * x * x;
    float t = tanhf(k0 * (x + k1 * x3));
    return 0.5f * x * (1.0f + t);
}

__device__ __forceinline__ uint32_t smem_u32(const void* p) {
    uint32_t a;
    asm("{ .reg .u64 t; cvta.to.shared.u64 t, %1; cvt.u32.u64 %0, t; }"
        : "=r"(a) : "l"(p));
    return a;
}

__device__ __forceinline__ void ldmat4(uint32_t* r, uint32_t addr) {
    asm volatile("ldmatrix.sync.aligned.m8n8.x4.shared.b16 {%0,%1,%2,%3}, [%4];"
                 : "=r"(r[0]), "=r"(r[1]), "=r"(r[2]), "=r"(r[3]) : "r"(addr));
}

__device__ __forceinline__ void mma16816(float* d, const uint32_t* a,
                                         const uint32_t* b) {
    asm volatile(
        "mma.sync.aligned.m16n8k16.row.col.f32.bf16.bf16.f32 "
        "{%0,%1,%2,%3}, {%4,%5,%6,%7}, {%8,%9}, {%0,%1,%2,%3};"
        : "+f"(d[0]), "+f"(d[1]), "+f"(d[2]), "+f"(d[3])
        : "r"(a[0]), "r"(a[1]), "r"(a[2]), "r"(a[3]), "r"(b[0]), "r"(b[1]));
}

__device__ __forceinline__ void split_bf16(float x, unsigned short& h,
                                           unsigned short& l) {
    __nv_bfloat16 hb = __float2bfloat16(x);
    float r = x - __bfloat162float(hb);
    __nv_bfloat16 lb = __float2bfloat16(r);
    h = __bfloat16_as_ushort(hb);
    l = __bfloat16_as_ushort(lb);
}

// ---------------------------------------------------------------------------
// Weight prep: W[K,NTOT] fp32 -> Wt_hi/lo [NTOT][K] bf16
// ---------------------------------------------------------------------------
__global__ void prep_w(const float* __restrict__ W, int K, int NTOT,
                       unsigned short* __restrict__ hi,
                       unsigned short* __restrict__ lo) {
    int idx = blockIdx.x * 256 + threadIdx.x;
    if (idx >= NTOT * K) return;
    int n = idx / K, k = idx - n * K;
    float w = W[(size_t)k * NTOT + n];
    unsigned short h, l;
    split_bf16(w, h, l);
    hi[idx] = h;
    lo[idx] = l;
}

// ---------------------------------------------------------------------------
// LayerNorm over C=96, warp per row.
// ---------------------------------------------------------------------------
template <bool PART>
__global__ void __launch_bounds__(256) ln_kernel(const float* __restrict__ in,
                                                 const float* __restrict__ gg,
                                                 const float* __restrict__ bb,
                                                 float* __restrict__ out) {
    int warp = threadIdx.x >> 5, lane = threadIdx.x & 31;
    int r = blockIdx.x * 8 + warp;
    int s = PART ? box_to_token(r) : r;
    const float* src = in + (size_t)s * 96;
    float v0 = src[lane], v1 = src[lane + 32], v2 = src[lane + 64];
    float s1 = v0 + v1 + v2;
    float s2 = v0 * v0 + v1 * v1 + v2 * v2;
#pragma unroll
    for (int off = 16; off; off >>= 1) {
        s1 += __shfl_xor_sync(0xffffffffu, s1, off);
        s2 += __shfl_xor_sync(0xffffffffu, s2, off);
    }
    float mean = s1 * (1.0f / 96.0f);
    float var  = s2 * (1.0f / 96.0f) - mean * mean;
    float inv  = rsqrtf(var + 1e-5f);
    float* dst = out + (size_t)r * 96;
    dst[lane]      = (v0 - mean) * inv * gg[lane]      + bb[lane];
    dst[lane + 32] = (v1 - mean) * inv * gg[lane + 32] + bb[lane + 32];
    dst[lane + 64] = (v2 - mean) * inv * gg[lane + 64] + bb[lane + 64];
}

// ---------------------------------------------------------------------------
// mma.sync bf16 split-precision GEMM (as R3; 128x96 tile, 8 warps).
// MODE: 0 bias | 1 box->token scatter, 0.5x+res | 2 bias+gelu | 3 0.5x+res
// ---------------------------------------------------------------------------
#define APAD 104
#define OFF_AHI 0
#define OFF_ALO (128 * APAD)
#define OFF_BHI (2 * 128 * APAD)
#define OFF_BLO (2 * 128 * APAD + 96 * APAD)
#define SMEM_U16 (2 * 128 * APAD + 2 * 96 * APAD)
#define SMEM_BYTES (SMEM_U16 * 2)

template <int KTOT, int NTOT, int MODE>
__global__ void __launch_bounds__(256, 1) mma_gemm(
    const float* __restrict__ A,
    const unsigned short* __restrict__ Whi,
    const unsigned short* __restrict__ Wlo,
    const float* __restrict__ bias,
    float* __restrict__ out,
    const float* __restrict__ res) {
    extern __shared__ __align__(16) unsigned short sm[];
    const uint32_t sb = smem_u32(sm);

    int tid = threadIdx.x, lane = tid & 31, wid = tid >> 5;
    int warpM = wid >> 1, warpN = wid & 1;
    int rowBase = blockIdx.x * 128;
    int colBase = blockIdx.y * 96;

    float acc[2][6][4];
#pragma unroll
    for (int mt = 0; mt < 2; mt++)
#pragma unroll
        for (int nt = 0; nt < 6; nt++)
#pragma unroll
            for (int i = 0; i < 4; i++) acc[mt][nt][i] = 0.f;

    int grp = lane >> 3, rin = lane & 7;
    int lrow = (grp & 1) * 8 + rin;
    int lkof = (grp >> 1) * 8;

    const int NCHUNK = KTOT / 96;
    for (int c = 0; c < NCHUNK; c++) {
        int kc = c * 96;
        __syncthreads();

#pragma unroll
        for (int it = 0; it < 24; it++) {
            int idx = it * 256 + tid;
            int r = idx / 48, kp = (idx - r * 48) * 2;
            float2 v = *(const float2*)(A + (size_t)(rowBase + r) * KTOT + kc + kp);
            unsigned short h0, l0, h1, l1;
            split_bf16(v.x, h0, l0);
            split_bf16(v.y, h1, l1);
            uint32_t hp = (uint32_t)h0 | ((uint32_t)h1 << 16);
            uint32_t lp = (uint32_t)l0 | ((uint32_t)l1 << 16);
            int off = r * APAD + kp;
            *(uint32_t*)(sm + OFF_AHI + off) = hp;
            *(uint32_t*)(sm + OFF_ALO + off) = lp;
        }
#pragma unroll
        for (int it = 0; it < 18; it++) {
            int idx = it * 256 + tid;
            int n = idx / 48, kp = (idx - n * 48) * 2;
            size_t gi = (size_t)(colBase + n) * KTOT + kc + kp;
            uint32_t hp = *(const uint32_t*)(Whi + gi);
            uint32_t lp = *(const uint32_t*)(Wlo + gi);
            int off = n * APAD + kp;
            *(uint32_t*)(sm + OFF_BHI + off) = hp;
            *(uint32_t*)(sm + OFF_BLO + off) = lp;
        }
        __syncthreads();

#pragma unroll
        for (int ks = 0; ks < 96; ks += 16) {
            uint32_t afh[2][4], afl[2][4];
#pragma unroll
            for (int mt = 0; mt < 2; mt++) {
                int r = warpM * 32 + mt * 16 + lrow;
                uint32_t off = (uint32_t)(r * APAD + ks + lkof) * 2;
                ldmat4(afh[mt], sb + OFF_AHI * 2 + off);
                ldmat4(afl[mt], sb + OFF_ALO * 2 + off);
            }
            uint32_t bfh[6][2], bfl[6][2];
#pragma unroll
            for (int np = 0; np < 3; np++) {
                int n = warpN * 48 + np * 16 + lrow;
                uint32_t off = (uint32_t)(n * APAD + ks + lkof) * 2;
                uint32_t t[4];
                ldmat4(t, sb + OFF_BHI * 2 + off);
                bfh[np * 2][0] = t[0]; bfh[np * 2][1] = t[2];
                bfh[np * 2 + 1][0] = t[1]; bfh[np * 2 + 1][1] = t[3];
                ldmat4(t, sb + OFF_BLO * 2 + off);
                bfl[np * 2][0] = t[0]; bfl[np * 2][1] = t[2];
                bfl[np * 2 + 1][0] = t[1]; bfl[np * 2 + 1][1] = t[3];
            }
#pragma unroll
            for (int mt = 0; mt < 2; mt++)
#pragma unroll
                for (int nt = 0; nt < 6; nt++) {
                    mma16816(acc[mt][nt], afh[mt], bfh[nt]);
                    mma16816(acc[mt][nt], afh[mt], bfl[nt]);
                    mma16816(acc[mt][nt], afl[mt], bfh[nt]);
                }
        }
    }

    int qr = lane >> 2, qc = (lane & 3) * 2;
#pragma unroll
    for (int mt = 0; mt < 2; mt++) {
#pragma unroll
        for (int half = 0; half < 2; half++) {
            int row = rowBase + warpM * 32 + mt * 16 + qr + half * 8;
            int t = (MODE == 1) ? box_to_token(row) : row;
#pragma unroll
            for (int nt = 0; nt < 6; nt++) {
                int col = colBase + warpN * 48 + nt * 8 + qc;
                float v0 = acc[mt][nt][half * 2 + 0] + bias[col];
                float v1 = acc[mt][nt][half * 2 + 1] + bias[col + 1];
                if (MODE == 0) {
                    float2 v = {v0, v1};
                    *(float2*)(out + (size_t)row * NTOT + col) = v;
                } else if (MODE == 2) {
                    float2 v = {gelu_tanh(v0), gelu_tanh(v1)};
                    *(float2*)(out + (size_t)row * NTOT + col) = v;
                } else {
                    const float* rr = res + (size_t)t * 96 + col;
                    float2 v = {0.5f * v0 + rr[0], 0.5f * v1 + rr[1]};
                    *(float2*)(out + (size_t)t * 96 + col) = v;
                }
            }
        }
    }
}

// ---------------------------------------------------------------------------
// Tensor-core windowed attention. One CTA per (window, head), 128 threads.
// S = Q K^T via 3-pass bf16 split (k padded 24->32); softmax on fragments;
// P re-split hi/lo in registers (FA2 accumulator->A-operand layout match);
// O = P V via 3-pass split with V^T staged in smem.
// Pad strides: Q/K 40 u16 (80B), V^T 72 u16 (144B), mask 65 f32 -> ldmatrix /
// LDS conflict-free.
// ---------------------------------------------------------------------------
__global__ void __launch_bounds__(128) attn_mma_kernel(
    const float* __restrict__ qkv,
    const float* __restrict__ mask,
    float* __restrict__ out) {
    __shared__ __align__(16) unsigned short q_hi[64 * 40], q_lo[64 * 40];
    __shared__ __align__(16) unsigned short k_hi[64 * 40], k_lo[64 * 40];
    __shared__ __align__(16) unsigned short vt_hi[32 * 72], vt_lo[32 * 72];
    __shared__ float msk[64 * 65];

    int w = blockIdx.x >> 2, h = blockIdx.x & 3;
    int tid = threadIdx.x, lane = tid & 31, wid = tid >> 5;

    // ---- load Q,K (row t, dim d; d>=24 zero-padded) ----
#pragma unroll
    for (int it = 0; it < 16; it++) {
        int idx = it * 128 + tid;
        int t = idx >> 5, d = idx & 31;
        float qv = 0.f, kv = 0.f;
        if (d < 24) {
            const float* p = qkv + (size_t)(w * 64 + t) * 288 + h * 24 + d;
            qv = p[0];
            kv = p[96];
        }
        unsigned short hh, ll;
        split_bf16(qv, hh, ll);
        q_hi[t * 40 + d] = hh; q_lo[t * 40 + d] = ll;
        split_bf16(kv, hh, ll);
        k_hi[t * 40 + d] = hh; k_lo[t * 40 + d] = ll;
    }
    // ---- load V transposed: vt[d][t] ----
#pragma unroll
    for (int it = 0; it < 16; it++) {
        int idx = it * 128 + tid;
        int t = idx >> 5, d = idx & 31;
        float vv = (d < 24)
            ? qkv[(size_t)(w * 64 + t) * 288 + h * 24 + 192 + d] : 0.f;
        unsigned short hh, ll;
        split_bf16(vv, hh, ll);
        vt_hi[d * 72 + t] = hh;
        vt_lo[d * 72 + t] = ll;
    }
    // ---- mask tile -> smem (pad 65) ----
    const float* mrow = mask + (size_t)(w & 511) * 4096;
#pragma unroll
    for (int it = 0; it < 8; it++) {
        int idx = it * 128 + tid;
        int r = idx >> 4, c4 = (idx & 15) * 4;
        float4 mv = *(const float4*)(mrow + r * 64 + c4);
        msk[r * 65 + c4 + 0] = mv.x;
        msk[r * 65 + c4 + 1] = mv.y;
        msk[r * 65 + c4 + 2] = mv.z;
        msk[r * 65 + c4 + 3] = mv.w;
    }
    __syncthreads();

    const uint32_t sq_hi = smem_u32(q_hi), sq_lo = smem_u32(q_lo);
    const uint32_t sk_hi = smem_u32(k_hi), sk_lo = smem_u32(k_lo);
    const uint32_t sv_hi = smem_u32(vt_hi), sv_lo = smem_u32(vt_lo);

    int grp = lane >> 3, rin = lane & 7;
    int lrow = (grp & 1) * 8 + rin;
    int lkof = (grp >> 1) * 8;

    // ---- S = Q K^T : warp owns rows wid*16..+15; nt 0..7 cover 64 keys ----
    float sacc[8][4];
#pragma unroll
    for (int nt = 0; nt < 8; nt++)
#pragma unroll
        for (int i = 0; i < 4; i++) sacc[nt][i] = 0.f;

#pragma unroll
    for (int ks = 0; ks < 32; ks += 16) {
        uint32_t ah[4], al[4];
        uint32_t aoff = (uint32_t)((wid * 16 + lrow) * 40 + ks + lkof) * 2;
        ldmat4(ah, sq_hi + aoff);
        ldmat4(al, sq_lo + aoff);
#pragma unroll
        for (int np = 0; np < 4; np++) {
            uint32_t boff = (uint32_t)((np * 16 + lrow) * 40 + ks + lkof) * 2;
            uint32_t t4[4], t4l[4];
            ldmat4(t4, sk_hi + boff);
            ldmat4(t4l, sk_lo + boff);
            uint32_t bh0[2] = {t4[0], t4[2]}, bh1[2] = {t4[1], t4[3]};
            uint32_t bl0[2] = {t4l[0], t4l[2]}, bl1[2] = {t4l[1], t4l[3]};
            mma16816(sacc[np * 2], ah, bh0);
            mma16816(sacc[np * 2], ah, bl0);
            mma16816(sacc[np * 2], al, bh0);
            mma16816(sacc[np * 2 + 1], ah, bh1);
            mma16816(sacc[np * 2 + 1], ah, bl1);
            mma16816(sacc[np * 2 + 1], al, bh1);
        }
    }

    // ---- mask + softmax on fragments ----
    const float scale = 0.2041241452319315f;  // 24^-0.5
    int qr = lane >> 2, qc = (lane & 3) * 2;
    int row0 = wid * 16 + qr, row1 = row0 + 8;

    float mx0 = -1e30f, mx1 = -1e30f;
#pragma unroll
    for (int nt = 0; nt < 8; nt++) {
#pragma unroll
        for (int c = 0; c < 2; c++) {
            int col = nt * 8 + qc + c;
            float s0 = sacc[nt][c]     * scale + msk[row0 * 65 + col];
            float s1 = sacc[nt][c + 2] * scale + msk[row1 * 65 + col];
            sacc[nt][c]     = s0;
            sacc[nt][c + 2] = s1;
            mx0 = fmaxf(mx0, s0);
            mx1 = fmaxf(mx1, s1);
        }
    }
    mx0 = fmaxf(mx0, __shfl_xor_sync(0xffffffffu, mx0, 1));
    mx0 = fmaxf(mx0, __shfl_xor_sync(0xffffffffu, mx0, 2));
    mx1 = fmaxf(mx1, __shfl_xor_sync(0xffffffffu, mx1, 1));
    mx1 = fmaxf(mx1, __shfl_xor_sync(0xffffffffu, mx1, 2));

    float sum0 = 0.f, sum1 = 0.f;
    uint32_t ph01[8], ph23[8], pl01[8], pl23[8];
#pragma unroll
    for (int nt = 0; nt < 8; nt++) {
        float p0 = __expf(sacc[nt][0] - mx0);
        float p1 = __expf(sacc[nt][1] - mx0);
        float p2 = __expf(sacc[nt][2] - mx1);
        float p3 = __expf(sacc[nt][3] - mx1);
        sum0 += p0 + p1;
        sum1 += p2 + p3;
        unsigned short h0, l0, h1, l1, h2, l2, h3, l3;
        split_bf16(p0, h0, l0);
        split_bf16(p1, h1, l1);
        split_bf16(p2, h2, l2);
        split_bf16(p3, h3, l3);
        ph01[nt] = (uint32_t)h0 | ((uint32_t)h1 << 16);
        ph23[nt] = (uint32_t)h2 | ((uint32_t)h3 << 16);
        pl01[nt] = (uint32_t)l0 | ((uint32_t)l1 << 16);
        pl23[nt] = (uint32_t)l2 | ((uint32_t)l3 << 16);
    }
    sum0 += __shfl_xor_sync(0xffffffffu, sum0, 1);
    sum0 += __shfl_xor_sync(0xffffffffu, sum0, 2);
    sum1 += __shfl_xor_sync(0xffffffffu, sum1, 1);
    sum1 += __shfl_xor_sync(0xffffffffu, sum1, 2);
    float inv0 = 1.f / sum0, inv1 = 1.f / sum1;

    // ---- O = P V (3-pass split), V^T in smem ----
    float oacc[3][4];
#pragma unroll
    for (int nt = 0; nt < 3; nt++)
#pragma unroll
        for (int i = 0; i < 4; i++) oacc[nt][i] = 0.f;

#pragma unroll
    for (int ks = 0; ks < 4; ks++) {
        uint32_t Ahi[4] = {ph01[2 * ks], ph23[2 * ks], ph01[2 * ks + 1], ph23[2 * ks + 1]};
        uint32_t Alo[4] = {pl01[2 * ks], pl23[2 * ks], pl01[2 * ks + 1], pl23[2 * ks + 1]};
        uint32_t boff0 = (uint32_t)(lrow * 72 + ks * 16 + lkof) * 2;
        uint32_t boff1 = (uint32_t)((16 + lrow) * 72 + ks * 16 + lkof) * 2;
        uint32_t t4[4];
        uint32_t bh[3][2], bl[3][2];
        ldmat4(t4, sv_hi + boff0);
        bh[0][0] = t4[0]; bh[0][1] = t4[2];
        bh[1][0] = t4[1]; bh[1][1] = t4[3];
        ldmat4(t4, sv_hi + boff1);
        bh[2][0] = t4[0]; bh[2][1] = t4[2];
        ldmat4(t4, sv_lo + boff0);
        bl[0][0] = t4[0]; bl[0][1] = t4[2];
        bl[1][0] = t4[1]; bl[1][1] = t4[3];
        ldmat4(t4, sv_lo + boff1);
        bl[2][0] = t4[0]; bl[2][1] = t4[2];
#pragma unroll
        for (int nt = 0; nt < 3; nt++) {
            mma16816(oacc[nt], Ahi, bh[nt]);
            mma16816(oacc[nt], Ahi, bl[nt]);
            mma16816(oacc[nt], Alo, bh[nt]);
        }
    }

    // ---- write O (apply 1/sum), cols = head dims nt*8+qc ----
#pragma unroll
    for (int nt = 0; nt < 3; nt++) {
        int col = h * 24 + nt * 8 + qc;
        float2 v0 = {oacc[nt][0] * inv0, oacc[nt][1] * inv0};
        float2 v1 = {oacc[nt][2] * inv1, oacc[nt][3] * inv1};
        *(float2*)(out + (size_t)(w * 64 + row0) * 96 + col) = v0;
        *(float2*)(out + (size_t)(w * 64 + row1) * 96 + col) = v1;
    }
}

// ---------------------------------------------------------------------------
extern "C" void kernel_launch(void* const* d_in, const int* in_sizes, int n_in,
                              void* d_out, int out_size) {
    const float* inputs = (const float*)d_in[0];
    const float* n1g    = (const float*)d_in[1];
    const float* n1b    = (const float*)d_in[2];
    const float* qkv_w  = (const float*)d_in[3];
    const float* qkv_b  = (const float*)d_in[4];
    const float* proj_w = (const float*)d_in[5];
    const float* proj_b = (const float*)d_in[6];
    const float* n2g    = (const float*)d_in[7];
    const float* n2b    = (const float*)d_in[8];
    const float* w1     = (const float*)d_in[9];
    const float* b1     = (const float*)d_in[10];
    const float* w2     = (const float*)d_in[11];
    const float* b2     = (const float*)d_in[12];
    const float* mask   = (const float*)d_in[13];
    float* out = (float*)d_out;

    float *boxes, *qkv, *att, *x, *h1;
    cudaGetSymbolAddress((void**)&boxes, g_boxes);
    cudaGetSymbolAddress((void**)&qkv,   g_qkv);
    cudaGetSymbolAddress((void**)&att,   g_att);
    cudaGetSymbolAddress((void**)&x,     g_x);
    cudaGetSymbolAddress((void**)&h1,    g_h1);

    unsigned short *wqh, *wql, *wph, *wpl, *w1h, *w1l, *w2h, *w2l;
    cudaGetSymbolAddress((void**)&wqh, g_wqkv_hi);
    cudaGetSymbolAddress((void**)&wql, g_wqkv_lo);
    cudaGetSymbolAddress((void**)&wph, g_wproj_hi);
    cudaGetSymbolAddress((void**)&wpl, g_wproj_lo);
    cudaGetSymbolAddress((void**)&w1h, g_wm1_hi);
    cudaGetSymbolAddress((void**)&w1l, g_wm1_lo);
    cudaGetSymbolAddress((void**)&w2h, g_wm2_hi);
    cudaGetSymbolAddress((void**)&w2l, g_wm2_lo);

    cudaFuncSetAttribute(mma_gemm<96, 288, 0>,
                         cudaFuncAttributeMaxDynamicSharedMemorySize, SMEM_BYTES);
    cudaFuncSetAttribute(mma_gemm<96, 96, 1>,
                         cudaFuncAttributeMaxDynamicSharedMemorySize, SMEM_BYTES);
    cudaFuncSetAttribute(mma_gemm<96, 384, 2>,
                         cudaFuncAttributeMaxDynamicSharedMemorySize, SMEM_BYTES);
    cudaFuncSetAttribute(mma_gemm<384, 96, 3>,
                         cudaFuncAttributeMaxDynamicSharedMemorySize, SMEM_BYTES);

    // 0. weight prep (split + transpose)
    prep_w<<<(288 * 96 + 255) / 256, 256>>>(qkv_w, 96, 288, wqh, wql);
    prep_w<<<(96 * 96 + 255) / 256, 256>>>(proj_w, 96, 96, wph, wpl);
    prep_w<<<(384 * 96 + 255) / 256, 256>>>(w1, 96, 384, w1h, w1l);
    prep_w<<<(96 * 384 + 255) / 256, 256>>>(w2, 384, 96, w2h, w2l);

    // 1. LN1 + roll(-2) + box partition
    ln_kernel<true><<<T_TOKENS / 8, 256>>>(inputs, n1g, n1b, boxes);
    // 2. QKV: [131072,96] x [96,288]
    mma_gemm<96, 288, 0><<<dim3(1024, 3), 256, SMEM_BYTES>>>(
        boxes, wqh, wql, qkv_b, qkv, nullptr);
    // 3. Windowed attention (tensor cores)
    attn_mma_kernel<<<8192, 128>>>(qkv, mask, att);
    // 4. Proj + box reverse + roll(+2) + 0.5x + shortcut
    mma_gemm<96, 96, 1><<<dim3(1024, 1), 256, SMEM_BYTES>>>(
        att, wph, wpl, proj_b, x, inputs);
    // 5. LN2
    ln_kernel<false><<<T_TOKENS / 8, 256>>>(x, n2g, n2b, boxes);
    // 6. MLP1 + gelu: [131072,96] x [96,384]
    mma_gemm<96, 384, 2><<<dim3(1024, 4), 256, SMEM_BYTES>>>(
        boxes, w1h, w1l, b1, h1, nullptr);
    // 7. MLP2 + 0.5x + residual: [131072,384] x [384,96]
    mma_gemm<384, 96, 3><<<dim3(1024, 1), 256, SMEM_BYTES>>>(
        h1, w2h, w2l, b2, out, x);
}

// round 7
// speedup vs baseline: 2.9210x; 1.2393x over previous
#include <cuda_runtime.h>
#include <cuda_bf16.h>
#include <stdint.h>

// ---------------------------------------------------------------------------
// Swin-3D block on GB300. GEMMs + attention via mma.sync bf16 split-precision.
// R6 = R5 with the mlp2 launch-arg fix: LN fused into GEMM A-load;
// CTA-internal N-loop; cp.async double-buffered B prefetch; single prep kernel.
// B=4, R=32, C=96, W=4, HEADS=4, dh=24, N=64/window, T=131072 tokens.
// ---------------------------------------------------------------------------

#define T_TOKENS 131072

// fp32 scratch
__device__ float g_qkv[131072 * 288];
__device__ float g_att[131072 * 96];
__device__ float g_x[131072 * 96];
__device__ float g_h1[131072 * 384];

// split-precision transposed weights: layout [N][K], bf16 bits (16B aligned
// for cp.async)
__device__ __align__(16) unsigned short g_wqkv_hi[288 * 96], g_wqkv_lo[288 * 96];
__device__ __align__(16) unsigned short g_wproj_hi[96 * 96], g_wproj_lo[96 * 96];
__device__ __align__(16) unsigned short g_wm1_hi[384 * 96],  g_wm1_lo[384 * 96];
__device__ __align__(16) unsigned short g_wm2_hi[96 * 384],  g_wm2_lo[96 * 384];

// ---------------------------------------------------------------------------
__device__ __forceinline__ int box_to_token(int r) {
    int w = r >> 6, n = r & 63;
    int b  = w >> 9;
    int bi = (w >> 6) & 7, bj = (w >> 3) & 7, bk = w & 7;
    int wi = n >> 4, wj = (n >> 2) & 3, wk = n & 3;
    int i = (bi * 4 + wi + 2) & 31;
    int j = (bj * 4 + wj + 2) & 31;
    int k = (bk * 4 + wk + 2) & 31;
    return ((b * 32 + i) * 32 + j) * 32 + k;
}

__device__ __forceinline__ float gelu_tanh(float x) {
    const float k0 = 0.7978845608028654f;
    const float k1 = 0.044715f;
    float x3 = x * x * x;
    float t = tanhf(k0 * (x + k1 * x3));
    return 0.5f * x * (1.0f + t);
}

__device__ __forceinline__ uint32_t smem_u32(const void* p) {
    uint32_t a;
    asm("{ .reg .u64 t; cvta.to.shared.u64 t, %1; cvt.u32.u64 %0, t; }"
        : "=r"(a) : "l"(p));
    return a;
}

__device__ __forceinline__ void ldmat4(uint32_t* r, uint32_t addr) {
    asm volatile("ldmatrix.sync.aligned.m8n8.x4.shared.b16 {%0,%1,%2,%3}, [%4];"
                 : "=r"(r[0]), "=r"(r[1]), "=r"(r[2]), "=r"(r[3]) : "r"(addr));
}

__device__ __forceinline__ void mma16816(float* d, const uint32_t* a,
                                         const uint32_t* b) {
    asm volatile(
        "mma.sync.aligned.m16n8k16.row.col.f32.bf16.bf16.f32 "
        "{%0,%1,%2,%3}, {%4,%5,%6,%7}, {%8,%9}, {%0,%1,%2,%3};"
        : "+f"(d[0]), "+f"(d[1]), "+f"(d[2]), "+f"(d[3])
        : "r"(a[0]), "r"(a[1]), "r"(a[2]), "r"(a[3]), "r"(b[0]), "r"(b[1]));
}

__device__ __forceinline__ void split_bf16(float x, unsigned short& h,
                                           unsigned short& l) {
    __nv_bfloat16 hb = __float2bfloat16(x);
    float r = x - __bfloat162float(hb);
    __nv_bfloat16 lb = __float2bfloat16(r);
    h = __bfloat16_as_ushort(hb);
    l = __bfloat16_as_ushort(lb);
}

__device__ __forceinline__ void cp_async16(uint32_t saddr, const void* g) {
    asm volatile("cp.async.ca.shared.global [%0], [%1], 16;"
                 :: "r"(saddr), "l"(g));
}
__device__ __forceinline__ void cp_commit() {
    asm volatile("cp.async.commit_group;" ::: "memory");
}
__device__ __forceinline__ void cp_wait0() {
    asm volatile("cp.async.wait_group 0;" ::: "memory");
}

// ---------------------------------------------------------------------------
// Weight prep, all 4 matrices in one launch. W[K,NTOT] -> Wt_hi/lo [NTOT][K].
// ---------------------------------------------------------------------------
__global__ void prep_all(const float* __restrict__ qkv_w,
                         const float* __restrict__ proj_w,
                         const float* __restrict__ w1,
                         const float* __restrict__ w2,
                         unsigned short* wqh, unsigned short* wql,
                         unsigned short* wph, unsigned short* wpl,
                         unsigned short* w1h, unsigned short* w1l,
                         unsigned short* w2h, unsigned short* w2l) {
    int idx = blockIdx.x * 256 + threadIdx.x;
    const float* W;
    unsigned short *hi, *lo;
    int K, NTOT, local;
    if (idx < 27648) {                       // qkv: K=96, N=288
        W = qkv_w; hi = wqh; lo = wql; K = 96; NTOT = 288; local = idx;
    } else if (idx < 36864) {                // proj: 96x96
        W = proj_w; hi = wph; lo = wpl; K = 96; NTOT = 96; local = idx - 27648;
    } else if (idx < 73728) {                // mlp1: K=96, N=384
        W = w1; hi = w1h; lo = w1l; K = 96; NTOT = 384; local = idx - 36864;
    } else if (idx < 110592) {               // mlp2: K=384, N=96
        W = w2; hi = w2h; lo = w2l; K = 384; NTOT = 96; local = idx - 73728;
    } else return;
    int n = local / K, k = local - n * K;
    unsigned short h, l;
    split_bf16(W[(size_t)k * NTOT + n], h, l);
    hi[local] = h;
    lo[local] = l;
}

// ---------------------------------------------------------------------------
// mma.sync bf16 split-precision GEMM, pipelined.
// CTA: 128 rows; loops over KCH k-chunks x NCH n-chunks of 96 (exactly one of
// KCH/NCH > 1). A converted once per k-chunk into smem (hi/lo); B slabs
// double-buffered via cp.async. 8 warps, 4x2 warp grid, 32x48 tiles.
// LN: 0 none | 1 LN + box gather (qkv) | 2 LN identity (mlp1)
// MODE: 0 bias | 1 box->token scatter 0.5x+res | 2 bias+gelu | 3 0.5x+res
// ---------------------------------------------------------------------------
#define APAD 104
#define OFF_AHI 0
#define OFF_ALO 13312
#define OFF_B0  26624                 // buf0 hi
#define BHALF   9984                  // 96*104, hi->lo offset within buffer
#define BBUF    19968                 // buffer stride
#define SMEM_U16 (26624 + 2 * 19968) // 66560
#define SMEM_BYTES (SMEM_U16 * 2)    // 133120

template <int KCH, int NCH, int LN, int MODE>
__global__ void __launch_bounds__(256, 1) mma_gemm(
    const float* __restrict__ A,
    const float* __restrict__ gamma,
    const float* __restrict__ beta,
    const unsigned short* __restrict__ Whi,
    const unsigned short* __restrict__ Wlo,
    const float* __restrict__ bias,
    float* __restrict__ out,
    const float* __restrict__ res) {
    extern __shared__ __align__(16) unsigned short sm[];
    const uint32_t sb = smem_u32(sm);
    constexpr int KTOT = 96 * KCH;
    constexpr int NTOT = 96 * NCH;
    constexpr int CH = KCH * NCH;

    int tid = threadIdx.x, lane = tid & 31, wid = tid >> 5;
    int warpM = wid >> 1, warpN = wid & 1;
    int rowBase = blockIdx.x * 128;

    int grp = lane >> 3, rin = lane & 7;
    int lrow = (grp & 1) * 8 + rin;
    int lkof = (grp >> 1) * 8;

    // ---- B prefetch for chunk c into buffer bufsel ----
    auto prefetchB = [&](int c, int bufsel) {
        int k = (KCH > 1) ? c : 0;
        int n = (KCH > 1) ? 0 : c;
        uint32_t bbase = OFF_B0 + bufsel * BBUF;
#pragma unroll
        for (int it = 0; it < 9; it++) {
            int idx = it * 256 + tid;            // 0..2303
            int half = idx >= 1152;
            int j = idx - half * 1152;
            int row = j / 12, seg = j - row * 12;
            const unsigned short* g =
                (half ? Wlo : Whi) + (size_t)(n * 96 + row) * KTOT + k * 96 + seg * 8;
            uint32_t sa = sb + 2 * (bbase + half * BHALF + row * APAD + seg * 8);
            cp_async16(sa, g);
        }
        cp_commit();
    };

    // ---- A chunk load (fp32 -> hi/lo split into smem) ----
    auto loadA = [&](int kchunk) {
        if (LN == 0) {
            int kc = kchunk * 96;
#pragma unroll
            for (int it = 0; it < 24; it++) {
                int idx = it * 256 + tid;
                int r = idx / 48, kp = (idx - r * 48) * 2;
                float2 v = *(const float2*)(A + (size_t)(rowBase + r) * KTOT + kc + kp);
                unsigned short h0, l0, h1, l1;
                split_bf16(v.x, h0, l0);
                split_bf16(v.y, h1, l1);
                int off = r * APAD + kp;
                *(uint32_t*)(sm + OFF_AHI + off) =
                    (uint32_t)h0 | ((uint32_t)h1 << 16);
                *(uint32_t*)(sm + OFF_ALO + off) =
                    (uint32_t)l0 | ((uint32_t)l1 << 16);
            }
        } else {
            // fused LayerNorm: warp handles 16 rows
#pragma unroll
            for (int rr = 0; rr < 16; rr++) {
                int r = wid * 16 + rr;
                int gr = rowBase + r;
                int s = (LN == 1) ? box_to_token(gr) : gr;
                const float* src = A + (size_t)s * 96;
                float v0 = src[lane], v1 = src[lane + 32], v2 = src[lane + 64];
                float s1 = v0 + v1 + v2;
                float s2 = v0 * v0 + v1 * v1 + v2 * v2;
#pragma unroll
                for (int o = 16; o; o >>= 1) {
                    s1 += __shfl_xor_sync(0xffffffffu, s1, o);
                    s2 += __shfl_xor_sync(0xffffffffu, s2, o);
                }
                float mean = s1 * (1.0f / 96.0f);
                float var  = s2 * (1.0f / 96.0f) - mean * mean;
                float inv  = rsqrtf(var + 1e-5f);
                float y0 = (v0 - mean) * inv * gamma[lane]      + beta[lane];
                float y1 = (v1 - mean) * inv * gamma[lane + 32] + beta[lane + 32];
                float y2 = (v2 - mean) * inv * gamma[lane + 64] + beta[lane + 64];
                unsigned short h, l;
                int ro = r * APAD;
                split_bf16(y0, h, l);
                sm[OFF_AHI + ro + lane] = h;      sm[OFF_ALO + ro + lane] = l;
                split_bf16(y1, h, l);
                sm[OFF_AHI + ro + lane + 32] = h; sm[OFF_ALO + ro + lane + 32] = l;
                split_bf16(y2, h, l);
                sm[OFF_AHI + ro + lane + 64] = h; sm[OFF_ALO + ro + lane + 64] = l;
            }
        }
    };

    float acc[2][6][4];
    auto resetAcc = [&]() {
#pragma unroll
        for (int mt = 0; mt < 2; mt++)
#pragma unroll
            for (int nt = 0; nt < 6; nt++)
#pragma unroll
                for (int i = 0; i < 4; i++) acc[mt][nt][i] = 0.f;
    };

    auto epilogue = [&](int nchunk) {
        int colBase = nchunk * 96;
        int qr = lane >> 2, qc = (lane & 3) * 2;
#pragma unroll
        for (int mt = 0; mt < 2; mt++) {
#pragma unroll
            for (int half = 0; half < 2; half++) {
                int row = rowBase + warpM * 32 + mt * 16 + qr + half * 8;
                int t = (MODE == 1) ? box_to_token(row) : row;
#pragma unroll
                for (int nt = 0; nt < 6; nt++) {
                    int col = colBase + warpN * 48 + nt * 8 + qc;
                    float v0 = acc[mt][nt][half * 2 + 0] + bias[col];
                    float v1 = acc[mt][nt][half * 2 + 1] + bias[col + 1];
                    if (MODE == 0) {
                        float2 v = {v0, v1};
                        *(float2*)(out + (size_t)row * NTOT + col) = v;
                    } else if (MODE == 2) {
                        float2 v = {gelu_tanh(v0), gelu_tanh(v1)};
                        *(float2*)(out + (size_t)row * NTOT + col) = v;
                    } else {
                        const float* rr = res + (size_t)t * 96 + col;
                        float2 v = {0.5f * v0 + rr[0], 0.5f * v1 + rr[1]};
                        *(float2*)(out + (size_t)t * 96 + col) = v;
                    }
                }
            }
        }
    };

    // ---- pipeline start ----
    prefetchB(0, 0);
    loadA(0);
    cp_wait0();
    __syncthreads();

    if (KCH > 1) resetAcc();

    for (int c = 0; c < CH; c++) {
        if (c + 1 < CH) prefetchB(c + 1, (c + 1) & 1);
        if (NCH > 1 || CH == 1) resetAcc();

        uint32_t bbase2 = (OFF_B0 + (c & 1) * BBUF) * 2;
#pragma unroll
        for (int ks = 0; ks < 96; ks += 16) {
            uint32_t afh[2][4], afl[2][4];
#pragma unroll
            for (int mt = 0; mt < 2; mt++) {
                int r = warpM * 32 + mt * 16 + lrow;
                uint32_t off = (uint32_t)(r * APAD + ks + lkof) * 2;
                ldmat4(afh[mt], sb + OFF_AHI * 2 + off);
                ldmat4(afl[mt], sb + OFF_ALO * 2 + off);
            }
            uint32_t bfh[6][2], bfl[6][2];
#pragma unroll
            for (int np = 0; np < 3; np++) {
                int n = warpN * 48 + np * 16 + lrow;
                uint32_t off = (uint32_t)(n * APAD + ks + lkof) * 2;
                uint32_t t4[4];
                ldmat4(t4, sb + bbase2 + off);
                bfh[np * 2][0] = t4[0]; bfh[np * 2][1] = t4[2];
                bfh[np * 2 + 1][0] = t4[1]; bfh[np * 2 + 1][1] = t4[3];
                ldmat4(t4, sb + bbase2 + BHALF * 2 + off);
                bfl[np * 2][0] = t4[0]; bfl[np * 2][1] = t4[2];
                bfl[np * 2 + 1][0] = t4[1]; bfl[np * 2 + 1][1] = t4[3];
            }
#pragma unroll
            for (int mt = 0; mt < 2; mt++)
#pragma unroll
                for (int nt = 0; nt < 6; nt++) {
                    mma16816(acc[mt][nt], afh[mt], bfh[nt]);
                    mma16816(acc[mt][nt], afh[mt], bfl[nt]);
                    mma16816(acc[mt][nt], afl[mt], bfh[nt]);
                }
        }

        if (NCH > 1) epilogue(c);

        if (c + 1 < CH) {
            cp_wait0();
            __syncthreads();
            if (KCH > 1) {
                loadA(c + 1);
                __syncthreads();
            }
        }
    }
    if (NCH == 1) epilogue(0);
}

// ---------------------------------------------------------------------------
// Tensor-core windowed attention (as R4). One CTA per (window, head).
// ---------------------------------------------------------------------------
__global__ void __launch_bounds__(128) attn_mma_kernel(
    const float* __restrict__ qkv,
    const float* __restrict__ mask,
    float* __restrict__ out) {
    __shared__ __align__(16) unsigned short q_hi[64 * 40], q_lo[64 * 40];
    __shared__ __align__(16) unsigned short k_hi[64 * 40], k_lo[64 * 40];
    __shared__ __align__(16) unsigned short vt_hi[32 * 72], vt_lo[32 * 72];
    __shared__ float msk[64 * 65];

    int w = blockIdx.x >> 2, h = blockIdx.x & 3;
    int tid = threadIdx.x, lane = tid & 31, wid = tid >> 5;

#pragma unroll
    for (int it = 0; it < 16; it++) {
        int idx = it * 128 + tid;
        int t = idx >> 5, d = idx & 31;
        float qv = 0.f, kv = 0.f;
        if (d < 24) {
            const float* p = qkv + (size_t)(w * 64 + t) * 288 + h * 24 + d;
            qv = p[0];
            kv = p[96];
        }
        unsigned short hh, ll;
        split_bf16(qv, hh, ll);
        q_hi[t * 40 + d] = hh; q_lo[t * 40 + d] = ll;
        split_bf16(kv, hh, ll);
        k_hi[t * 40 + d] = hh; k_lo[t * 40 + d] = ll;
    }
#pragma unroll
    for (int it = 0; it < 16; it++) {
        int idx = it * 128 + tid;
        int t = idx >> 5, d = idx & 31;
        float vv = (d < 24)
            ? qkv[(size_t)(w * 64 + t) * 288 + h * 24 + 192 + d] : 0.f;
        unsigned short hh, ll;
        split_bf16(vv, hh, ll);
        vt_hi[d * 72 + t] = hh;
        vt_lo[d * 72 + t] = ll;
    }
    const float* mrow = mask + (size_t)(w & 511) * 4096;
#pragma unroll
    for (int it = 0; it < 8; it++) {
        int idx = it * 128 + tid;
        int r = idx >> 4, c4 = (idx & 15) * 4;
        float4 mv = *(const float4*)(mrow + r * 64 + c4);
        msk[r * 65 + c4 + 0] = mv.x;
        msk[r * 65 + c4 + 1] = mv.y;
        msk[r * 65 + c4 + 2] = mv.z;
        msk[r * 65 + c4 + 3] = mv.w;
    }
    __syncthreads();

    const uint32_t sq_hi = smem_u32(q_hi), sq_lo = smem_u32(q_lo);
    const uint32_t sk_hi = smem_u32(k_hi), sk_lo = smem_u32(k_lo);
    const uint32_t sv_hi = smem_u32(vt_hi), sv_lo = smem_u32(vt_lo);

    int grp = lane >> 3, rin = lane & 7;
    int lrow = (grp & 1) * 8 + rin;
    int lkof = (grp >> 1) * 8;

    float sacc[8][4];
#pragma unroll
    for (int nt = 0; nt < 8; nt++)
#pragma unroll
        for (int i = 0; i < 4; i++) sacc[nt][i] = 0.f;

#pragma unroll
    for (int ks = 0; ks < 32; ks += 16) {
        uint32_t ah[4], al[4];
        uint32_t aoff = (uint32_t)((wid * 16 + lrow) * 40 + ks + lkof) * 2;
        ldmat4(ah, sq_hi + aoff);
        ldmat4(al, sq_lo + aoff);
#pragma unroll
        for (int np = 0; np < 4; np++) {
            uint32_t boff = (uint32_t)((np * 16 + lrow) * 40 + ks + lkof) * 2;
            uint32_t t4[4], t4l[4];
            ldmat4(t4, sk_hi + boff);
            ldmat4(t4l, sk_lo + boff);
            uint32_t bh0[2] = {t4[0], t4[2]}, bh1[2] = {t4[1], t4[3]};
            uint32_t bl0[2] = {t4l[0], t4l[2]}, bl1[2] = {t4l[1], t4l[3]};
            mma16816(sacc[np * 2], ah, bh0);
            mma16816(sacc[np * 2], ah, bl0);
            mma16816(sacc[np * 2], al, bh0);
            mma16816(sacc[np * 2 + 1], ah, bh1);
            mma16816(sacc[np * 2 + 1], ah, bl1);
            mma16816(sacc[np * 2 + 1], al, bh1);
        }
    }

    const float scale = 0.2041241452319315f;
    int qr = lane >> 2, qc = (lane & 3) * 2;
    int row0 = wid * 16 + qr, row1 = row0 + 8;

    float mx0 = -1e30f, mx1 = -1e30f;
#pragma unroll
    for (int nt = 0; nt < 8; nt++) {
#pragma unroll
        for (int c = 0; c < 2; c++) {
            int col = nt * 8 + qc + c;
            float s0 = sacc[nt][c]     * scale + msk[row0 * 65 + col];
            float s1 = sacc[nt][c + 2] * scale + msk[row1 * 65 + col];
            sacc[nt][c]     = s0;
            sacc[nt][c + 2] = s1;
            mx0 = fmaxf(mx0, s0);
            mx1 = fmaxf(mx1, s1);
        }
    }
    mx0 = fmaxf(mx0, __shfl_xor_sync(0xffffffffu, mx0, 1));
    mx0 = fmaxf(mx0, __shfl_xor_sync(0xffffffffu, mx0, 2));
    mx1 = fmaxf(mx1, __shfl_xor_sync(0xffffffffu, mx1, 1));
    mx1 = fmaxf(mx1, __shfl_xor_sync(0xffffffffu, mx1, 2));

    float sum0 = 0.f, sum1 = 0.f;
    uint32_t ph01[8], ph23[8], pl01[8], pl23[8];
#pragma unroll
    for (int nt = 0; nt < 8; nt++) {
        float p0 = __expf(sacc[nt][0] - mx0);
        float p1 = __expf(sacc[nt][1] - mx0);
        float p2 = __expf(sacc[nt][2] - mx1);
        float p3 = __expf(sacc[nt][3] - mx1);
        sum0 += p0 + p1;
        sum1 += p2 + p3;
        unsigned short h0, l0, h1, l1, h2, l2, h3, l3;
        split_bf16(p0, h0, l0);
        split_bf16(p1, h1, l1);
        split_bf16(p2, h2, l2);
        split_bf16(p3, h3, l3);
        ph01[nt] = (uint32_t)h0 | ((uint32_t)h1 << 16);
        ph23[nt] = (uint32_t)h2 | ((uint32_t)h3 << 16);
        pl01[nt] = (uint32_t)l0 | ((uint32_t)l1 << 16);
        pl23[nt] = (uint32_t)l2 | ((uint32_t)l3 << 16);
    }
    sum0 += __shfl_xor_sync(0xffffffffu, sum0, 1);
    sum0 += __shfl_xor_sync(0xffffffffu, sum0, 2);
    sum1 += __shfl_xor_sync(0xffffffffu, sum1, 1);
    sum1 += __shfl_xor_sync(0xffffffffu, sum1, 2);
    float inv0 = 1.f / sum0, inv1 = 1.f / sum1;

    float oacc[3][4];
#pragma unroll
    for (int nt = 0; nt < 3; nt++)
#pragma unroll
        for (int i = 0; i < 4; i++) oacc[nt][i] = 0.f;

#pragma unroll
    for (int ks = 0; ks < 4; ks++) {
        uint32_t Ahi[4] = {ph01[2 * ks], ph23[2 * ks], ph01[2 * ks + 1], ph23[2 * ks + 1]};
        uint32_t Alo[4] = {pl01[2 * ks], pl23[2 * ks], pl01[2 * ks + 1], pl23[2 * ks + 1]};
        uint32_t boff0 = (uint32_t)(lrow * 72 + ks * 16 + lkof) * 2;
        uint32_t boff1 = (uint32_t)((16 + lrow) * 72 + ks * 16 + lkof) * 2;
        uint32_t t4[4];
        uint32_t bh[3][2], bl[3][2];
        ldmat4(t4, sv_hi + boff0);
        bh[0][0] = t4[0]; bh[0][1] = t4[2];
        bh[1][0] = t4[1]; bh[1][1] = t4[3];
        ldmat4(t4, sv_hi + boff1);
        bh[2][0] = t4[0]; bh[2][1] = t4[2];
        ldmat4(t4, sv_lo + boff0);
        bl[0][0] = t4[0]; bl[0][1] = t4[2];
        bl[1][0] = t4[1]; bl[1][1] = t4[3];
        ldmat4(t4, sv_lo + boff1);
        bl[2][0] = t4[0]; bl[2][1] = t4[2];
#pragma unroll
        for (int nt = 0; nt < 3; nt++) {
            mma16816(oacc[nt], Ahi, bh[nt]);
            mma16816(oacc[nt], Ahi, bl[nt]);
            mma16816(oacc[nt], Alo, bh[nt]);
        }
    }

#pragma unroll
    for (int nt = 0; nt < 3; nt++) {
        int col = h * 24 + nt * 8 + qc;
        float2 v0 = {oacc[nt][0] * inv0, oacc[nt][1] * inv0};
        float2 v1 = {oacc[nt][2] * inv1, oacc[nt][3] * inv1};
        *(float2*)(out + (size_t)(w * 64 + row0) * 96 + col) = v0;
        *(float2*)(out + (size_t)(w * 64 + row1) * 96 + col) = v1;
    }
}

// ---------------------------------------------------------------------------
extern "C" void kernel_launch(void* const* d_in, const int* in_sizes, int n_in,
                              void* d_out, int out_size) {
    const float* inputs = (const float*)d_in[0];
    const float* n1g    = (const float*)d_in[1];
    const float* n1b    = (const float*)d_in[2];
    const float* qkv_w  = (const float*)d_in[3];
    const float* qkv_b  = (const float*)d_in[4];
    const float* proj_w = (const float*)d_in[5];
    const float* proj_b = (const float*)d_in[6];
    const float* n2g    = (const float*)d_in[7];
    const float* n2b    = (const float*)d_in[8];
    const float* w1     = (const float*)d_in[9];
    const float* b1     = (const float*)d_in[10];
    const float* w2     = (const float*)d_in[11];
    const float* b2     = (const float*)d_in[12];
    const float* mask   = (const float*)d_in[13];
    float* out = (float*)d_out;

    float *qkv, *att, *x, *h1;
    cudaGetSymbolAddress((void**)&qkv, g_qkv);
    cudaGetSymbolAddress((void**)&att, g_att);
    cudaGetSymbolAddress((void**)&x,   g_x);
    cudaGetSymbolAddress((void**)&h1,  g_h1);

    unsigned short *wqh, *wql, *wph, *wpl, *w1h, *w1l, *w2h, *w2l;
    cudaGetSymbolAddress((void**)&wqh, g_wqkv_hi);
    cudaGetSymbolAddress((void**)&wql, g_wqkv_lo);
    cudaGetSymbolAddress((void**)&wph, g_wproj_hi);
    cudaGetSymbolAddress((void**)&wpl, g_wproj_lo);
    cudaGetSymbolAddress((void**)&w1h, g_wm1_hi);
    cudaGetSymbolAddress((void**)&w1l, g_wm1_lo);
    cudaGetSymbolAddress((void**)&w2h, g_wm2_hi);
    cudaGetSymbolAddress((void**)&w2l, g_wm2_lo);

    cudaFuncSetAttribute(mma_gemm<1, 3, 1, 0>,
                         cudaFuncAttributeMaxDynamicSharedMemorySize, SMEM_BYTES);
    cudaFuncSetAttribute(mma_gemm<1, 1, 0, 1>,
                         cudaFuncAttributeMaxDynamicSharedMemorySize, SMEM_BYTES);
    cudaFuncSetAttribute(mma_gemm<1, 4, 2, 2>,
                         cudaFuncAttributeMaxDynamicSharedMemorySize, SMEM_BYTES);
    cudaFuncSetAttribute(mma_gemm<4, 1, 0, 3>,
                         cudaFuncAttributeMaxDynamicSharedMemorySize, SMEM_BYTES);

    // 0. weight prep (split + transpose), single launch
    prep_all<<<432, 256>>>(qkv_w, proj_w, w1, w2,
                           wqh, wql, wph, wpl, w1h, w1l, w2h, w2l);
    // 1. LN1 (fused) + box partition + QKV: [131072,96] x [96,288]
    mma_gemm<1, 3, 1, 0><<<1024, 256, SMEM_BYTES>>>(
        inputs, n1g, n1b, wqh, wql, qkv_b, qkv, nullptr);
    // 2. Windowed attention (tensor cores)
    attn_mma_kernel<<<8192, 128>>>(qkv, mask, att);
    // 3. Proj + box reverse + roll + 0.5x + shortcut
    mma_gemm<1, 1, 0, 1><<<1024, 256, SMEM_BYTES>>>(
        att, nullptr, nullptr, wph, wpl, proj_b, x, inputs);
    // 4. LN2 (fused) + MLP1 + gelu: [131072,96] x [96,384]
    mma_gemm<1, 4, 2, 2><<<1024, 256, SMEM_BYTES>>>(
        x, n2g, n2b, w1h, w1l, b1, h1, nullptr);
    // 5. MLP2 + 0.5x + residual: [131072,384] x [384,96]
    mma_gemm<4, 1, 0, 3><<<1024, 256, SMEM_BYTES>>>(
        h1, nullptr, nullptr, w2h, w2l, b2, out, x);
}

// round 8
// speedup vs baseline: 3.3286x; 1.1395x over previous
#include <cuda_runtime.h>
#include <cuda_bf16.h>
#include <stdint.h>

// ---------------------------------------------------------------------------
// Swin-3D block on GB300. GEMMs + attention via mma.sync bf16 split-precision.
// R7: single B buffer + __launch_bounds__(256,2) -> 2 CTAs/SM; next-B cp.async
// issued before the epilogue (overlaps with gmem writes).
// B=4, R=32, C=96, W=4, HEADS=4, dh=24, N=64/window, T=131072 tokens.
// ---------------------------------------------------------------------------

#define T_TOKENS 131072

// fp32 scratch
__device__ float g_qkv[131072 * 288];
__device__ float g_att[131072 * 96];
__device__ float g_x[131072 * 96];
__device__ float g_h1[131072 * 384];

// split-precision transposed weights: layout [N][K], bf16 bits (16B aligned)
__device__ __align__(16) unsigned short g_wqkv_hi[288 * 96], g_wqkv_lo[288 * 96];
__device__ __align__(16) unsigned short g_wproj_hi[96 * 96], g_wproj_lo[96 * 96];
__device__ __align__(16) unsigned short g_wm1_hi[384 * 96],  g_wm1_lo[384 * 96];
__device__ __align__(16) unsigned short g_wm2_hi[96 * 384],  g_wm2_lo[96 * 384];

// ---------------------------------------------------------------------------
__device__ __forceinline__ int box_to_token(int r) {
    int w = r >> 6, n = r & 63;
    int b  = w >> 9;
    int bi = (w >> 6) & 7, bj = (w >> 3) & 7, bk = w & 7;
    int wi = n >> 4, wj = (n >> 2) & 3, wk = n & 3;
    int i = (bi * 4 + wi + 2) & 31;
    int j = (bj * 4 + wj + 2) & 31;
    int k = (bk * 4 + wk + 2) & 31;
    return ((b * 32 + i) * 32 + j) * 32 + k;
}

__device__ __forceinline__ float gelu_tanh(float x) {
    const float k0 = 0.7978845608028654f;
    const float k1 = 0.044715f;
    float x3 = x * x * x;
    float t = tanhf(k0 * (x + k1 * x3));
    return 0.5f * x * (1.0f + t);
}

__device__ __forceinline__ uint32_t smem_u32(const void* p) {
    uint32_t a;
    asm("{ .reg .u64 t; cvta.to.shared.u64 t, %1; cvt.u32.u64 %0, t; }"
        : "=r"(a) : "l"(p));
    return a;
}

__device__ __forceinline__ void ldmat4(uint32_t* r, uint32_t addr) {
    asm volatile("ldmatrix.sync.aligned.m8n8.x4.shared.b16 {%0,%1,%2,%3}, [%4];"
                 : "=r"(r[0]), "=r"(r[1]), "=r"(r[2]), "=r"(r[3]) : "r"(addr));
}

__device__ __forceinline__ void mma16816(float* d, const uint32_t* a,
                                         const uint32_t* b) {
    asm volatile(
        "mma.sync.aligned.m16n8k16.row.col.f32.bf16.bf16.f32 "
        "{%0,%1,%2,%3}, {%4,%5,%6,%7}, {%8,%9}, {%0,%1,%2,%3};"
        : "+f"(d[0]), "+f"(d[1]), "+f"(d[2]), "+f"(d[3])
        : "r"(a[0]), "r"(a[1]), "r"(a[2]), "r"(a[3]), "r"(b[0]), "r"(b[1]));
}

__device__ __forceinline__ void split_bf16(float x, unsigned short& h,
                                           unsigned short& l) {
    __nv_bfloat16 hb = __float2bfloat16(x);
    float r = x - __bfloat162float(hb);
    __nv_bfloat16 lb = __float2bfloat16(r);
    h = __bfloat16_as_ushort(hb);
    l = __bfloat16_as_ushort(lb);
}

__device__ __forceinline__ void cp_async16(uint32_t saddr, const void* g) {
    asm volatile("cp.async.ca.shared.global [%0], [%1], 16;"
                 :: "r"(saddr), "l"(g));
}
__device__ __forceinline__ void cp_commit() {
    asm volatile("cp.async.commit_group;" ::: "memory");
}
__device__ __forceinline__ void cp_wait0() {
    asm volatile("cp.async.wait_group 0;" ::: "memory");
}

// ---------------------------------------------------------------------------
// Weight prep, all 4 matrices in one launch. W[K,NTOT] -> Wt_hi/lo [NTOT][K].
// ---------------------------------------------------------------------------
__global__ void prep_all(const float* __restrict__ qkv_w,
                         const float* __restrict__ proj_w,
                         const float* __restrict__ w1,
                         const float* __restrict__ w2,
                         unsigned short* wqh, unsigned short* wql,
                         unsigned short* wph, unsigned short* wpl,
                         unsigned short* w1h, unsigned short* w1l,
                         unsigned short* w2h, unsigned short* w2l) {
    int idx = blockIdx.x * 256 + threadIdx.x;
    const float* W;
    unsigned short *hi, *lo;
    int K, NTOT, local;
    if (idx < 27648) {
        W = qkv_w; hi = wqh; lo = wql; K = 96; NTOT = 288; local = idx;
    } else if (idx < 36864) {
        W = proj_w; hi = wph; lo = wpl; K = 96; NTOT = 96; local = idx - 27648;
    } else if (idx < 73728) {
        W = w1; hi = w1h; lo = w1l; K = 96; NTOT = 384; local = idx - 36864;
    } else if (idx < 110592) {
        W = w2; hi = w2h; lo = w2l; K = 384; NTOT = 96; local = idx - 73728;
    } else return;
    int n = local / K, k = local - n * K;
    unsigned short h, l;
    split_bf16(W[(size_t)k * NTOT + n], h, l);
    hi[local] = h;
    lo[local] = l;
}

// ---------------------------------------------------------------------------
// mma.sync bf16 split-precision GEMM, 2 CTAs/SM.
// CTA: 128 rows; loops over KCH k-chunks x NCH n-chunks of 96 (exactly one of
// KCH/NCH > 1). A converted once per k-chunk into smem (hi/lo); single B
// buffer, next slab's cp.async issued before the epilogue. 8 warps, 4x2 grid.
// LN: 0 none | 1 LN + box gather (qkv) | 2 LN identity (mlp1)
// MODE: 0 bias | 1 box->token scatter 0.5x+res | 2 bias+gelu | 3 0.5x+res
// ---------------------------------------------------------------------------
#define APAD 104
#define OFF_AHI 0
#define OFF_ALO 13312
#define OFF_B0  26624                 // B hi
#define BHALF   9984                  // 96*104, hi->lo offset
#define SMEM_U16 (26624 + 19968)      // 46592
#define SMEM_BYTES (SMEM_U16 * 2)     // 93184

template <int KCH, int NCH, int LN, int MODE>
__global__ void __launch_bounds__(256, 2) mma_gemm(
    const float* __restrict__ A,
    const float* __restrict__ gamma,
    const float* __restrict__ beta,
    const unsigned short* __restrict__ Whi,
    const unsigned short* __restrict__ Wlo,
    const float* __restrict__ bias,
    float* __restrict__ out,
    const float* __restrict__ res) {
    extern __shared__ __align__(16) unsigned short sm[];
    const uint32_t sb = smem_u32(sm);
    constexpr int KTOT = 96 * KCH;
    constexpr int NTOT = 96 * NCH;
    constexpr int CH = KCH * NCH;

    int tid = threadIdx.x, lane = tid & 31, wid = tid >> 5;
    int warpM = wid >> 1, warpN = wid & 1;
    int rowBase = blockIdx.x * 128;

    int grp = lane >> 3, rin = lane & 7;
    int lrow = (grp & 1) * 8 + rin;
    int lkof = (grp >> 1) * 8;

    auto prefetchB = [&](int c) {
        int k = (KCH > 1) ? c : 0;
        int n = (KCH > 1) ? 0 : c;
#pragma unroll
        for (int it = 0; it < 9; it++) {
            int idx = it * 256 + tid;            // 0..2303
            int half = idx >= 1152;
            int j = idx - half * 1152;
            int row = j / 12, seg = j - row * 12;
            const unsigned short* g =
                (half ? Wlo : Whi) + (size_t)(n * 96 + row) * KTOT + k * 96 + seg * 8;
            uint32_t sa = sb + 2 * (OFF_B0 + half * BHALF + row * APAD + seg * 8);
            cp_async16(sa, g);
        }
        cp_commit();
    };

    auto loadA = [&](int kchunk) {
        if (LN == 0) {
            int kc = kchunk * 96;
#pragma unroll
            for (int it = 0; it < 24; it++) {
                int idx = it * 256 + tid;
                int r = idx / 48, kp = (idx - r * 48) * 2;
                float2 v = *(const float2*)(A + (size_t)(rowBase + r) * KTOT + kc + kp);
                unsigned short h0, l0, h1, l1;
                split_bf16(v.x, h0, l0);
                split_bf16(v.y, h1, l1);
                int off = r * APAD + kp;
                *(uint32_t*)(sm + OFF_AHI + off) =
                    (uint32_t)h0 | ((uint32_t)h1 << 16);
                *(uint32_t*)(sm + OFF_ALO + off) =
                    (uint32_t)l0 | ((uint32_t)l1 << 16);
            }
        } else {
#pragma unroll
            for (int rr = 0; rr < 16; rr++) {
                int r = wid * 16 + rr;
                int gr = rowBase + r;
                int s = (LN == 1) ? box_to_token(gr) : gr;
                const float* src = A + (size_t)s * 96;
                float v0 = src[lane], v1 = src[lane + 32], v2 = src[lane + 64];
                float s1 = v0 + v1 + v2;
                float s2 = v0 * v0 + v1 * v1 + v2 * v2;
#pragma unroll
                for (int o = 16; o; o >>= 1) {
                    s1 += __shfl_xor_sync(0xffffffffu, s1, o);
                    s2 += __shfl_xor_sync(0xffffffffu, s2, o);
                }
                float mean = s1 * (1.0f / 96.0f);
                float var  = s2 * (1.0f / 96.0f) - mean * mean;
                float inv  = rsqrtf(var + 1e-5f);
                float y0 = (v0 - mean) * inv * gamma[lane]      + beta[lane];
                float y1 = (v1 - mean) * inv * gamma[lane + 32] + beta[lane + 32];
                float y2 = (v2 - mean) * inv * gamma[lane + 64] + beta[lane + 64];
                unsigned short h, l;
                int ro = r * APAD;
                split_bf16(y0, h, l);
                sm[OFF_AHI + ro + lane] = h;      sm[OFF_ALO + ro + lane] = l;
                split_bf16(y1, h, l);
                sm[OFF_AHI + ro + lane + 32] = h; sm[OFF_ALO + ro + lane + 32] = l;
                split_bf16(y2, h, l);
                sm[OFF_AHI + ro + lane + 64] = h; sm[OFF_ALO + ro + lane + 64] = l;
            }
        }
    };

    float acc[2][6][4];
    auto resetAcc = [&]() {
#pragma unroll
        for (int mt = 0; mt < 2; mt++)
#pragma unroll
            for (int nt = 0; nt < 6; nt++)
#pragma unroll
                for (int i = 0; i < 4; i++) acc[mt][nt][i] = 0.f;
    };

    auto epilogue = [&](int nchunk) {
        int colBase = nchunk * 96;
        int qr = lane >> 2, qc = (lane & 3) * 2;
#pragma unroll
        for (int mt = 0; mt < 2; mt++) {
#pragma unroll
            for (int half = 0; half < 2; half++) {
                int row = rowBase + warpM * 32 + mt * 16 + qr + half * 8;
                int t = (MODE == 1) ? box_to_token(row) : row;
#pragma unroll
                for (int nt = 0; nt < 6; nt++) {
                    int col = colBase + warpN * 48 + nt * 8 + qc;
                    float v0 = acc[mt][nt][half * 2 + 0] + bias[col];
                    float v1 = acc[mt][nt][half * 2 + 1] + bias[col + 1];
                    if (MODE == 0) {
                        float2 v = {v0, v1};
                        *(float2*)(out + (size_t)row * NTOT + col) = v;
                    } else if (MODE == 2) {
                        float2 v = {gelu_tanh(v0), gelu_tanh(v1)};
                        *(float2*)(out + (size_t)row * NTOT + col) = v;
                    } else {
                        const float* rr = res + (size_t)t * 96 + col;
                        float2 v = {0.5f * v0 + rr[0], 0.5f * v1 + rr[1]};
                        *(float2*)(out + (size_t)t * 96 + col) = v;
                    }
                }
            }
        }
    };

    // ---- pipeline start ----
    prefetchB(0);
    loadA(0);
    cp_wait0();
    __syncthreads();

    if (KCH > 1) resetAcc();

    for (int c = 0; c < CH; c++) {
        if (NCH > 1 || CH == 1 || c == 0) resetAcc();

#pragma unroll
        for (int ks = 0; ks < 96; ks += 16) {
            uint32_t afh[2][4], afl[2][4];
#pragma unroll
            for (int mt = 0; mt < 2; mt++) {
                int r = warpM * 32 + mt * 16 + lrow;
                uint32_t off = (uint32_t)(r * APAD + ks + lkof) * 2;
                ldmat4(afh[mt], sb + OFF_AHI * 2 + off);
                ldmat4(afl[mt], sb + OFF_ALO * 2 + off);
            }
            uint32_t bfh[6][2], bfl[6][2];
#pragma unroll
            for (int np = 0; np < 3; np++) {
                int n = warpN * 48 + np * 16 + lrow;
                uint32_t off = (uint32_t)(n * APAD + ks + lkof) * 2;
                uint32_t t4[4];
                ldmat4(t4, sb + OFF_B0 * 2 + off);
                bfh[np * 2][0] = t4[0]; bfh[np * 2][1] = t4[2];
                bfh[np * 2 + 1][0] = t4[1]; bfh[np * 2 + 1][1] = t4[3];
                ldmat4(t4, sb + (OFF_B0 + BHALF) * 2 + off);
                bfl[np * 2][0] = t4[0]; bfl[np * 2][1] = t4[2];
                bfl[np * 2 + 1][0] = t4[1]; bfl[np * 2 + 1][1] = t4[3];
            }
#pragma unroll
            for (int mt = 0; mt < 2; mt++)
#pragma unroll
                for (int nt = 0; nt < 6; nt++) {
                    mma16816(acc[mt][nt], afh[mt], bfh[nt]);
                    mma16816(acc[mt][nt], afh[mt], bfl[nt]);
                    mma16816(acc[mt][nt], afl[mt], bfh[nt]);
                }
        }

        if (c + 1 < CH) {
            __syncthreads();             // all warps done reading B (and A)
            prefetchB(c + 1);            // overlaps with epilogue below
            if (KCH > 1) loadA(c + 1);
        }

        if (NCH > 1) epilogue(c);

        if (c + 1 < CH) {
            cp_wait0();
            __syncthreads();
        }
    }
    if (NCH == 1) epilogue(0);
}

// ---------------------------------------------------------------------------
// Tensor-core windowed attention (as R4). One CTA per (window, head).
// ---------------------------------------------------------------------------
__global__ void __launch_bounds__(128) attn_mma_kernel(
    const float* __restrict__ qkv,
    const float* __restrict__ mask,
    float* __restrict__ out) {
    __shared__ __align__(16) unsigned short q_hi[64 * 40], q_lo[64 * 40];
    __shared__ __align__(16) unsigned short k_hi[64 * 40], k_lo[64 * 40];
    __shared__ __align__(16) unsigned short vt_hi[32 * 72], vt_lo[32 * 72];
    __shared__ float msk[64 * 65];

    int w = blockIdx.x >> 2, h = blockIdx.x & 3;
    int tid = threadIdx.x, lane = tid & 31, wid = tid >> 5;

#pragma unroll
    for (int it = 0; it < 16; it++) {
        int idx = it * 128 + tid;
        int t = idx >> 5, d = idx & 31;
        float qv = 0.f, kv = 0.f;
        if (d < 24) {
            const float* p = qkv + (size_t)(w * 64 + t) * 288 + h * 24 + d;
            qv = p[0];
            kv = p[96];
        }
        unsigned short hh, ll;
        split_bf16(qv, hh, ll);
        q_hi[t * 40 + d] = hh; q_lo[t * 40 + d] = ll;
        split_bf16(kv, hh, ll);
        k_hi[t * 40 + d] = hh; k_lo[t * 40 + d] = ll;
    }
#pragma unroll
    for (int it = 0; it < 16; it++) {
        int idx = it * 128 + tid;
        int t = idx >> 5, d = idx & 31;
        float vv = (d < 24)
            ? qkv[(size_t)(w * 64 + t) * 288 + h * 24 + 192 + d] : 0.f;
        unsigned short hh, ll;
        split_bf16(vv, hh, ll);
        vt_hi[d * 72 + t] = hh;
        vt_lo[d * 72 + t] = ll;
    }
    const float* mrow = mask + (size_t)(w & 511) * 4096;
#pragma unroll
    for (int it = 0; it < 8; it++) {
        int idx = it * 128 + tid;
        int r = idx >> 4, c4 = (idx & 15) * 4;
        float4 mv = *(const float4*)(mrow + r * 64 + c4);
        msk[r * 65 + c4 + 0] = mv.x;
        msk[r * 65 + c4 + 1] = mv.y;
        msk[r * 65 + c4 + 2] = mv.z;
        msk[r * 65 + c4 + 3] = mv.w;
    }
    __syncthreads();

    const uint32_t sq_hi = smem_u32(q_hi), sq_lo = smem_u32(q_lo);
    const uint32_t sk_hi = smem_u32(k_hi), sk_lo = smem_u32(k_lo);
    const uint32_t sv_hi = smem_u32(vt_hi), sv_lo = smem_u32(vt_lo);

    int grp = lane >> 3, rin = lane & 7;
    int lrow = (grp & 1) * 8 + rin;
    int lkof = (grp >> 1) * 8;

    float sacc[8][4];
#pragma unroll
    for (int nt = 0; nt < 8; nt++)
#pragma unroll
        for (int i = 0; i < 4; i++) sacc[nt][i] = 0.f;

#pragma unroll
    for (int ks = 0; ks < 32; ks += 16) {
        uint32_t ah[4], al[4];
        uint32_t aoff = (uint32_t)((wid * 16 + lrow) * 40 + ks + lkof) * 2;
        ldmat4(ah, sq_hi + aoff);
        ldmat4(al, sq_lo + aoff);
#pragma unroll
        for (int np = 0; np < 4; np++) {
            uint32_t boff = (uint32_t)((np * 16 + lrow) * 40 + ks + lkof) * 2;
            uint32_t t4[4], t4l[4];
            ldmat4(t4, sk_hi + boff);
            ldmat4(t4l, sk_lo + boff);
            uint32_t bh0[2] = {t4[0], t4[2]}, bh1[2] = {t4[1], t4[3]};
            uint32_t bl0[2] = {t4l[0], t4l[2]}, bl1[2] = {t4l[1], t4l[3]};
            mma16816(sacc[np * 2], ah, bh0);
            mma16816(sacc[np * 2], ah, bl0);
            mma16816(sacc[np * 2], al, bh0);
            mma16816(sacc[np * 2 + 1], ah, bh1);
            mma16816(sacc[np * 2 + 1], ah, bl1);
            mma16816(sacc[np * 2 + 1], al, bh1);
        }
    }

    const float scale = 0.2041241452319315f;
    int qr = lane >> 2, qc = (lane & 3) * 2;
    int row0 = wid * 16 + qr, row1 = row0 + 8;

    float mx0 = -1e30f, mx1 = -1e30f;
#pragma unroll
    for (int nt = 0; nt < 8; nt++) {
#pragma unroll
        for (int c = 0; c < 2; c++) {
            int col = nt * 8 + qc + c;
            float s0 = sacc[nt][c]     * scale + msk[row0 * 65 + col];
            float s1 = sacc[nt][c + 2] * scale + msk[row1 * 65 + col];
            sacc[nt][c]     = s0;
            sacc[nt][c + 2] = s1;
            mx0 = fmaxf(mx0, s0);
            mx1 = fmaxf(mx1, s1);
        }
    }
    mx0 = fmaxf(mx0, __shfl_xor_sync(0xffffffffu, mx0, 1));
    mx0 = fmaxf(mx0, __shfl_xor_sync(0xffffffffu, mx0, 2));
    mx1 = fmaxf(mx1, __shfl_xor_sync(0xffffffffu, mx1, 1));
    mx1 = fmaxf(mx1, __shfl_xor_sync(0xffffffffu, mx1, 2));

    float sum0 = 0.f, sum1 = 0.f;
    uint32_t ph01[8], ph23[8], pl01[8], pl23[8];
#pragma unroll
    for (int nt = 0; nt < 8; nt++) {
        float p0 = __expf(sacc[nt][0] - mx0);
        float p1 = __expf(sacc[nt][1] - mx0);
        float p2 = __expf(sacc[nt][2] - mx1);
        float p3 = __expf(sacc[nt][3] - mx1);
        sum0 += p0 + p1;
        sum1 += p2 + p3;
        unsigned short h0, l0, h1, l1, h2, l2, h3, l3;
        split_bf16(p0, h0, l0);
        split_bf16(p1, h1, l1);
        split_bf16(p2, h2, l2);
        split_bf16(p3, h3, l3);
        ph01[nt] = (uint32_t)h0 | ((uint32_t)h1 << 16);
        ph23[nt] = (uint32_t)h2 | ((uint32_t)h3 << 16);
        pl01[nt] = (uint32_t)l0 | ((uint32_t)l1 << 16);
        pl23[nt] = (uint32_t)l2 | ((uint32_t)l3 << 16);
    }
    sum0 += __shfl_xor_sync(0xffffffffu, sum0, 1);
    sum0 += __shfl_xor_sync(0xffffffffu, sum0, 2);
    sum1 += __shfl_xor_sync(0xffffffffu, sum1, 1);
    sum1 += __shfl_xor_sync(0xffffffffu, sum1, 2);
    float inv0 = 1.f / sum0, inv1 = 1.f / sum1;

    float oacc[3][4];
#pragma unroll
    for (int nt = 0; nt < 3; nt++)
#pragma unroll
        for (int i = 0; i < 4; i++) oacc[nt][i] = 0.f;

#pragma unroll
    for (int ks = 0; ks < 4; ks++) {
        uint32_t Ahi[4] = {ph01[2 * ks], ph23[2 * ks], ph01[2 * ks + 1], ph23[2 * ks + 1]};
        uint32_t Alo[4] = {pl01[2 * ks], pl23[2 * ks], pl01[2 * ks + 1], pl23[2 * ks + 1]};
        uint32_t boff0 = (uint32_t)(lrow * 72 + ks * 16 + lkof) * 2;
        uint32_t boff1 = (uint32_t)((16 + lrow) * 72 + ks * 16 + lkof) * 2;
        uint32_t t4[4];
        uint32_t bh[3][2], bl[3][2];
        ldmat4(t4, sv_hi + boff0);
        bh[0][0] = t4[0]; bh[0][1] = t4[2];
        bh[1][0] = t4[1]; bh[1][1] = t4[3];
        ldmat4(t4, sv_hi + boff1);
        bh[2][0] = t4[0]; bh[2][1] = t4[2];
        ldmat4(t4, sv_lo + boff0);
        bl[0][0] = t4[0]; bl[0][1] = t4[2];
        bl[1][0] = t4[1]; bl[1][1] = t4[3];
        ldmat4(t4, sv_lo + boff1);
        bl[2][0] = t4[0]; bl[2][1] = t4[2];
#pragma unroll
        for (int nt = 0; nt < 3; nt++) {
            mma16816(oacc[nt], Ahi, bh[nt]);
            mma16816(oacc[nt], Ahi, bl[nt]);
            mma16816(oacc[nt], Alo, bh[nt]);
        }
    }

#pragma unroll
    for (int nt = 0; nt < 3; nt++) {
        int col = h * 24 + nt * 8 + qc;
        float2 v0 = {oacc[nt][0] * inv0, oacc[nt][1] * inv0};
        float2 v1 = {oacc[nt][2] * inv1, oacc[nt][3] * inv1};
        *(float2*)(out + (size_t)(w * 64 + row0) * 96 + col) = v0;
        *(float2*)(out + (size_t)(w * 64 + row1) * 96 + col) = v1;
    }
}

// ---------------------------------------------------------------------------
extern "C" void kernel_launch(void* const* d_in, const int* in_sizes, int n_in,
                              void* d_out, int out_size) {
    const float* inputs = (const float*)d_in[0];
    const float* n1g    = (const float*)d_in[1];
    const float* n1b    = (const float*)d_in[2];
    const float* qkv_w  = (const float*)d_in[3];
    const float* qkv_b  = (const float*)d_in[4];
    const float* proj_w = (const float*)d_in[5];
    const float* proj_b = (const float*)d_in[6];
    const float* n2g    = (const float*)d_in[7];
    const float* n2b    = (const float*)d_in[8];
    const float* w1     = (const float*)d_in[9];
    const float* b1     = (const float*)d_in[10];
    const float* w2     = (const float*)d_in[11];
    const float* b2     = (const float*)d_in[12];
    const float* mask   = (const float*)d_in[13];
    float* out = (float*)d_out;

    float *qkv, *att, *x, *h1;
    cudaGetSymbolAddress((void**)&qkv, g_qkv);
    cudaGetSymbolAddress((void**)&att, g_att);
    cudaGetSymbolAddress((void**)&x,   g_x);
    cudaGetSymbolAddress((void**)&h1,  g_h1);

    unsigned short *wqh, *wql, *wph, *wpl, *w1h, *w1l, *w2h, *w2l;
    cudaGetSymbolAddress((void**)&wqh, g_wqkv_hi);
    cudaGetSymbolAddress((void**)&wql, g_wqkv_lo);
    cudaGetSymbolAddress((void**)&wph, g_wproj_hi);
    cudaGetSymbolAddress((void**)&wpl, g_wproj_lo);
    cudaGetSymbolAddress((void**)&w1h, g_wm1_hi);
    cudaGetSymbolAddress((void**)&w1l, g_wm1_lo);
    cudaGetSymbolAddress((void**)&w2h, g_wm2_hi);
    cudaGetSymbolAddress((void**)&w2l, g_wm2_lo);

    cudaFuncSetAttribute(mma_gemm<1, 3, 1, 0>,
                         cudaFuncAttributeMaxDynamicSharedMemorySize, SMEM_BYTES);
    cudaFuncSetAttribute(mma_gemm<1, 1, 0, 1>,
                         cudaFuncAttributeMaxDynamicSharedMemorySize, SMEM_BYTES);
    cudaFuncSetAttribute(mma_gemm<1, 4, 2, 2>,
                         cudaFuncAttributeMaxDynamicSharedMemorySize, SMEM_BYTES);
    cudaFuncSetAttribute(mma_gemm<4, 1, 0, 3>,
                         cudaFuncAttributeMaxDynamicSharedMemorySize, SMEM_BYTES);

    // 0. weight prep (split + transpose), single launch
    prep_all<<<432, 256>>>(qkv_w, proj_w, w1, w2,
                           wqh, wql, wph, wpl, w1h, w1l, w2h, w2l);
    // 1. LN1 (fused) + box partition + QKV: [131072,96] x [96,288]
    mma_gemm<1, 3, 1, 0><<<1024, 256, SMEM_BYTES>>>(
        inputs, n1g, n1b, wqh, wql, qkv_b, qkv, nullptr);
    // 2. Windowed attention (tensor cores)
    attn_mma_kernel<<<8192, 128>>>(qkv, mask, att);
    // 3. Proj + box reverse + roll + 0.5x + shortcut
    mma_gemm<1, 1, 0, 1><<<1024, 256, SMEM_BYTES>>>(
        att, nullptr, nullptr, wph, wpl, proj_b, x, inputs);
    // 4. LN2 (fused) + MLP1 + gelu: [131072,96] x [96,384]
    mma_gemm<1, 4, 2, 2><<<1024, 256, SMEM_BYTES>>>(
        x, n2g, n2b, w1h, w1l, b1, h1, nullptr);
    // 5. MLP2 + 0.5x + residual: [131072,384] x [384,96]
    mma_gemm<4, 1, 0, 3><<<1024, 256, SMEM_BYTES>>>(
        h1, nullptr, nullptr, w2h, w2l, b2, out, x);
}

// round 9
// speedup vs baseline: 4.3620x; 1.3105x over previous
#include <cuda_runtime.h>
#include <cuda_bf16.h>
#include <stdint.h>

// ---------------------------------------------------------------------------
// Swin-3D block on GB300. R8: bf16 activations (qkv/att/h1), A-operand
// bf16-exact + B split hi/lo -> 2-pass GEMM MMA; attention QK 1-pass,
// PV 2-pass; cp.async A tiles for proj/mlp2. Residual stream x stays fp32.
// B=4, R=32, C=96, W=4, HEADS=4, dh=24, N=64/window, T=131072 tokens.
// ---------------------------------------------------------------------------

#define T_TOKENS 131072

// activations
__device__ __align__(16) unsigned short g_qkv[131072 * 288];  // bf16
__device__ __align__(16) unsigned short g_att[131072 * 96];   // bf16
__device__ float g_x[131072 * 96];                            // fp32 residual
__device__ __align__(16) unsigned short g_h1[131072 * 384];   // bf16

// split-precision transposed weights: layout [N][K], bf16 bits
__device__ __align__(16) unsigned short g_wqkv_hi[288 * 96], g_wqkv_lo[288 * 96];
__device__ __align__(16) unsigned short g_wproj_hi[96 * 96], g_wproj_lo[96 * 96];
__device__ __align__(16) unsigned short g_wm1_hi[384 * 96],  g_wm1_lo[384 * 96];
__device__ __align__(16) unsigned short g_wm2_hi[96 * 384],  g_wm2_lo[96 * 384];

// ---------------------------------------------------------------------------
__device__ __forceinline__ int box_to_token(int r) {
    int w = r >> 6, n = r & 63;
    int b  = w >> 9;
    int bi = (w >> 6) & 7, bj = (w >> 3) & 7, bk = w & 7;
    int wi = n >> 4, wj = (n >> 2) & 3, wk = n & 3;
    int i = (bi * 4 + wi + 2) & 31;
    int j = (bj * 4 + wj + 2) & 31;
    int k = (bk * 4 + wk + 2) & 31;
    return ((b * 32 + i) * 32 + j) * 32 + k;
}

__device__ __forceinline__ float gelu_tanh(float x) {
    const float k0 = 0.7978845608028654f;
    const float k1 = 0.044715f;
    float x3 = x * x * x;
    float t = tanhf(k0 * (x + k1 * x3));
    return 0.5f * x * (1.0f + t);
}

__device__ __forceinline__ uint32_t smem_u32(const void* p) {
    uint32_t a;
    asm("{ .reg .u64 t; cvta.to.shared.u64 t, %1; cvt.u32.u64 %0, t; }"
        : "=r"(a) : "l"(p));
    return a;
}

__device__ __forceinline__ void ldmat4(uint32_t* r, uint32_t addr) {
    asm volatile("ldmatrix.sync.aligned.m8n8.x4.shared.b16 {%0,%1,%2,%3}, [%4];"
                 : "=r"(r[0]), "=r"(r[1]), "=r"(r[2]), "=r"(r[3]) : "r"(addr));
}

__device__ __forceinline__ void mma16816(float* d, const uint32_t* a,
                                         const uint32_t* b) {
    asm volatile(
        "mma.sync.aligned.m16n8k16.row.col.f32.bf16.bf16.f32 "
        "{%0,%1,%2,%3}, {%4,%5,%6,%7}, {%8,%9}, {%0,%1,%2,%3};"
        : "+f"(d[0]), "+f"(d[1]), "+f"(d[2]), "+f"(d[3])
        : "r"(a[0]), "r"(a[1]), "r"(a[2]), "r"(a[3]), "r"(b[0]), "r"(b[1]));
}

__device__ __forceinline__ void split_bf16(float x, unsigned short& h,
                                           unsigned short& l) {
    __nv_bfloat16 hb = __float2bfloat16(x);
    float r = x - __bfloat162float(hb);
    __nv_bfloat16 lb = __float2bfloat16(r);
    h = __bfloat16_as_ushort(hb);
    l = __bfloat16_as_ushort(lb);
}

__device__ __forceinline__ unsigned short to_bf16(float x) {
    return __bfloat16_as_ushort(__float2bfloat16(x));
}

__device__ __forceinline__ void cp_async16(uint32_t saddr, const void* g) {
    asm volatile("cp.async.ca.shared.global [%0], [%1], 16;"
                 :: "r"(saddr), "l"(g));
}
__device__ __forceinline__ void cp_commit() {
    asm volatile("cp.async.commit_group;" ::: "memory");
}
__device__ __forceinline__ void cp_wait0() {
    asm volatile("cp.async.wait_group 0;" ::: "memory");
}

// ---------------------------------------------------------------------------
// Weight prep, all 4 matrices in one launch. W[K,NTOT] -> Wt_hi/lo [NTOT][K].
// ---------------------------------------------------------------------------
__global__ void prep_all(const float* __restrict__ qkv_w,
                         const float* __restrict__ proj_w,
                         const float* __restrict__ w1,
                         const float* __restrict__ w2,
                         unsigned short* wqh, unsigned short* wql,
                         unsigned short* wph, unsigned short* wpl,
                         unsigned short* w1h, unsigned short* w1l,
                         unsigned short* w2h, unsigned short* w2l) {
    int idx = blockIdx.x * 256 + threadIdx.x;
    const float* W;
    unsigned short *hi, *lo;
    int K, NTOT, local;
    if (idx < 27648) {
        W = qkv_w; hi = wqh; lo = wql; K = 96; NTOT = 288; local = idx;
    } else if (idx < 36864) {
        W = proj_w; hi = wph; lo = wpl; K = 96; NTOT = 96; local = idx - 27648;
    } else if (idx < 73728) {
        W = w1; hi = w1h; lo = w1l; K = 96; NTOT = 384; local = idx - 36864;
    } else if (idx < 110592) {
        W = w2; hi = w2h; lo = w2l; K = 384; NTOT = 96; local = idx - 73728;
    } else return;
    int n = local / K, k = local - n * K;
    unsigned short h, l;
    split_bf16(W[(size_t)k * NTOT + n], h, l);
    hi[local] = h;
    lo[local] = l;
}

// ---------------------------------------------------------------------------
// GEMM: A (bf16-exact, single copy in smem) x B (split hi/lo, 2-pass MMA).
// CTA: 128 rows; KCH k-chunks x NCH n-chunks of 96. LN==0 => A is bf16 in
// gmem, streamed via cp.async. LN: 1 LN+box gather | 2 LN identity.
// MODE: 0 qkv (bias, bf16 out) | 1 proj (scatter, 0.5x+res, fp32 out)
//       2 mlp1 (bias+gelu, bf16 out) | 3 mlp2 (0.5x+res, fp32 out)
// ---------------------------------------------------------------------------
#define APAD 104
#define OFF_B 13312                   // B hi (u16 units)
#define BHALF 9984                    // 96*104
#define SMEM_U16 (13312 + 2 * 9984)   // 33280
#define SMEM_BYTES (SMEM_U16 * 2)     // 66560

template <int KCH, int NCH, int LN, int MODE>
__global__ void __launch_bounds__(256, 2) mma_gemm(
    const void* __restrict__ Avoid,
    const float* __restrict__ gamma,
    const float* __restrict__ beta,
    const unsigned short* __restrict__ Whi,
    const unsigned short* __restrict__ Wlo,
    const float* __restrict__ bias,
    void* __restrict__ outv,
    const float* __restrict__ res) {
    extern __shared__ __align__(16) unsigned short sm[];
    const uint32_t sb = smem_u32(sm);
    constexpr int KTOT = 96 * KCH;
    constexpr int NTOT = 96 * NCH;
    constexpr int CH = KCH * NCH;
    constexpr bool OUTBF = (MODE == 0 || MODE == 2);

    int tid = threadIdx.x, lane = tid & 31, wid = tid >> 5;
    int warpM = wid >> 1, warpN = wid & 1;
    int rowBase = blockIdx.x * 128;

    int grp = lane >> 3, rin = lane & 7;
    int lrow = (grp & 1) * 8 + rin;
    int lkof = (grp >> 1) * 8;

    auto prefetchB = [&](int c) {
        int k = (KCH > 1) ? c : 0;
        int n = (KCH > 1) ? 0 : c;
#pragma unroll
        for (int it = 0; it < 9; it++) {
            int idx = it * 256 + tid;            // 0..2303
            int half = idx >= 1152;
            int j = idx - half * 1152;
            int row = j / 12, seg = j - row * 12;
            const unsigned short* g =
                (half ? Wlo : Whi) + (size_t)(n * 96 + row) * KTOT + k * 96 + seg * 8;
            uint32_t sa = sb + 2 * (OFF_B + half * BHALF + row * APAD + seg * 8);
            cp_async16(sa, g);
        }
        cp_commit();
    };

    auto loadA = [&](int kchunk) {
        if (LN == 0) {
            const unsigned short* Ab = (const unsigned short*)Avoid;
            int kc = kchunk * 96;
#pragma unroll
            for (int it = 0; it < 6; it++) {
                int idx = it * 256 + tid;        // 0..1535
                int r = idx / 12, seg = idx - r * 12;
                const unsigned short* g =
                    Ab + (size_t)(rowBase + r) * KTOT + kc + seg * 8;
                cp_async16(sb + 2 * (r * APAD + seg * 8), g);
            }
            cp_commit();
        } else {
            const float* A = (const float*)Avoid;
#pragma unroll
            for (int rr = 0; rr < 16; rr++) {
                int r = wid * 16 + rr;
                int gr = rowBase + r;
                int s = (LN == 1) ? box_to_token(gr) : gr;
                const float* src = A + (size_t)s * 96;
                float v0 = src[lane], v1 = src[lane + 32], v2 = src[lane + 64];
                float s1 = v0 + v1 + v2;
                float s2 = v0 * v0 + v1 * v1 + v2 * v2;
#pragma unroll
                for (int o = 16; o; o >>= 1) {
                    s1 += __shfl_xor_sync(0xffffffffu, s1, o);
                    s2 += __shfl_xor_sync(0xffffffffu, s2, o);
                }
                float mean = s1 * (1.0f / 96.0f);
                float var  = s2 * (1.0f / 96.0f) - mean * mean;
                float inv  = rsqrtf(var + 1e-5f);
                int ro = r * APAD;
                sm[ro + lane] =
                    to_bf16((v0 - mean) * inv * gamma[lane] + beta[lane]);
                sm[ro + lane + 32] =
                    to_bf16((v1 - mean) * inv * gamma[lane + 32] + beta[lane + 32]);
                sm[ro + lane + 64] =
                    to_bf16((v2 - mean) * inv * gamma[lane + 64] + beta[lane + 64]);
            }
        }
    };

    float acc[2][6][4];
    auto resetAcc = [&]() {
#pragma unroll
        for (int mt = 0; mt < 2; mt++)
#pragma unroll
            for (int nt = 0; nt < 6; nt++)
#pragma unroll
                for (int i = 0; i < 4; i++) acc[mt][nt][i] = 0.f;
    };

    auto epilogue = [&](int nchunk) {
        int colBase = nchunk * 96;
        int qr = lane >> 2, qc = (lane & 3) * 2;
#pragma unroll
        for (int mt = 0; mt < 2; mt++) {
#pragma unroll
            for (int half = 0; half < 2; half++) {
                int row = rowBase + warpM * 32 + mt * 16 + qr + half * 8;
                int t = (MODE == 1) ? box_to_token(row) : row;
#pragma unroll
                for (int nt = 0; nt < 6; nt++) {
                    int col = colBase + warpN * 48 + nt * 8 + qc;
                    float v0 = acc[mt][nt][half * 2 + 0] + bias[col];
                    float v1 = acc[mt][nt][half * 2 + 1] + bias[col + 1];
                    if (OUTBF) {
                        if (MODE == 2) { v0 = gelu_tanh(v0); v1 = gelu_tanh(v1); }
                        uint32_t pk = (uint32_t)to_bf16(v0) |
                                      ((uint32_t)to_bf16(v1) << 16);
                        *(uint32_t*)((unsigned short*)outv +
                                     (size_t)row * NTOT + col) = pk;
                    } else {
                        const float* rr = res + (size_t)t * 96 + col;
                        float2 v = {0.5f * v0 + rr[0], 0.5f * v1 + rr[1]};
                        *(float2*)((float*)outv + (size_t)t * 96 + col) = v;
                    }
                }
            }
        }
    };

    // ---- pipeline ----
    prefetchB(0);
    loadA(0);
    cp_wait0();
    __syncthreads();

    if (KCH > 1) resetAcc();

    for (int c = 0; c < CH; c++) {
        if (NCH > 1 || CH == 1 || c == 0) resetAcc();

#pragma unroll
        for (int ks = 0; ks < 96; ks += 16) {
            uint32_t af[2][4];
#pragma unroll
            for (int mt = 0; mt < 2; mt++) {
                int r = warpM * 32 + mt * 16 + lrow;
                ldmat4(af[mt], sb + (uint32_t)(r * APAD + ks + lkof) * 2);
            }
            uint32_t bfh[6][2], bfl[6][2];
#pragma unroll
            for (int np = 0; np < 3; np++) {
                int n = warpN * 48 + np * 16 + lrow;
                uint32_t off = (uint32_t)(n * APAD + ks + lkof) * 2;
                uint32_t t4[4];
                ldmat4(t4, sb + OFF_B * 2 + off);
                bfh[np * 2][0] = t4[0]; bfh[np * 2][1] = t4[2];
                bfh[np * 2 + 1][0] = t4[1]; bfh[np * 2 + 1][1] = t4[3];
                ldmat4(t4, sb + (OFF_B + BHALF) * 2 + off);
                bfl[np * 2][0] = t4[0]; bfl[np * 2][1] = t4[2];
                bfl[np * 2 + 1][0] = t4[1]; bfl[np * 2 + 1][1] = t4[3];
            }
#pragma unroll
            for (int mt = 0; mt < 2; mt++)
#pragma unroll
                for (int nt = 0; nt < 6; nt++) {
                    mma16816(acc[mt][nt], af[mt], bfh[nt]);
                    mma16816(acc[mt][nt], af[mt], bfl[nt]);
                }
        }

        if (c + 1 < CH) {
            __syncthreads();
            prefetchB(c + 1);
            if (KCH > 1) loadA(c + 1);
        }

        if (NCH > 1) epilogue(c);

        if (c + 1 < CH) {
            cp_wait0();
            __syncthreads();
        }
    }
    if (NCH == 1) epilogue(0);
}

// ---------------------------------------------------------------------------
// Tensor-core windowed attention, bf16 q/k/v (exact). One CTA per
// (window, head), 128 threads. QK 1-pass; softmax on fragments; PV 2-pass
// (P split hi/lo, V exact). att out bf16.
// ---------------------------------------------------------------------------
__global__ void __launch_bounds__(128) attn_mma_kernel(
    const unsigned short* __restrict__ qkv,
    const float* __restrict__ mask,
    unsigned short* __restrict__ out) {
    __shared__ __align__(16) unsigned short q_s[64 * 40];
    __shared__ __align__(16) unsigned short k_s[64 * 40];
    __shared__ __align__(16) unsigned short vt[32 * 72];
    __shared__ float msk[64 * 65];

    int w = blockIdx.x >> 2, h = blockIdx.x & 3;
    int tid = threadIdx.x, lane = tid & 31, wid = tid >> 5;

#pragma unroll
    for (int it = 0; it < 16; it++) {
        int idx = it * 128 + tid;
        int t = idx >> 5, d = idx & 31;
        const unsigned short* base = qkv + (size_t)(w * 64 + t) * 288 + h * 24;
        unsigned short qv = 0, kv = 0, vv = 0;
        if (d < 24) {
            qv = base[d];
            kv = base[96 + d];
            vv = base[192 + d];
        }
        q_s[t * 40 + d] = qv;
        k_s[t * 40 + d] = kv;
        vt[d * 72 + t] = vv;
    }
    const float* mrow = mask + (size_t)(w & 511) * 4096;
#pragma unroll
    for (int it = 0; it < 8; it++) {
        int idx = it * 128 + tid;
        int r = idx >> 4, c4 = (idx & 15) * 4;
        float4 mv = *(const float4*)(mrow + r * 64 + c4);
        msk[r * 65 + c4 + 0] = mv.x;
        msk[r * 65 + c4 + 1] = mv.y;
        msk[r * 65 + c4 + 2] = mv.z;
        msk[r * 65 + c4 + 3] = mv.w;
    }
    __syncthreads();

    const uint32_t sq = smem_u32(q_s), sk = smem_u32(k_s), sv = smem_u32(vt);

    int grp = lane >> 3, rin = lane & 7;
    int lrow = (grp & 1) * 8 + rin;
    int lkof = (grp >> 1) * 8;

    // ---- S = Q K^T (1 pass) ----
    float sacc[8][4];
#pragma unroll
    for (int nt = 0; nt < 8; nt++)
#pragma unroll
        for (int i = 0; i < 4; i++) sacc[nt][i] = 0.f;

#pragma unroll
    for (int ks = 0; ks < 32; ks += 16) {
        uint32_t ah[4];
        ldmat4(ah, sq + (uint32_t)((wid * 16 + lrow) * 40 + ks + lkof) * 2);
#pragma unroll
        for (int np = 0; np < 4; np++) {
            uint32_t t4[4];
            ldmat4(t4, sk + (uint32_t)((np * 16 + lrow) * 40 + ks + lkof) * 2);
            uint32_t b0[2] = {t4[0], t4[2]}, b1[2] = {t4[1], t4[3]};
            mma16816(sacc[np * 2], ah, b0);
            mma16816(sacc[np * 2 + 1], ah, b1);
        }
    }

    const float scale = 0.2041241452319315f;
    int qr = lane >> 2, qc = (lane & 3) * 2;
    int row0 = wid * 16 + qr, row1 = row0 + 8;

    float mx0 = -1e30f, mx1 = -1e30f;
#pragma unroll
    for (int nt = 0; nt < 8; nt++) {
#pragma unroll
        for (int c = 0; c < 2; c++) {
            int col = nt * 8 + qc + c;
            float s0 = sacc[nt][c]     * scale + msk[row0 * 65 + col];
            float s1 = sacc[nt][c + 2] * scale + msk[row1 * 65 + col];
            sacc[nt][c]     = s0;
            sacc[nt][c + 2] = s1;
            mx0 = fmaxf(mx0, s0);
            mx1 = fmaxf(mx1, s1);
        }
    }
    mx0 = fmaxf(mx0, __shfl_xor_sync(0xffffffffu, mx0, 1));
    mx0 = fmaxf(mx0, __shfl_xor_sync(0xffffffffu, mx0, 2));
    mx1 = fmaxf(mx1, __shfl_xor_sync(0xffffffffu, mx1, 1));
    mx1 = fmaxf(mx1, __shfl_xor_sync(0xffffffffu, mx1, 2));

    float sum0 = 0.f, sum1 = 0.f;
    uint32_t ph01[8], ph23[8], pl01[8], pl23[8];
#pragma unroll
    for (int nt = 0; nt < 8; nt++) {
        float p0 = __expf(sacc[nt][0] - mx0);
        float p1 = __expf(sacc[nt][1] - mx0);
        float p2 = __expf(sacc[nt][2] - mx1);
        float p3 = __expf(sacc[nt][3] - mx1);
        sum0 += p0 + p1;
        sum1 += p2 + p3;
        unsigned short h0, l0, h1, l1, h2, l2, h3, l3;
        split_bf16(p0, h0, l0);
        split_bf16(p1, h1, l1);
        split_bf16(p2, h2, l2);
        split_bf16(p3, h3, l3);
        ph01[nt] = (uint32_t)h0 | ((uint32_t)h1 << 16);
        ph23[nt] = (uint32_t)h2 | ((uint32_t)h3 << 16);
        pl01[nt] = (uint32_t)l0 | ((uint32_t)l1 << 16);
        pl23[nt] = (uint32_t)l2 | ((uint32_t)l3 << 16);
    }
    sum0 += __shfl_xor_sync(0xffffffffu, sum0, 1);
    sum0 += __shfl_xor_sync(0xffffffffu, sum0, 2);
    sum1 += __shfl_xor_sync(0xffffffffu, sum1, 1);
    sum1 += __shfl_xor_sync(0xffffffffu, sum1, 2);
    float inv0 = 1.f / sum0, inv1 = 1.f / sum1;

    // ---- O = P V (P split 2-pass, V exact) ----
    float oacc[3][4];
#pragma unroll
    for (int nt = 0; nt < 3; nt++)
#pragma unroll
        for (int i = 0; i < 4; i++) oacc[nt][i] = 0.f;

#pragma unroll
    for (int ks = 0; ks < 4; ks++) {
        uint32_t Ahi[4] = {ph01[2 * ks], ph23[2 * ks], ph01[2 * ks + 1], ph23[2 * ks + 1]};
        uint32_t Alo[4] = {pl01[2 * ks], pl23[2 * ks], pl01[2 * ks + 1], pl23[2 * ks + 1]};
        uint32_t boff0 = (uint32_t)(lrow * 72 + ks * 16 + lkof) * 2;
        uint32_t boff1 = (uint32_t)((16 + lrow) * 72 + ks * 16 + lkof) * 2;
        uint32_t t4[4];
        uint32_t bh[3][2];
        ldmat4(t4, sv + boff0);
        bh[0][0] = t4[0]; bh[0][1] = t4[2];
        bh[1][0] = t4[1]; bh[1][1] = t4[3];
        ldmat4(t4, sv + boff1);
        bh[2][0] = t4[0]; bh[2][1] = t4[2];
#pragma unroll
        for (int nt = 0; nt < 3; nt++) {
            mma16816(oacc[nt], Ahi, bh[nt]);
            mma16816(oacc[nt], Alo, bh[nt]);
        }
    }

#pragma unroll
    for (int nt = 0; nt < 3; nt++) {
        int col = h * 24 + nt * 8 + qc;
        uint32_t pk0 = (uint32_t)to_bf16(oacc[nt][0] * inv0) |
                       ((uint32_t)to_bf16(oacc[nt][1] * inv0) << 16);
        uint32_t pk1 = (uint32_t)to_bf16(oacc[nt][2] * inv1) |
                       ((uint32_t)to_bf16(oacc[nt][3] * inv1) << 16);
        *(uint32_t*)(out + (size_t)(w * 64 + row0) * 96 + col) = pk0;
        *(uint32_t*)(out + (size_t)(w * 64 + row1) * 96 + col) = pk1;
    }
}

// ---------------------------------------------------------------------------
extern "C" void kernel_launch(void* const* d_in, const int* in_sizes, int n_in,
                              void* d_out, int out_size) {
    const float* inputs = (const float*)d_in[0];
    const float* n1g    = (const float*)d_in[1];
    const float* n1b    = (const float*)d_in[2];
    const float* qkv_w  = (const float*)d_in[3];
    const float* qkv_b  = (const float*)d_in[4];
    const float* proj_w = (const float*)d_in[5];
    const float* proj_b = (const float*)d_in[6];
    const float* n2g    = (const float*)d_in[7];
    const float* n2b    = (const float*)d_in[8];
    const float* w1     = (const float*)d_in[9];
    const float* b1     = (const float*)d_in[10];
    const float* w2     = (const float*)d_in[11];
    const float* b2     = (const float*)d_in[12];
    const float* mask   = (const float*)d_in[13];
    float* out = (float*)d_out;

    unsigned short *qkv, *att, *h1;
    float* x;
    cudaGetSymbolAddress((void**)&qkv, g_qkv);
    cudaGetSymbolAddress((void**)&att, g_att);
    cudaGetSymbolAddress((void**)&x,   g_x);
    cudaGetSymbolAddress((void**)&h1,  g_h1);

    unsigned short *wqh, *wql, *wph, *wpl, *w1h, *w1l, *w2h, *w2l;
    cudaGetSymbolAddress((void**)&wqh, g_wqkv_hi);
    cudaGetSymbolAddress((void**)&wql, g_wqkv_lo);
    cudaGetSymbolAddress((void**)&wph, g_wproj_hi);
    cudaGetSymbolAddress((void**)&wpl, g_wproj_lo);
    cudaGetSymbolAddress((void**)&w1h, g_wm1_hi);
    cudaGetSymbolAddress((void**)&w1l, g_wm1_lo);
    cudaGetSymbolAddress((void**)&w2h, g_wm2_hi);
    cudaGetSymbolAddress((void**)&w2l, g_wm2_lo);

    cudaFuncSetAttribute(mma_gemm<1, 3, 1, 0>,
                         cudaFuncAttributeMaxDynamicSharedMemorySize, SMEM_BYTES);
    cudaFuncSetAttribute(mma_gemm<1, 1, 0, 1>,
                         cudaFuncAttributeMaxDynamicSharedMemorySize, SMEM_BYTES);
    cudaFuncSetAttribute(mma_gemm<1, 4, 2, 2>,
                         cudaFuncAttributeMaxDynamicSharedMemorySize, SMEM_BYTES);
    cudaFuncSetAttribute(mma_gemm<4, 1, 0, 3>,
                         cudaFuncAttributeMaxDynamicSharedMemorySize, SMEM_BYTES);

    // 0. weight prep (split + transpose), single launch
    prep_all<<<432, 256>>>(qkv_w, proj_w, w1, w2,
                           wqh, wql, wph, wpl, w1h, w1l, w2h, w2l);
    // 1. LN1 (fused) + box partition + QKV -> bf16
    mma_gemm<1, 3, 1, 0><<<1024, 256, SMEM_BYTES>>>(
        inputs, n1g, n1b, wqh, wql, qkv_b, qkv, nullptr);
    // 2. Windowed attention (bf16 in/out)
    attn_mma_kernel<<<8192, 128>>>(qkv, mask, att);
    // 3. Proj (A bf16) + box reverse + roll + 0.5x + shortcut -> x fp32
    mma_gemm<1, 1, 0, 1><<<1024, 256, SMEM_BYTES>>>(
        att, nullptr, nullptr, wph, wpl, proj_b, x, inputs);
    // 4. LN2 (fused) + MLP1 + gelu -> h1 bf16
    mma_gemm<1, 4, 2, 2><<<1024, 256, SMEM_BYTES>>>(
        x, n2g, n2b, w1h, w1l, b1, h1, nullptr);
    // 5. MLP2 (A bf16) + 0.5x + residual -> out fp32
    mma_gemm<4, 1, 0, 3><<<1024, 256, SMEM_BYTES>>>(
        h1, nullptr, nullptr, w2h, w2l, b2, out, x);
}

// round 10
// speedup vs baseline: 4.8096x; 1.1026x over previous
#include <cuda_runtime.h>
#include <cuda_bf16.h>
#include <stdint.h>

// ---------------------------------------------------------------------------
// Swin-3D block on GB300. R9: attention mask computed inline from window
// geometry (no 134 MB mask traffic); proj+LN2+mlp1 fused into one kernel
// (x kept in registers through LN2). bf16 activations, B split hi/lo 2-pass.
// B=4, R=32, C=96, W=4, HEADS=4, dh=24, N=64/window, T=131072 tokens.
// ---------------------------------------------------------------------------

#define T_TOKENS 131072

// activations
__device__ __align__(16) unsigned short g_qkv[131072 * 288];  // bf16
__device__ __align__(16) unsigned short g_att[131072 * 96];   // bf16
__device__ float g_x[131072 * 96];                            // fp32 residual
__device__ __align__(16) unsigned short g_h1[131072 * 384];   // bf16

// split-precision transposed weights: layout [N][K], bf16 bits
__device__ __align__(16) unsigned short g_wqkv_hi[288 * 96], g_wqkv_lo[288 * 96];
__device__ __align__(16) unsigned short g_wproj_hi[96 * 96], g_wproj_lo[96 * 96];
__device__ __align__(16) unsigned short g_wm1_hi[384 * 96],  g_wm1_lo[384 * 96];
__device__ __align__(16) unsigned short g_wm2_hi[96 * 384],  g_wm2_lo[96 * 384];

// ---------------------------------------------------------------------------
__device__ __forceinline__ int box_to_token(int r) {
    int w = r >> 6, n = r & 63;
    int b  = w >> 9;
    int bi = (w >> 6) & 7, bj = (w >> 3) & 7, bk = w & 7;
    int wi = n >> 4, wj = (n >> 2) & 3, wk = n & 3;
    int i = (bi * 4 + wi + 2) & 31;
    int j = (bj * 4 + wj + 2) & 31;
    int k = (bk * 4 + wk + 2) & 31;
    return ((b * 32 + i) * 32 + j) * 32 + k;
}

__device__ __forceinline__ float gelu_tanh(float x) {
    const float k0 = 0.7978845608028654f;
    const float k1 = 0.044715f;
    float x3 = x * x * x;
    float t = tanhf(k0 * (x + k1 * x3));
    return 0.5f * x * (1.0f + t);
}

__device__ __forceinline__ uint32_t smem_u32(const void* p) {
    uint32_t a;
    asm("{ .reg .u64 t; cvta.to.shared.u64 t, %1; cvt.u32.u64 %0, t; }"
        : "=r"(a) : "l"(p));
    return a;
}

__device__ __forceinline__ void ldmat4(uint32_t* r, uint32_t addr) {
    asm volatile("ldmatrix.sync.aligned.m8n8.x4.shared.b16 {%0,%1,%2,%3}, [%4];"
                 : "=r"(r[0]), "=r"(r[1]), "=r"(r[2]), "=r"(r[3]) : "r"(addr));
}

__device__ __forceinline__ void mma16816(float* d, const uint32_t* a,
                                         const uint32_t* b) {
    asm volatile(
        "mma.sync.aligned.m16n8k16.row.col.f32.bf16.bf16.f32 "
        "{%0,%1,%2,%3}, {%4,%5,%6,%7}, {%8,%9}, {%0,%1,%2,%3};"
        : "+f"(d[0]), "+f"(d[1]), "+f"(d[2]), "+f"(d[3])
        : "r"(a[0]), "r"(a[1]), "r"(a[2]), "r"(a[3]), "r"(b[0]), "r"(b[1]));
}

__device__ __forceinline__ void split_bf16(float x, unsigned short& h,
                                           unsigned short& l) {
    __nv_bfloat16 hb = __float2bfloat16(x);
    float r = x - __bfloat162float(hb);
    __nv_bfloat16 lb = __float2bfloat16(r);
    h = __bfloat16_as_ushort(hb);
    l = __bfloat16_as_ushort(lb);
}

__device__ __forceinline__ unsigned short to_bf16(float x) {
    return __bfloat16_as_ushort(__float2bfloat16(x));
}

__device__ __forceinline__ void cp_async16(uint32_t saddr, const void* g) {
    asm volatile("cp.async.ca.shared.global [%0], [%1], 16;"
                 :: "r"(saddr), "l"(g));
}
__device__ __forceinline__ void cp_commit() {
    asm volatile("cp.async.commit_group;" ::: "memory");
}
__device__ __forceinline__ void cp_wait0() {
    asm volatile("cp.async.wait_group 0;" ::: "memory");
}

// ---------------------------------------------------------------------------
// Weight prep, all 4 matrices in one launch. W[K,NTOT] -> Wt_hi/lo [NTOT][K].
// ---------------------------------------------------------------------------
__global__ void prep_all(const float* __restrict__ qkv_w,
                         const float* __restrict__ proj_w,
                         const float* __restrict__ w1,
                         const float* __restrict__ w2,
                         unsigned short* wqh, unsigned short* wql,
                         unsigned short* wph, unsigned short* wpl,
                         unsigned short* w1h, unsigned short* w1l,
                         unsigned short* w2h, unsigned short* w2l) {
    int idx = blockIdx.x * 256 + threadIdx.x;
    const float* W;
    unsigned short *hi, *lo;
    int K, NTOT, local;
    if (idx < 27648) {
        W = qkv_w; hi = wqh; lo = wql; K = 96; NTOT = 288; local = idx;
    } else if (idx < 36864) {
        W = proj_w; hi = wph; lo = wpl; K = 96; NTOT = 96; local = idx - 27648;
    } else if (idx < 73728) {
        W = w1; hi = w1h; lo = w1l; K = 96; NTOT = 384; local = idx - 36864;
    } else if (idx < 110592) {
        W = w2; hi = w2h; lo = w2l; K = 384; NTOT = 96; local = idx - 73728;
    } else return;
    int n = local / K, k = local - n * K;
    unsigned short h, l;
    split_bf16(W[(size_t)k * NTOT + n], h, l);
    hi[local] = h;
    lo[local] = l;
}

// ---------------------------------------------------------------------------
// Generic GEMM (used for qkv and mlp2): A bf16-exact, B split 2-pass.
// LN: 0 A bf16 gmem via cp.async | 1 LN + box gather (fp32 in)
// MODE: 0 bias, bf16 out | 3 0.5x+res, fp32 out
// ---------------------------------------------------------------------------
#define APAD 104
#define OFF_B 13312                   // B hi (u16 units)
#define BHALF 9984                    // 96*104
#define SMEM_U16 (13312 + 2 * 9984)   // 33280
#define SMEM_BYTES (SMEM_U16 * 2)     // 66560
#define SMEM_FUSED (SMEM_BYTES + 2048)

template <int KCH, int NCH, int LN, int MODE>
__global__ void __launch_bounds__(256, 2) mma_gemm(
    const void* __restrict__ Avoid,
    const float* __restrict__ gamma,
    const float* __restrict__ beta,
    const unsigned short* __restrict__ Whi,
    const unsigned short* __restrict__ Wlo,
    const float* __restrict__ bias,
    void* __restrict__ outv,
    const float* __restrict__ res) {
    extern __shared__ __align__(16) unsigned short sm[];
    const uint32_t sb = smem_u32(sm);
    constexpr int KTOT = 96 * KCH;
    constexpr int NTOT = 96 * NCH;
    constexpr int CH = KCH * NCH;
    constexpr bool OUTBF = (MODE == 0);

    int tid = threadIdx.x, lane = tid & 31, wid = tid >> 5;
    int warpM = wid >> 1, warpN = wid & 1;
    int rowBase = blockIdx.x * 128;

    int grp = lane >> 3, rin = lane & 7;
    int lrow = (grp & 1) * 8 + rin;
    int lkof = (grp >> 1) * 8;

    auto prefetchB = [&](int c) {
        int k = (KCH > 1) ? c : 0;
        int n = (KCH > 1) ? 0 : c;
#pragma unroll
        for (int it = 0; it < 9; it++) {
            int idx = it * 256 + tid;
            int half = idx >= 1152;
            int j = idx - half * 1152;
            int row = j / 12, seg = j - row * 12;
            const unsigned short* g =
                (half ? Wlo : Whi) + (size_t)(n * 96 + row) * KTOT + k * 96 + seg * 8;
            uint32_t sa = sb + 2 * (OFF_B + half * BHALF + row * APAD + seg * 8);
            cp_async16(sa, g);
        }
        cp_commit();
    };

    auto loadA = [&](int kchunk) {
        if (LN == 0) {
            const unsigned short* Ab = (const unsigned short*)Avoid;
            int kc = kchunk * 96;
#pragma unroll
            for (int it = 0; it < 6; it++) {
                int idx = it * 256 + tid;
                int r = idx / 12, seg = idx - r * 12;
                const unsigned short* g =
                    Ab + (size_t)(rowBase + r) * KTOT + kc + seg * 8;
                cp_async16(sb + 2 * (r * APAD + seg * 8), g);
            }
            cp_commit();
        } else {
            const float* A = (const float*)Avoid;
#pragma unroll
            for (int rr = 0; rr < 16; rr++) {
                int r = wid * 16 + rr;
                int gr = rowBase + r;
                int s = box_to_token(gr);
                const float* src = A + (size_t)s * 96;
                float v0 = src[lane], v1 = src[lane + 32], v2 = src[lane + 64];
                float s1 = v0 + v1 + v2;
                float s2 = v0 * v0 + v1 * v1 + v2 * v2;
#pragma unroll
                for (int o = 16; o; o >>= 1) {
                    s1 += __shfl_xor_sync(0xffffffffu, s1, o);
                    s2 += __shfl_xor_sync(0xffffffffu, s2, o);
                }
                float mean = s1 * (1.0f / 96.0f);
                float var  = s2 * (1.0f / 96.0f) - mean * mean;
                float inv  = rsqrtf(var + 1e-5f);
                int ro = r * APAD;
                sm[ro + lane] =
                    to_bf16((v0 - mean) * inv * gamma[lane] + beta[lane]);
                sm[ro + lane + 32] =
                    to_bf16((v1 - mean) * inv * gamma[lane + 32] + beta[lane + 32]);
                sm[ro + lane + 64] =
                    to_bf16((v2 - mean) * inv * gamma[lane + 64] + beta[lane + 64]);
            }
        }
    };

    float acc[2][6][4];
    auto resetAcc = [&]() {
#pragma unroll
        for (int mt = 0; mt < 2; mt++)
#pragma unroll
            for (int nt = 0; nt < 6; nt++)
#pragma unroll
                for (int i = 0; i < 4; i++) acc[mt][nt][i] = 0.f;
    };

    auto kloop = [&]() {
#pragma unroll
        for (int ks = 0; ks < 96; ks += 16) {
            uint32_t af[2][4];
#pragma unroll
            for (int mt = 0; mt < 2; mt++) {
                int r = warpM * 32 + mt * 16 + lrow;
                ldmat4(af[mt], sb + (uint32_t)(r * APAD + ks + lkof) * 2);
            }
            uint32_t bfh[6][2], bfl[6][2];
#pragma unroll
            for (int np = 0; np < 3; np++) {
                int n = warpN * 48 + np * 16 + lrow;
                uint32_t off = (uint32_t)(n * APAD + ks + lkof) * 2;
                uint32_t t4[4];
                ldmat4(t4, sb + OFF_B * 2 + off);
                bfh[np * 2][0] = t4[0]; bfh[np * 2][1] = t4[2];
                bfh[np * 2 + 1][0] = t4[1]; bfh[np * 2 + 1][1] = t4[3];
                ldmat4(t4, sb + (OFF_B + BHALF) * 2 + off);
                bfl[np * 2][0] = t4[0]; bfl[np * 2][1] = t4[2];
                bfl[np * 2 + 1][0] = t4[1]; bfl[np * 2 + 1][1] = t4[3];
            }
#pragma unroll
            for (int mt = 0; mt < 2; mt++)
#pragma unroll
                for (int nt = 0; nt < 6; nt++) {
                    mma16816(acc[mt][nt], af[mt], bfh[nt]);
                    mma16816(acc[mt][nt], af[mt], bfl[nt]);
                }
        }
    };

    auto epilogue = [&](int nchunk) {
        int colBase = nchunk * 96;
        int qr = lane >> 2, qc = (lane & 3) * 2;
#pragma unroll
        for (int mt = 0; mt < 2; mt++) {
#pragma unroll
            for (int half = 0; half < 2; half++) {
                int row = rowBase + warpM * 32 + mt * 16 + qr + half * 8;
#pragma unroll
                for (int nt = 0; nt < 6; nt++) {
                    int col = colBase + warpN * 48 + nt * 8 + qc;
                    float v0 = acc[mt][nt][half * 2 + 0] + bias[col];
                    float v1 = acc[mt][nt][half * 2 + 1] + bias[col + 1];
                    if (OUTBF) {
                        uint32_t pk = (uint32_t)to_bf16(v0) |
                                      ((uint32_t)to_bf16(v1) << 16);
                        *(uint32_t*)((unsigned short*)outv +
                                     (size_t)row * NTOT + col) = pk;
                    } else {
                        const float* rr = res + (size_t)row * 96 + col;
                        float2 v = {0.5f * v0 + rr[0], 0.5f * v1 + rr[1]};
                        *(float2*)((float*)outv + (size_t)row * 96 + col) = v;
                    }
                }
            }
        }
    };

    prefetchB(0);
    loadA(0);
    cp_wait0();
    __syncthreads();

    if (KCH > 1) resetAcc();

    for (int c = 0; c < CH; c++) {
        if (NCH > 1 || CH == 1 || c == 0) resetAcc();
        kloop();
        if (c + 1 < CH) {
            __syncthreads();
            prefetchB(c + 1);
            if (KCH > 1) loadA(c + 1);
        }
        if (NCH > 1) epilogue(c);
        if (c + 1 < CH) {
            cp_wait0();
            __syncthreads();
        }
    }
    if (NCH == 1) epilogue(0);
}

// ---------------------------------------------------------------------------
// Fused proj + residual + LN2 + mlp1(+gelu). CTA = 128 box rows, 256 threads.
// x values stay in accumulators through LN2 (quad-shfl + 2KB smem reduce).
// Writes x (fp32, token order) and h1 (bf16, token order).
// ---------------------------------------------------------------------------
__global__ void __launch_bounds__(256, 2) fused_proj_mlp1(
    const unsigned short* __restrict__ att,
    const float* __restrict__ res,
    const unsigned short* __restrict__ Wp_hi,
    const unsigned short* __restrict__ Wp_lo,
    const float* __restrict__ proj_b,
    const float* __restrict__ n2g,
    const float* __restrict__ n2b,
    const unsigned short* __restrict__ W1_hi,
    const unsigned short* __restrict__ W1_lo,
    const float* __restrict__ b1,
    float* __restrict__ x,
    unsigned short* __restrict__ h1) {
    extern __shared__ __align__(16) unsigned short sm[];
    const uint32_t sb = smem_u32(sm);
    float* red = (float*)(sm + SMEM_U16);   // 128 rows * 4 floats

    int tid = threadIdx.x, lane = tid & 31, wid = tid >> 5;
    int warpM = wid >> 1, warpN = wid & 1;
    int rowBase = blockIdx.x * 128;

    int grp = lane >> 3, rin = lane & 7;
    int lrow = (grp & 1) * 8 + rin;
    int lkof = (grp >> 1) * 8;
    int qr = lane >> 2, qc = (lane & 3) * 2;

    auto prefetchB = [&](const unsigned short* Whi, const unsigned short* Wlo,
                         int n) {
#pragma unroll
        for (int it = 0; it < 9; it++) {
            int idx = it * 256 + tid;
            int half = idx >= 1152;
            int j = idx - half * 1152;
            int row = j / 12, seg = j - row * 12;
            const unsigned short* g =
                (half ? Wlo : Whi) + (size_t)(n * 96 + row) * 96 + seg * 8;
            uint32_t sa = sb + 2 * (OFF_B + half * BHALF + row * APAD + seg * 8);
            cp_async16(sa, g);
        }
        cp_commit();
    };

    float acc[2][6][4];
    auto resetAcc = [&]() {
#pragma unroll
        for (int mt = 0; mt < 2; mt++)
#pragma unroll
            for (int nt = 0; nt < 6; nt++)
#pragma unroll
                for (int i = 0; i < 4; i++) acc[mt][nt][i] = 0.f;
    };

    auto kloop = [&]() {
#pragma unroll
        for (int ks = 0; ks < 96; ks += 16) {
            uint32_t af[2][4];
#pragma unroll
            for (int mt = 0; mt < 2; mt++) {
                int r = warpM * 32 + mt * 16 + lrow;
                ldmat4(af[mt], sb + (uint32_t)(r * APAD + ks + lkof) * 2);
            }
            uint32_t bfh[6][2], bfl[6][2];
#pragma unroll
            for (int np = 0; np < 3; np++) {
                int n = warpN * 48 + np * 16 + lrow;
                uint32_t off = (uint32_t)(n * APAD + ks + lkof) * 2;
                uint32_t t4[4];
                ldmat4(t4, sb + OFF_B * 2 + off);
                bfh[np * 2][0] = t4[0]; bfh[np * 2][1] = t4[2];
                bfh[np * 2 + 1][0] = t4[1]; bfh[np * 2 + 1][1] = t4[3];
                ldmat4(t4, sb + (OFF_B + BHALF) * 2 + off);
                bfl[np * 2][0] = t4[0]; bfl[np * 2][1] = t4[2];
                bfl[np * 2 + 1][0] = t4[1]; bfl[np * 2 + 1][1] = t4[3];
            }
#pragma unroll
            for (int mt = 0; mt < 2; mt++)
#pragma unroll
                for (int nt = 0; nt < 6; nt++) {
                    mma16816(acc[mt][nt], af[mt], bfh[nt]);
                    mma16816(acc[mt][nt], af[mt], bfl[nt]);
                }
        }
    };

    // ---- phase A: proj ----
    prefetchB(Wp_hi, Wp_lo, 0);
    {   // A <- att bf16
#pragma unroll
        for (int it = 0; it < 6; it++) {
            int idx = it * 256 + tid;
            int r = idx / 12, seg = idx - r * 12;
            cp_async16(sb + 2 * (r * APAD + seg * 8),
                       att + (size_t)(rowBase + r) * 96 + seg * 8);
        }
        cp_commit();
    }
    cp_wait0();
    __syncthreads();
    resetAcc();
    kloop();
    __syncthreads();
    prefetchB(W1_hi, W1_lo, 0);   // overlaps with epilogue + LN2

    // ---- proj epilogue: x = 0.5*(acc+b) + res; keep in acc; row sums ----
#pragma unroll
    for (int mt = 0; mt < 2; mt++) {
#pragma unroll
        for (int half = 0; half < 2; half++) {
            int rl = warpM * 32 + mt * 16 + qr + half * 8;
            int t = box_to_token(rowBase + rl);
            const float* rr = res + (size_t)t * 96;
            float* xo = x + (size_t)t * 96;
            float rs1 = 0.f, rs2 = 0.f;
#pragma unroll
            for (int nt = 0; nt < 6; nt++) {
                int col = warpN * 48 + nt * 8 + qc;
                float v0 = acc[mt][nt][half * 2 + 0] + proj_b[col];
                float v1 = acc[mt][nt][half * 2 + 1] + proj_b[col + 1];
                v0 = 0.5f * v0 + rr[col];
                v1 = 0.5f * v1 + rr[col + 1];
                float2 v = {v0, v1};
                *(float2*)(xo + col) = v;
                acc[mt][nt][half * 2 + 0] = v0;
                acc[mt][nt][half * 2 + 1] = v1;
                rs1 += v0 + v1;
                rs2 += v0 * v0 + v1 * v1;
            }
            rs1 += __shfl_xor_sync(0xffffffffu, rs1, 1);
            rs1 += __shfl_xor_sync(0xffffffffu, rs1, 2);
            rs2 += __shfl_xor_sync(0xffffffffu, rs2, 1);
            rs2 += __shfl_xor_sync(0xffffffffu, rs2, 2);
            if ((lane & 3) == 0) {
                red[rl * 4 + warpN * 2 + 0] = rs1;
                red[rl * 4 + warpN * 2 + 1] = rs2;
            }
        }
    }
    __syncthreads();

    // ---- LN2: normalize acc, write bf16 A-tile ----
#pragma unroll
    for (int mt = 0; mt < 2; mt++) {
#pragma unroll
        for (int half = 0; half < 2; half++) {
            int rl = warpM * 32 + mt * 16 + qr + half * 8;
            float s1 = red[rl * 4 + 0] + red[rl * 4 + 2];
            float s2 = red[rl * 4 + 1] + red[rl * 4 + 3];
            float mean = s1 * (1.0f / 96.0f);
            float var  = s2 * (1.0f / 96.0f) - mean * mean;
            float inv  = rsqrtf(var + 1e-5f);
#pragma unroll
            for (int nt = 0; nt < 6; nt++) {
                int col = warpN * 48 + nt * 8 + qc;
                float y0 = (acc[mt][nt][half * 2 + 0] - mean) * inv * n2g[col]
                           + n2b[col];
                float y1 = (acc[mt][nt][half * 2 + 1] - mean) * inv * n2g[col + 1]
                           + n2b[col + 1];
                uint32_t pk = (uint32_t)to_bf16(y0) | ((uint32_t)to_bf16(y1) << 16);
                *(uint32_t*)(sm + rl * APAD + col) = pk;
            }
        }
    }
    cp_wait0();
    __syncthreads();

    // ---- phase B: mlp1, 4 slabs of 96 ----
    for (int c = 0; c < 4; c++) {
        resetAcc();
        kloop();
        if (c < 3) {
            __syncthreads();
            prefetchB(W1_hi, W1_lo, c + 1);
        }
#pragma unroll
        for (int mt = 0; mt < 2; mt++) {
#pragma unroll
            for (int half = 0; half < 2; half++) {
                int rl = warpM * 32 + mt * 16 + qr + half * 8;
                int t = box_to_token(rowBase + rl);
#pragma unroll
                for (int nt = 0; nt < 6; nt++) {
                    int col = c * 96 + warpN * 48 + nt * 8 + qc;
                    float v0 = gelu_tanh(acc[mt][nt][half * 2 + 0] + b1[col]);
                    float v1 = gelu_tanh(acc[mt][nt][half * 2 + 1] + b1[col + 1]);
                    uint32_t pk = (uint32_t)to_bf16(v0) |
                                  ((uint32_t)to_bf16(v1) << 16);
                    *(uint32_t*)(h1 + (size_t)t * 384 + col) = pk;
                }
            }
        }
        if (c < 3) {
            cp_wait0();
            __syncthreads();
        }
    }
}

// ---------------------------------------------------------------------------
// Tensor-core windowed attention, mask computed inline from window geometry.
// One CTA per (window, head), 128 threads. QK 1-pass, PV 2-pass.
// ---------------------------------------------------------------------------
__global__ void __launch_bounds__(128) attn_mma_kernel(
    const unsigned short* __restrict__ qkv,
    unsigned short* __restrict__ out) {
    __shared__ __align__(16) unsigned short q_s[64 * 40];
    __shared__ __align__(16) unsigned short k_s[64 * 40];
    __shared__ __align__(16) unsigned short vt[32 * 72];
    __shared__ unsigned char codes[64];

    int w = blockIdx.x >> 2, h = blockIdx.x & 3;
    int tid = threadIdx.x, lane = tid & 31, wid = tid >> 5;

    if (tid < 64) {
        int n = tid;
        int bi = (w >> 6) & 7, bj = (w >> 3) & 7, bk = w & 7;
        int wi = n >> 4, wj = (n >> 2) & 3, wk = n & 3;
        int rx = (bi == 7) ? ((wi < 2) ? 1 : 2) : 0;
        int ry = (bj == 7) ? ((wj < 2) ? 1 : 2) : 0;
        int rz = (bk == 7) ? ((wk < 2) ? 1 : 2) : 0;
        codes[n] = (unsigned char)(rx * 9 + ry * 3 + rz);
    }
#pragma unroll
    for (int it = 0; it < 16; it++) {
        int idx = it * 128 + tid;
        int t = idx >> 5, d = idx & 31;
        const unsigned short* base = qkv + (size_t)(w * 64 + t) * 288 + h * 24;
        unsigned short qv = 0, kv = 0, vv = 0;
        if (d < 24) {
            qv = base[d];
            kv = base[96 + d];
            vv = base[192 + d];
        }
        q_s[t * 40 + d] = qv;
        k_s[t * 40 + d] = kv;
        vt[d * 72 + t] = vv;
    }
    __syncthreads();

    const uint32_t sq = smem_u32(q_s), sk = smem_u32(k_s), sv = smem_u32(vt);

    int grp = lane >> 3, rin = lane & 7;
    int lrow = (grp & 1) * 8 + rin;
    int lkof = (grp >> 1) * 8;

    float sacc[8][4];
#pragma unroll
    for (int nt = 0; nt < 8; nt++)
#pragma unroll
        for (int i = 0; i < 4; i++) sacc[nt][i] = 0.f;

#pragma unroll
    for (int ks = 0; ks < 32; ks += 16) {
        uint32_t ah[4];
        ldmat4(ah, sq + (uint32_t)((wid * 16 + lrow) * 40 + ks + lkof) * 2);
#pragma unroll
        for (int np = 0; np < 4; np++) {
            uint32_t t4[4];
            ldmat4(t4, sk + (uint32_t)((np * 16 + lrow) * 40 + ks + lkof) * 2);
            uint32_t b0[2] = {t4[0], t4[2]}, b1r[2] = {t4[1], t4[3]};
            mma16816(sacc[np * 2], ah, b0);
            mma16816(sacc[np * 2 + 1], ah, b1r);
        }
    }

    const float scale = 0.2041241452319315f;
    int qr = lane >> 2, qc = (lane & 3) * 2;
    int row0 = wid * 16 + qr, row1 = row0 + 8;
    unsigned char c0 = codes[row0], c1 = codes[row1];

    float mx0 = -1e30f, mx1 = -1e30f;
#pragma unroll
    for (int nt = 0; nt < 8; nt++) {
#pragma unroll
        for (int c = 0; c < 2; c++) {
            int col = nt * 8 + qc + c;
            unsigned char cc = codes[col];
            float s0 = sacc[nt][c]     * scale + ((cc == c0) ? 0.f : -100.f);
            float s1 = sacc[nt][c + 2] * scale + ((cc == c1) ? 0.f : -100.f);
            sacc[nt][c]     = s0;
            sacc[nt][c + 2] = s1;
            mx0 = fmaxf(mx0, s0);
            mx1 = fmaxf(mx1, s1);
        }
    }
    mx0 = fmaxf(mx0, __shfl_xor_sync(0xffffffffu, mx0, 1));
    mx0 = fmaxf(mx0, __shfl_xor_sync(0xffffffffu, mx0, 2));
    mx1 = fmaxf(mx1, __shfl_xor_sync(0xffffffffu, mx1, 1));
    mx1 = fmaxf(mx1, __shfl_xor_sync(0xffffffffu, mx1, 2));

    float sum0 = 0.f, sum1 = 0.f;
    uint32_t ph01[8], ph23[8], pl01[8], pl23[8];
#pragma unroll
    for (int nt = 0; nt < 8; nt++) {
        float p0 = __expf(sacc[nt][0] - mx0);
        float p1 = __expf(sacc[nt][1] - mx0);
        float p2 = __expf(sacc[nt][2] - mx1);
        float p3 = __expf(sacc[nt][3] - mx1);
        sum0 += p0 + p1;
        sum1 += p2 + p3;
        unsigned short h0, l0, h1v, l1, h2, l2, h3, l3;
        split_bf16(p0, h0, l0);
        split_bf16(p1, h1v, l1);
        split_bf16(p2, h2, l2);
        split_bf16(p3, h3, l3);
        ph01[nt] = (uint32_t)h0 | ((uint32_t)h1v << 16);
        ph23[nt] = (uint32_t)h2 | ((uint32_t)h3 << 16);
        pl01[nt] = (uint32_t)l0 | ((uint32_t)l1 << 16);
        pl23[nt] = (uint32_t)l2 | ((uint32_t)l3 << 16);
    }
    sum0 += __shfl_xor_sync(0xffffffffu, sum0, 1);
    sum0 += __shfl_xor_sync(0xffffffffu, sum0, 2);
    sum1 += __shfl_xor_sync(0xffffffffu, sum1, 1);
    sum1 += __shfl_xor_sync(0xffffffffu, sum1, 2);
    float inv0 = 1.f / sum0, inv1 = 1.f / sum1;

    float oacc[3][4];
#pragma unroll
    for (int nt = 0; nt < 3; nt++)
#pragma unroll
        for (int i = 0; i < 4; i++) oacc[nt][i] = 0.f;

#pragma unroll
    for (int ks = 0; ks < 4; ks++) {
        uint32_t Ahi[4] = {ph01[2 * ks], ph23[2 * ks], ph01[2 * ks + 1], ph23[2 * ks + 1]};
        uint32_t Alo[4] = {pl01[2 * ks], pl23[2 * ks], pl01[2 * ks + 1], pl23[2 * ks + 1]};
        uint32_t boff0 = (uint32_t)(lrow * 72 + ks * 16 + lkof) * 2;
        uint32_t boff1 = (uint32_t)((16 + lrow) * 72 + ks * 16 + lkof) * 2;
        uint32_t t4[4];
        uint32_t bh[3][2];
        ldmat4(t4, sv + boff0);
        bh[0][0] = t4[0]; bh[0][1] = t4[2];
        bh[1][0] = t4[1]; bh[1][1] = t4[3];
        ldmat4(t4, sv + boff1);
        bh[2][0] = t4[0]; bh[2][1] = t4[2];
#pragma unroll
        for (int nt = 0; nt < 3; nt++) {
            mma16816(oacc[nt], Ahi, bh[nt]);
            mma16816(oacc[nt], Alo, bh[nt]);
        }
    }

#pragma unroll
    for (int nt = 0; nt < 3; nt++) {
        int col = h * 24 + nt * 8 + qc;
        uint32_t pk0 = (uint32_t)to_bf16(oacc[nt][0] * inv0) |
                       ((uint32_t)to_bf16(oacc[nt][1] * inv0) << 16);
        uint32_t pk1 = (uint32_t)to_bf16(oacc[nt][2] * inv1) |
                       ((uint32_t)to_bf16(oacc[nt][3] * inv1) << 16);
        *(uint32_t*)(out + (size_t)(w * 64 + row0) * 96 + col) = pk0;
        *(uint32_t*)(out + (size_t)(w * 64 + row1) * 96 + col) = pk1;
    }
}

// ---------------------------------------------------------------------------
extern "C" void kernel_launch(void* const* d_in, const int* in_sizes, int n_in,
                              void* d_out, int out_size) {
    const float* inputs = (const float*)d_in[0];
    const float* n1g    = (const float*)d_in[1];
    const float* n1b    = (const float*)d_in[2];
    const float* qkv_w  = (const float*)d_in[3];
    const float* qkv_b  = (const float*)d_in[4];
    const float* proj_w = (const float*)d_in[5];
    const float* proj_b = (const float*)d_in[6];
    const float* n2g    = (const float*)d_in[7];
    const float* n2b    = (const float*)d_in[8];
    const float* w1     = (const float*)d_in[9];
    const float* b1     = (const float*)d_in[10];
    const float* w2     = (const float*)d_in[11];
    const float* b2     = (const float*)d_in[12];
    float* out = (float*)d_out;

    unsigned short *qkv, *att, *h1;
    float* x;
    cudaGetSymbolAddress((void**)&qkv, g_qkv);
    cudaGetSymbolAddress((void**)&att, g_att);
    cudaGetSymbolAddress((void**)&x,   g_x);
    cudaGetSymbolAddress((void**)&h1,  g_h1);

    unsigned short *wqh, *wql, *wph, *wpl, *w1h, *w1l, *w2h, *w2l;
    cudaGetSymbolAddress((void**)&wqh, g_wqkv_hi);
    cudaGetSymbolAddress((void**)&wql, g_wqkv_lo);
    cudaGetSymbolAddress((void**)&wph, g_wproj_hi);
    cudaGetSymbolAddress((void**)&wpl, g_wproj_lo);
    cudaGetSymbolAddress((void**)&w1h, g_wm1_hi);
    cudaGetSymbolAddress((void**)&w1l, g_wm1_lo);
    cudaGetSymbolAddress((void**)&w2h, g_wm2_hi);
    cudaGetSymbolAddress((void**)&w2l, g_wm2_lo);

    cudaFuncSetAttribute(mma_gemm<1, 3, 1, 0>,
                         cudaFuncAttributeMaxDynamicSharedMemorySize, SMEM_BYTES);
    cudaFuncSetAttribute(mma_gemm<4, 1, 0, 3>,
                         cudaFuncAttributeMaxDynamicSharedMemorySize, SMEM_BYTES);
    cudaFuncSetAttribute(fused_proj_mlp1,
                         cudaFuncAttributeMaxDynamicSharedMemorySize, SMEM_FUSED);

    // 0. weight prep
    prep_all<<<432, 256>>>(qkv_w, proj_w, w1, w2,
                           wqh, wql, wph, wpl, w1h, w1l, w2h, w2l);
    // 1. LN1 (fused) + box partition + QKV -> bf16
    mma_gemm<1, 3, 1, 0><<<1024, 256, SMEM_BYTES>>>(
        inputs, n1g, n1b, wqh, wql, qkv_b, qkv, nullptr);
    // 2. Windowed attention (inline mask)
    attn_mma_kernel<<<8192, 128>>>(qkv, att);
    // 3. Fused proj + residual + LN2 + MLP1 + gelu -> x, h1
    fused_proj_mlp1<<<1024, 256, SMEM_FUSED>>>(
        att, inputs, wph, wpl, proj_b, n2g, n2b, w1h, w1l, b1, x, h1);
    // 4. MLP2 + 0.5x + residual -> out
    mma_gemm<4, 1, 0, 3><<<1024, 256, SMEM_BYTES>>>(
        h1, nullptr, nullptr, w2h, w2l, b2, out, x);
}

// round 14
// speedup vs baseline: 5.0223x; 1.0442x over previous
#include <cuda_runtime.h>
#include <cuda_bf16.h>
#include <stdint.h>

// ---------------------------------------------------------------------------
// Swin-3D block on GB300. R10: tanh.approx gelu; attention PV single-pass
// (P bf16-rounded). Otherwise R9: inline mask, proj+LN2+mlp1 fusion, bf16
// activations, B split hi/lo 2-pass GEMMs.
// B=4, R=32, C=96, W=4, HEADS=4, dh=24, N=64/window, T=131072 tokens.
// ---------------------------------------------------------------------------

#define T_TOKENS 131072

// activations
__device__ __align__(16) unsigned short g_qkv[131072 * 288];  // bf16
__device__ __align__(16) unsigned short g_att[131072 * 96];   // bf16
__device__ float g_x[131072 * 96];                            // fp32 residual
__device__ __align__(16) unsigned short g_h1[131072 * 384];   // bf16

// split-precision transposed weights: layout [N][K], bf16 bits
__device__ __align__(16) unsigned short g_wqkv_hi[288 * 96], g_wqkv_lo[288 * 96];
__device__ __align__(16) unsigned short g_wproj_hi[96 * 96], g_wproj_lo[96 * 96];
__device__ __align__(16) unsigned short g_wm1_hi[384 * 96],  g_wm1_lo[384 * 96];
__device__ __align__(16) unsigned short g_wm2_hi[96 * 384],  g_wm2_lo[96 * 384];

// ---------------------------------------------------------------------------
__device__ __forceinline__ int box_to_token(int r) {
    int w = r >> 6, n = r & 63;
    int b  = w >> 9;
    int bi = (w >> 6) & 7, bj = (w >> 3) & 7, bk = w & 7;
    int wi = n >> 4, wj = (n >> 2) & 3, wk = n & 3;
    int i = (bi * 4 + wi + 2) & 31;
    int j = (bj * 4 + wj + 2) & 31;
    int k = (bk * 4 + wk + 2) & 31;
    return ((b * 32 + i) * 32 + j) * 32 + k;
}

__device__ __forceinline__ float tanh_fast(float x) {
    float y;
    asm("tanh.approx.f32 %0, %1;" : "=f"(y) : "f"(x));
    return y;
}

__device__ __forceinline__ float gelu_tanh(float x) {
    const float k0 = 0.7978845608028654f;
    const float k1 = 0.044715f;
    float x3 = x * x * x;
    float t = tanh_fast(k0 * (x + k1 * x3));
    return 0.5f * x * (1.0f + t);
}

__device__ __forceinline__ uint32_t smem_u32(const void* p) {
    uint32_t a;
    asm("{ .reg .u64 t; cvta.to.shared.u64 t, %1; cvt.u32.u64 %0, t; }"
        : "=r"(a) : "l"(p));
    return a;
}

__device__ __forceinline__ void ldmat4(uint32_t* r, uint32_t addr) {
    asm volatile("ldmatrix.sync.aligned.m8n8.x4.shared.b16 {%0,%1,%2,%3}, [%4];"
                 : "=r"(r[0]), "=r"(r[1]), "=r"(r[2]), "=r"(r[3]) : "r"(addr));
}

__device__ __forceinline__ void mma16816(float* d, const uint32_t* a,
                                         const uint32_t* b) {
    asm volatile(
        "mma.sync.aligned.m16n8k16.row.col.f32.bf16.bf16.f32 "
        "{%0,%1,%2,%3}, {%4,%5,%6,%7}, {%8,%9}, {%0,%1,%2,%3};"
        : "+f"(d[0]), "+f"(d[1]), "+f"(d[2]), "+f"(d[3])
        : "r"(a[0]), "r"(a[1]), "r"(a[2]), "r"(a[3]), "r"(b[0]), "r"(b[1]));
}

__device__ __forceinline__ void split_bf16(float x, unsigned short& h,
                                           unsigned short& l) {
    __nv_bfloat16 hb = __float2bfloat16(x);
    float r = x - __bfloat162float(hb);
    __nv_bfloat16 lb = __float2bfloat16(r);
    h = __bfloat16_as_ushort(hb);
    l = __bfloat16_as_ushort(lb);
}

__device__ __forceinline__ unsigned short to_bf16(float x) {
    return __bfloat16_as_ushort(__float2bfloat16(x));
}

__device__ __forceinline__ uint32_t pack_bf16x2(float a, float b) {
    return (uint32_t)to_bf16(a) | ((uint32_t)to_bf16(b) << 16);
}

__device__ __forceinline__ void cp_async16(uint32_t saddr, const void* g) {
    asm volatile("cp.async.ca.shared.global [%0], [%1], 16;"
                 :: "r"(saddr), "l"(g));
}
__device__ __forceinline__ void cp_commit() {
    asm volatile("cp.async.commit_group;" ::: "memory");
}
__device__ __forceinline__ void cp_wait0() {
    asm volatile("cp.async.wait_group 0;" ::: "memory");
}

// ---------------------------------------------------------------------------
// Weight prep, all 4 matrices in one launch. W[K,NTOT] -> Wt_hi/lo [NTOT][K].
// ---------------------------------------------------------------------------
__global__ void prep_all(const float* __restrict__ qkv_w,
                         const float* __restrict__ proj_w,
                         const float* __restrict__ w1,
                         const float* __restrict__ w2,
                         unsigned short* wqh, unsigned short* wql,
                         unsigned short* wph, unsigned short* wpl,
                         unsigned short* w1h, unsigned short* w1l,
                         unsigned short* w2h, unsigned short* w2l) {
    int idx = blockIdx.x * 256 + threadIdx.x;
    const float* W;
    unsigned short *hi, *lo;
    int K, NTOT, local;
    if (idx < 27648) {
        W = qkv_w; hi = wqh; lo = wql; K = 96; NTOT = 288; local = idx;
    } else if (idx < 36864) {
        W = proj_w; hi = wph; lo = wpl; K = 96; NTOT = 96; local = idx - 27648;
    } else if (idx < 73728) {
        W = w1; hi = w1h; lo = w1l; K = 96; NTOT = 384; local = idx - 36864;
    } else if (idx < 110592) {
        W = w2; hi = w2h; lo = w2l; K = 384; NTOT = 96; local = idx - 73728;
    } else return;
    int n = local / K, k = local - n * K;
    unsigned short h, l;
    split_bf16(W[(size_t)k * NTOT + n], h, l);
    hi[local] = h;
    lo[local] = l;
}

// ---------------------------------------------------------------------------
// Generic GEMM (qkv and mlp2): A bf16-exact, B split 2-pass.
// LN: 0 A bf16 gmem via cp.async | 1 LN + box gather (fp32 in)
// MODE: 0 bias, bf16 out | 3 0.5x+res, fp32 out
// ---------------------------------------------------------------------------
#define APAD 104
#define OFF_B 13312                   // B hi (u16 units)
#define BHALF 9984                    // 96*104
#define SMEM_U16 (13312 + 2 * 9984)   // 33280
#define SMEM_BYTES (SMEM_U16 * 2)     // 66560
#define SMEM_FUSED (SMEM_BYTES + 2048)

template <int KCH, int NCH, int LN, int MODE>
__global__ void __launch_bounds__(256, 2) mma_gemm(
    const void* __restrict__ Avoid,
    const float* __restrict__ gamma,
    const float* __restrict__ beta,
    const unsigned short* __restrict__ Whi,
    const unsigned short* __restrict__ Wlo,
    const float* __restrict__ bias,
    void* __restrict__ outv,
    const float* __restrict__ res) {
    extern __shared__ __align__(16) unsigned short sm[];
    const uint32_t sb = smem_u32(sm);
    constexpr int KTOT = 96 * KCH;
    constexpr int NTOT = 96 * NCH;
    constexpr int CH = KCH * NCH;
    constexpr bool OUTBF = (MODE == 0);

    int tid = threadIdx.x, lane = tid & 31, wid = tid >> 5;
    int warpM = wid >> 1, warpN = wid & 1;
    int rowBase = blockIdx.x * 128;

    int grp = lane >> 3, rin = lane & 7;
    int lrow = (grp & 1) * 8 + rin;
    int lkof = (grp >> 1) * 8;

    auto prefetchB = [&](int c) {
        int k = (KCH > 1) ? c : 0;
        int n = (KCH > 1) ? 0 : c;
#pragma unroll
        for (int it = 0; it < 9; it++) {
            int idx = it * 256 + tid;
            int half = idx >= 1152;
            int j = idx - half * 1152;
            int row = j / 12, seg = j - row * 12;
            const unsigned short* g =
                (half ? Wlo : Whi) + (size_t)(n * 96 + row) * KTOT + k * 96 + seg * 8;
            uint32_t sa = sb + 2 * (OFF_B + half * BHALF + row * APAD + seg * 8);
            cp_async16(sa, g);
        }
        cp_commit();
    };

    auto loadA = [&](int kchunk) {
        if (LN == 0) {
            const unsigned short* Ab = (const unsigned short*)Avoid;
            int kc = kchunk * 96;
#pragma unroll
            for (int it = 0; it < 6; it++) {
                int idx = it * 256 + tid;
                int r = idx / 12, seg = idx - r * 12;
                const unsigned short* g =
                    Ab + (size_t)(rowBase + r) * KTOT + kc + seg * 8;
                cp_async16(sb + 2 * (r * APAD + seg * 8), g);
            }
            cp_commit();
        } else {
            const float* A = (const float*)Avoid;
#pragma unroll
            for (int rr = 0; rr < 16; rr++) {
                int r = wid * 16 + rr;
                int gr = rowBase + r;
                int s = box_to_token(gr);
                const float* src = A + (size_t)s * 96;
                float v0 = src[lane], v1 = src[lane + 32], v2 = src[lane + 64];
                float s1 = v0 + v1 + v2;
                float s2 = v0 * v0 + v1 * v1 + v2 * v2;
#pragma unroll
                for (int o = 16; o; o >>= 1) {
                    s1 += __shfl_xor_sync(0xffffffffu, s1, o);
                    s2 += __shfl_xor_sync(0xffffffffu, s2, o);
                }
                float mean = s1 * (1.0f / 96.0f);
                float var  = s2 * (1.0f / 96.0f) - mean * mean;
                float inv  = rsqrtf(var + 1e-5f);
                int ro = r * APAD;
                sm[ro + lane] =
                    to_bf16((v0 - mean) * inv * gamma[lane] + beta[lane]);
                sm[ro + lane + 32] =
                    to_bf16((v1 - mean) * inv * gamma[lane + 32] + beta[lane + 32]);
                sm[ro + lane + 64] =
                    to_bf16((v2 - mean) * inv * gamma[lane + 64] + beta[lane + 64]);
            }
        }
    };

    float acc[2][6][4];
    auto resetAcc = [&]() {
#pragma unroll
        for (int mt = 0; mt < 2; mt++)
#pragma unroll
            for (int nt = 0; nt < 6; nt++)
#pragma unroll
                for (int i = 0; i < 4; i++) acc[mt][nt][i] = 0.f;
    };

    auto kloop = [&]() {
#pragma unroll
        for (int ks = 0; ks < 96; ks += 16) {
            uint32_t af[2][4];
#pragma unroll
            for (int mt = 0; mt < 2; mt++) {
                int r = warpM * 32 + mt * 16 + lrow;
                ldmat4(af[mt], sb + (uint32_t)(r * APAD + ks + lkof) * 2);
            }
            uint32_t bfh[6][2], bfl[6][2];
#pragma unroll
            for (int np = 0; np < 3; np++) {
                int n = warpN * 48 + np * 16 + lrow;
                uint32_t off = (uint32_t)(n * APAD + ks + lkof) * 2;
                uint32_t t4[4];
                ldmat4(t4, sb + OFF_B * 2 + off);
                bfh[np * 2][0] = t4[0]; bfh[np * 2][1] = t4[2];
                bfh[np * 2 + 1][0] = t4[1]; bfh[np * 2 + 1][1] = t4[3];
                ldmat4(t4, sb + (OFF_B + BHALF) * 2 + off);
                bfl[np * 2][0] = t4[0]; bfl[np * 2][1] = t4[2];
                bfl[np * 2 + 1][0] = t4[1]; bfl[np * 2 + 1][1] = t4[3];
            }
#pragma unroll
            for (int mt = 0; mt < 2; mt++)
#pragma unroll
                for (int nt = 0; nt < 6; nt++) {
                    mma16816(acc[mt][nt], af[mt], bfh[nt]);
                    mma16816(acc[mt][nt], af[mt], bfl[nt]);
                }
        }
    };

    auto epilogue = [&](int nchunk) {
        int colBase = nchunk * 96;
        int qr = lane >> 2, qc = (lane & 3) * 2;
#pragma unroll
        for (int mt = 0; mt < 2; mt++) {
#pragma unroll
            for (int half = 0; half < 2; half++) {
                int row = rowBase + warpM * 32 + mt * 16 + qr + half * 8;
#pragma unroll
                for (int nt = 0; nt < 6; nt++) {
                    int col = colBase + warpN * 48 + nt * 8 + qc;
                    float v0 = acc[mt][nt][half * 2 + 0] + bias[col];
                    float v1 = acc[mt][nt][half * 2 + 1] + bias[col + 1];
                    if (OUTBF) {
                        *(uint32_t*)((unsigned short*)outv +
                                     (size_t)row * NTOT + col) = pack_bf16x2(v0, v1);
                    } else {
                        const float* rr = res + (size_t)row * 96 + col;
                        float2 v = {0.5f * v0 + rr[0], 0.5f * v1 + rr[1]};
                        *(float2*)((float*)outv + (size_t)row * 96 + col) = v;
                    }
                }
            }
        }
    };

    prefetchB(0);
    loadA(0);
    cp_wait0();
    __syncthreads();

    if (KCH > 1) resetAcc();

    for (int c = 0; c < CH; c++) {
        if (NCH > 1 || CH == 1 || c == 0) resetAcc();
        kloop();
        if (c + 1 < CH) {
            __syncthreads();
            prefetchB(c + 1);
            if (KCH > 1) loadA(c + 1);
        }
        if (NCH > 1) epilogue(c);
        if (c + 1 < CH) {
            cp_wait0();
            __syncthreads();
        }
    }
    if (NCH == 1) epilogue(0);
}

// ---------------------------------------------------------------------------
// Fused proj + residual + LN2 + mlp1(+gelu). CTA = 128 box rows, 256 threads.
// ---------------------------------------------------------------------------
__global__ void __launch_bounds__(256, 2) fused_proj_mlp1(
    const unsigned short* __restrict__ att,
    const float* __restrict__ res,
    const unsigned short* __restrict__ Wp_hi,
    const unsigned short* __restrict__ Wp_lo,
    const float* __restrict__ proj_b,
    const float* __restrict__ n2g,
    const float* __restrict__ n2b,
    const unsigned short* __restrict__ W1_hi,
    const unsigned short* __restrict__ W1_lo,
    const float* __restrict__ b1,
    float* __restrict__ x,
    unsigned short* __restrict__ h1) {
    extern __shared__ __align__(16) unsigned short sm[];
    const uint32_t sb = smem_u32(sm);
    float* red = (float*)(sm + SMEM_U16);   // 128 rows * 4 floats

    int tid = threadIdx.x, lane = tid & 31, wid = tid >> 5;
    int warpM = wid >> 1, warpN = wid & 1;
    int rowBase = blockIdx.x * 128;

    int grp = lane >> 3, rin = lane & 7;
    int lrow = (grp & 1) * 8 + rin;
    int lkof = (grp >> 1) * 8;
    int qr = lane >> 2, qc = (lane & 3) * 2;

    auto prefetchB = [&](const unsigned short* Whi, const unsigned short* Wlo,
                         int n) {
#pragma unroll
        for (int it = 0; it < 9; it++) {
            int idx = it * 256 + tid;
            int half = idx >= 1152;
            int j = idx - half * 1152;
            int row = j / 12, seg = j - row * 12;
            const unsigned short* g =
                (half ? Wlo : Whi) + (size_t)(n * 96 + row) * 96 + seg * 8;
            uint32_t sa = sb + 2 * (OFF_B + half * BHALF + row * APAD + seg * 8);
            cp_async16(sa, g);
        }
        cp_commit();
    };

    float acc[2][6][4];
    auto resetAcc = [&]() {
#pragma unroll
        for (int mt = 0; mt < 2; mt++)
#pragma unroll
            for (int nt = 0; nt < 6; nt++)
#pragma unroll
                for (int i = 0; i < 4; i++) acc[mt][nt][i] = 0.f;
    };

    auto kloop = [&]() {
#pragma unroll
        for (int ks = 0; ks < 96; ks += 16) {
            uint32_t af[2][4];
#pragma unroll
            for (int mt = 0; mt < 2; mt++) {
                int r = warpM * 32 + mt * 16 + lrow;
                ldmat4(af[mt], sb + (uint32_t)(r * APAD + ks + lkof) * 2);
            }
            uint32_t bfh[6][2], bfl[6][2];
#pragma unroll
            for (int np = 0; np < 3; np++) {
                int n = warpN * 48 + np * 16 + lrow;
                uint32_t off = (uint32_t)(n * APAD + ks + lkof) * 2;
                uint32_t t4[4];
                ldmat4(t4, sb + OFF_B * 2 + off);
                bfh[np * 2][0] = t4[0]; bfh[np * 2][1] = t4[2];
                bfh[np * 2 + 1][0] = t4[1]; bfh[np * 2 + 1][1] = t4[3];
                ldmat4(t4, sb + (OFF_B + BHALF) * 2 + off);
                bfl[np * 2][0] = t4[0]; bfl[np * 2][1] = t4[2];
                bfl[np * 2 + 1][0] = t4[1]; bfl[np * 2 + 1][1] = t4[3];
            }
#pragma unroll
            for (int mt = 0; mt < 2; mt++)
#pragma unroll
                for (int nt = 0; nt < 6; nt++) {
                    mma16816(acc[mt][nt], af[mt], bfh[nt]);
                    mma16816(acc[mt][nt], af[mt], bfl[nt]);
                }
        }
    };

    // ---- phase A: proj ----
    prefetchB(Wp_hi, Wp_lo, 0);
    {
#pragma unroll
        for (int it = 0; it < 6; it++) {
            int idx = it * 256 + tid;
            int r = idx / 12, seg = idx - r * 12;
            cp_async16(sb + 2 * (r * APAD + seg * 8),
                       att + (size_t)(rowBase + r) * 96 + seg * 8);
        }
        cp_commit();
    }
    cp_wait0();
    __syncthreads();
    resetAcc();
    kloop();
    __syncthreads();
    prefetchB(W1_hi, W1_lo, 0);

    // ---- proj epilogue: x = 0.5*(acc+b) + res; keep in acc; row sums ----
#pragma unroll
    for (int mt = 0; mt < 2; mt++) {
#pragma unroll
        for (int half = 0; half < 2; half++) {
            int rl = warpM * 32 + mt * 16 + qr + half * 8;
            int t = box_to_token(rowBase + rl);
            const float* rr = res + (size_t)t * 96;
            float* xo = x + (size_t)t * 96;
            float rs1 = 0.f, rs2 = 0.f;
#pragma unroll
            for (int nt = 0; nt < 6; nt++) {
                int col = warpN * 48 + nt * 8 + qc;
                float v0 = acc[mt][nt][half * 2 + 0] + proj_b[col];
                float v1 = acc[mt][nt][half * 2 + 1] + proj_b[col + 1];
                v0 = 0.5f * v0 + rr[col];
                v1 = 0.5f * v1 + rr[col + 1];
                float2 v = {v0, v1};
                *(float2*)(xo + col) = v;
                acc[mt][nt][half * 2 + 0] = v0;
                acc[mt][nt][half * 2 + 1] = v1;
                rs1 += v0 + v1;
                rs2 += v0 * v0 + v1 * v1;
            }
            rs1 += __shfl_xor_sync(0xffffffffu, rs1, 1);
            rs1 += __shfl_xor_sync(0xffffffffu, rs1, 2);
            rs2 += __shfl_xor_sync(0xffffffffu, rs2, 1);
            rs2 += __shfl_xor_sync(0xffffffffu, rs2, 2);
            if ((lane & 3) == 0) {
                red[rl * 4 + warpN * 2 + 0] = rs1;
                red[rl * 4 + warpN * 2 + 1] = rs2;
            }
        }
    }
    __syncthreads();

    // ---- LN2: normalize acc, write bf16 A-tile ----
#pragma unroll
    for (int mt = 0; mt < 2; mt++) {
#pragma unroll
        for (int half = 0; half < 2; half++) {
            int rl = warpM * 32 + mt * 16 + qr + half * 8;
            float s1 = red[rl * 4 + 0] + red[rl * 4 + 2];
            float s2 = red[rl * 4 + 1] + red[rl * 4 + 3];
            float mean = s1 * (1.0f / 96.0f);
            float var  = s2 * (1.0f / 96.0f) - mean * mean;
            float inv  = rsqrtf(var + 1e-5f);
#pragma unroll
            for (int nt = 0; nt < 6; nt++) {
                int col = warpN * 48 + nt * 8 + qc;
                float y0 = (acc[mt][nt][half * 2 + 0] - mean) * inv * n2g[col]
                           + n2b[col];
                float y1 = (acc[mt][nt][half * 2 + 1] - mean) * inv * n2g[col + 1]
                           + n2b[col + 1];
                *(uint32_t*)(sm + rl * APAD + col) = pack_bf16x2(y0, y1);
            }
        }
    }
    cp_wait0();
    __syncthreads();

    // ---- phase B: mlp1, 4 slabs of 96 ----
    for (int c = 0; c < 4; c++) {
        resetAcc();
        kloop();
        if (c < 3) {
            __syncthreads();
            prefetchB(W1_hi, W1_lo, c + 1);
        }
#pragma unroll
        for (int mt = 0; mt < 2; mt++) {
#pragma unroll
            for (int half = 0; half < 2; half++) {
                int rl = warpM * 32 + mt * 16 + qr + half * 8;
                int t = box_to_token(rowBase + rl);
#pragma unroll
                for (int nt = 0; nt < 6; nt++) {
                    int col = c * 96 + warpN * 48 + nt * 8 + qc;
                    float v0 = gelu_tanh(acc[mt][nt][half * 2 + 0] + b1[col]);
                    float v1 = gelu_tanh(acc[mt][nt][half * 2 + 1] + b1[col + 1]);
                    *(uint32_t*)(h1 + (size_t)t * 384 + col) = pack_bf16x2(v0, v1);
                }
            }
        }
        if (c < 3) {
            cp_wait0();
            __syncthreads();
        }
    }
}

// ---------------------------------------------------------------------------
// Tensor-core windowed attention, inline mask, PV single-pass (P bf16).
// One CTA per (window, head), 128 threads.
// ---------------------------------------------------------------------------
__global__ void __launch_bounds__(128) attn_mma_kernel(
    const unsigned short* __restrict__ qkv,
    unsigned short* __restrict__ out) {
    __shared__ __align__(16) unsigned short q_s[64 * 40];
    __shared__ __align__(16) unsigned short k_s[64 * 40];
    __shared__ __align__(16) unsigned short vt[32 * 72];
    __shared__ unsigned char codes[64];

    int w = blockIdx.x >> 2, h = blockIdx.x & 3;
    int tid = threadIdx.x, lane = tid & 31, wid = tid >> 5;

    if (tid < 64) {
        int n = tid;
        int bi = (w >> 6) & 7, bj = (w >> 3) & 7, bk = w & 7;
        int wi = n >> 4, wj = (n >> 2) & 3, wk = n & 3;
        int rx = (bi == 7) ? ((wi < 2) ? 1 : 2) : 0;
        int ry = (bj == 7) ? ((wj < 2) ? 1 : 2) : 0;
        int rz = (bk == 7) ? ((wk < 2) ? 1 : 2) : 0;
        codes[n] = (unsigned char)(rx * 9 + ry * 3 + rz);
    }
#pragma unroll
    for (int it = 0; it < 16; it++) {
        int idx = it * 128 + tid;
        int t = idx >> 5, d = idx & 31;
        const unsigned short* base = qkv + (size_t)(w * 64 + t) * 288 + h * 24;
        unsigned short qv = 0, kv = 0, vv = 0;
        if (d < 24) {
            qv = base[d];
            kv = base[96 + d];
            vv = base[192 + d];
        }
        q_s[t * 40 + d] = qv;
        k_s[t * 40 + d] = kv;
        vt[d * 72 + t] = vv;
    }
    __syncthreads();

    const uint32_t sq = smem_u32(q_s), sk = smem_u32(k_s), sv = smem_u32(vt);

    int grp = lane >> 3, rin = lane & 7;
    int lrow = (grp & 1) * 8 + rin;
    int lkof = (grp >> 1) * 8;

    float sacc[8][4];
#pragma unroll
    for (int nt = 0; nt < 8; nt++)
#pragma unroll
        for (int i = 0; i < 4; i++) sacc[nt][i] = 0.f;

#pragma unroll
    for (int ks = 0; ks < 32; ks += 16) {
        uint32_t ah[4];
        ldmat4(ah, sq + (uint32_t)((wid * 16 + lrow) * 40 + ks + lkof) * 2);
#pragma unroll
        for (int np = 0; np < 4; np++) {
            uint32_t t4[4];
            ldmat4(t4, sk + (uint32_t)((np * 16 + lrow) * 40 + ks + lkof) * 2);
            uint32_t b0[2] = {t4[0], t4[2]}, b1r[2] = {t4[1], t4[3]};
            mma16816(sacc[np * 2], ah, b0);
            mma16816(sacc[np * 2 + 1], ah, b1r);
        }
    }

    const float scale = 0.2041241452319315f;
    int qr = lane >> 2, qc = (lane & 3) * 2;
    int row0 = wid * 16 + qr, row1 = row0 + 8;
    unsigned char c0 = codes[row0], c1 = codes[row1];

    float mx0 = -1e30f, mx1 = -1e30f;
#pragma unroll
    for (int nt = 0; nt < 8; nt++) {
#pragma unroll
        for (int c = 0; c < 2; c++) {
            int col = nt * 8 + qc + c;
            unsigned char cc = codes[col];
            float s0 = sacc[nt][c]     * scale + ((cc == c0) ? 0.f : -100.f);
            float s1 = sacc[nt][c + 2] * scale + ((cc == c1) ? 0.f : -100.f);
            sacc[nt][c]     = s0;
            sacc[nt][c + 2] = s1;
            mx0 = fmaxf(mx0, s0);
            mx1 = fmaxf(mx1, s1);
        }
    }
    mx0 = fmaxf(mx0, __shfl_xor_sync(0xffffffffu, mx0, 1));
    mx0 = fmaxf(mx0, __shfl_xor_sync(0xffffffffu, mx0, 2));
    mx1 = fmaxf(mx1, __shfl_xor_sync(0xffffffffu, mx1, 1));
    mx1 = fmaxf(mx1, __shfl_xor_sync(0xffffffffu, mx1, 2));

    float sum0 = 0.f, sum1 = 0.f;
    uint32_t p01[8], p23[8];
#pragma unroll
    for (int nt = 0; nt < 8; nt++) {
        float p0 = __expf(sacc[nt][0] - mx0);
        float p1 = __expf(sacc[nt][1] - mx0);
        float p2 = __expf(sacc[nt][2] - mx1);
        float p3 = __expf(sacc[nt][3] - mx1);
        sum0 += p0 + p1;
        sum1 += p2 + p3;
        p01[nt] = pack_bf16x2(p0, p1);
        p23[nt] = pack_bf16x2(p2, p3);
    }
    sum0 += __shfl_xor_sync(0xffffffffu, sum0, 1);
    sum0 += __shfl_xor_sync(0xffffffffu, sum0, 2);
    sum1 += __shfl_xor_sync(0xffffffffu, sum1, 1);
    sum1 += __shfl_xor_sync(0xffffffffu, sum1, 2);
    float inv0 = 1.f / sum0, inv1 = 1.f / sum1;

    float oacc[3][4];
#pragma unroll
    for (int nt = 0; nt < 3; nt++)
#pragma unroll
        for (int i = 0; i < 4; i++) oacc[nt][i] = 0.f;

#pragma unroll
    for (int ks = 0; ks < 4; ks++) {
        uint32_t Ap[4] = {p01[2 * ks], p23[2 * ks], p01[2 * ks + 1], p23[2 * ks + 1]};
        uint32_t boff0 = (uint32_t)(lrow * 72 + ks * 16 + lkof) * 2;
        uint32_t boff1 = (uint32_t)((16 + lrow) * 72 + ks * 16 + lkof) * 2;
        uint32_t t4[4];
        uint32_t bh[3][2];
        ldmat4(t4, sv + boff0);
        bh[0][0] = t4[0]; bh[0][1] = t4[2];
        bh[1][0] = t4[1]; bh[1][1] = t4[3];
        ldmat4(t4, sv + boff1);
        bh[2][0] = t4[0]; bh[2][1] = t4[2];
#pragma unroll
        for (int nt = 0; nt < 3; nt++)
            mma16816(oacc[nt], Ap, bh[nt]);
    }

#pragma unroll
    for (int nt = 0; nt < 3; nt++) {
        int col = h * 24 + nt * 8 + qc;
        *(uint32_t*)(out + (size_t)(w * 64 + row0) * 96 + col) =
            pack_bf16x2(oacc[nt][0] * inv0, oacc[nt][1] * inv0);
        *(uint32_t*)(out + (size_t)(w * 64 + row1) * 96 + col) =
            pack_bf16x2(oacc[nt][2] * inv1, oacc[nt][3] * inv1);
    }
}

// ---------------------------------------------------------------------------
extern "C" void kernel_launch(void* const* d_in, const int* in_sizes, int n_in,
                              void* d_out, int out_size) {
    const float* inputs = (const float*)d_in[0];
    const float* n1g    = (const float*)d_in[1];
    const float* n1b    = (const float*)d_in[2];
    const float* qkv_w  = (const float*)d_in[3];
    const float* qkv_b  = (const float*)d_in[4];
    const float* proj_w = (const float*)d_in[5];
    const float* proj_b = (const float*)d_in[6];
    const float* n2g    = (const float*)d_in[7];
    const float* n2b    = (const float*)d_in[8];
    const float* w1     = (const float*)d_in[9];
    const float* b1     = (const float*)d_in[10];
    const float* w2     = (const float*)d_in[11];
    const float* b2     = (const float*)d_in[12];
    float* out = (float*)d_out;

    unsigned short *qkv, *att, *h1;
    float* x;
    cudaGetSymbolAddress((void**)&qkv, g_qkv);
    cudaGetSymbolAddress((void**)&att, g_att);
    cudaGetSymbolAddress((void**)&x,   g_x);
    cudaGetSymbolAddress((void**)&h1,  g_h1);

    unsigned short *wqh, *wql, *wph, *wpl, *w1h, *w1l, *w2h, *w2l;
    cudaGetSymbolAddress((void**)&wqh, g_wqkv_hi);
    cudaGetSymbolAddress((void**)&wql, g_wqkv_lo);
    cudaGetSymbolAddress((void**)&wph, g_wproj_hi);
    cudaGetSymbolAddress((void**)&wpl, g_wproj_lo);
    cudaGetSymbolAddress((void**)&w1h, g_wm1_hi);
    cudaGetSymbolAddress((void**)&w1l, g_wm1_lo);
    cudaGetSymbolAddress((void**)&w2h, g_wm2_hi);
    cudaGetSymbolAddress((void**)&w2l, g_wm2_lo);

    cudaFuncSetAttribute(mma_gemm<1, 3, 1, 0>,
                         cudaFuncAttributeMaxDynamicSharedMemorySize, SMEM_BYTES);
    cudaFuncSetAttribute(mma_gemm<4, 1, 0, 3>,
                         cudaFuncAttributeMaxDynamicSharedMemorySize, SMEM_BYTES);
    cudaFuncSetAttribute(fused_proj_mlp1,
                         cudaFuncAttributeMaxDynamicSharedMemorySize, SMEM_FUSED);

    // 0. weight prep
    prep_all<<<432, 256>>>(qkv_w, proj_w, w1, w2,
                           wqh, wql, wph, wpl, w1h, w1l, w2h, w2l);
    // 1. LN1 (fused) + box partition + QKV -> bf16
    mma_gemm<1, 3, 1, 0><<<1024, 256, SMEM_BYTES>>>(
        inputs, n1g, n1b, wqh, wql, qkv_b, qkv, nullptr);
    // 2. Windowed attention (inline mask)
    attn_mma_kernel<<<8192, 128>>>(qkv, att);
    // 3. Fused proj + residual + LN2 + MLP1 + gelu -> x, h1
    fused_proj_mlp1<<<1024, 256, SMEM_FUSED>>>(
        att, inputs, wph, wpl, proj_b, n2g, n2b, w1h, w1l, b1, x, h1);
    // 4. MLP2 + 0.5x + residual -> out
    mma_gemm<4, 1, 0, 3><<<1024, 256, SMEM_BYTES>>>(
        h1, nullptr, nullptr, w2h, w2l, b2, out, x);
}

// round 17
// speedup vs baseline: 6.2853x; 1.2515x over previous
#include <cuda_runtime.h>
#include <cuda_bf16.h>
#include <stdint.h>

// ---------------------------------------------------------------------------
// Swin-3D block on GB300. R14: single-pass bf16 MMA everywhere (weights
// bf16-rounded; the hi/lo weight split is dropped — measured error budget
// shows bf16 rounding of GEMM inputs contributes ~5e-5 total). Inline mask,
// proj+LN2+mlp1 fusion, bf16 activations, tanh.approx gelu.
// B=4, R=32, C=96, W=4, HEADS=4, dh=24, N=64/window, T=131072 tokens.
// ---------------------------------------------------------------------------

#define T_TOKENS 131072

// activations
__device__ __align__(16) unsigned short g_qkv[131072 * 288];  // bf16
__device__ __align__(16) unsigned short g_att[131072 * 96];   // bf16
__device__ float g_x[131072 * 96];                            // fp32 residual
__device__ __align__(16) unsigned short g_h1[131072 * 384];   // bf16

// transposed bf16 weights: layout [N][K]
__device__ __align__(16) unsigned short g_wqkv[288 * 96];
__device__ __align__(16) unsigned short g_wproj[96 * 96];
__device__ __align__(16) unsigned short g_wm1[384 * 96];
__device__ __align__(16) unsigned short g_wm2[96 * 384];

// ---------------------------------------------------------------------------
__device__ __forceinline__ int box_to_token(int r) {
    int w = r >> 6, n = r & 63;
    int b  = w >> 9;
    int bi = (w >> 6) & 7, bj = (w >> 3) & 7, bk = w & 7;
    int wi = n >> 4, wj = (n >> 2) & 3, wk = n & 3;
    int i = (bi * 4 + wi + 2) & 31;
    int j = (bj * 4 + wj + 2) & 31;
    int k = (bk * 4 + wk + 2) & 31;
    return ((b * 32 + i) * 32 + j) * 32 + k;
}

__device__ __forceinline__ float tanh_fast(float x) {
    float y;
    asm("tanh.approx.f32 %0, %1;" : "=f"(y) : "f"(x));
    return y;
}

__device__ __forceinline__ float gelu_tanh(float x) {
    const float k0 = 0.7978845608028654f;
    const float k1 = 0.044715f;
    float x3 = x * x * x;
    float t = tanh_fast(k0 * (x + k1 * x3));
    return 0.5f * x * (1.0f + t);
}

__device__ __forceinline__ uint32_t smem_u32(const void* p) {
    uint32_t a;
    asm("{ .reg .u64 t; cvta.to.shared.u64 t, %1; cvt.u32.u64 %0, t; }"
        : "=r"(a) : "l"(p));
    return a;
}

__device__ __forceinline__ void ldmat4(uint32_t* r, uint32_t addr) {
    asm volatile("ldmatrix.sync.aligned.m8n8.x4.shared.b16 {%0,%1,%2,%3}, [%4];"
                 : "=r"(r[0]), "=r"(r[1]), "=r"(r[2]), "=r"(r[3]) : "r"(addr));
}

__device__ __forceinline__ void mma16816(float* d, const uint32_t* a,
                                         const uint32_t* b) {
    asm volatile(
        "mma.sync.aligned.m16n8k16.row.col.f32.bf16.bf16.f32 "
        "{%0,%1,%2,%3}, {%4,%5,%6,%7}, {%8,%9}, {%0,%1,%2,%3};"
        : "+f"(d[0]), "+f"(d[1]), "+f"(d[2]), "+f"(d[3])
        : "r"(a[0]), "r"(a[1]), "r"(a[2]), "r"(a[3]), "r"(b[0]), "r"(b[1]));
}

__device__ __forceinline__ unsigned short to_bf16(float x) {
    return __bfloat16_as_ushort(__float2bfloat16(x));
}

__device__ __forceinline__ uint32_t pack_bf16x2(float a, float b) {
    return (uint32_t)to_bf16(a) | ((uint32_t)to_bf16(b) << 16);
}

__device__ __forceinline__ void cp_async16(uint32_t saddr, const void* g) {
    asm volatile("cp.async.ca.shared.global [%0], [%1], 16;"
                 :: "r"(saddr), "l"(g));
}
__device__ __forceinline__ void cp_commit() {
    asm volatile("cp.async.commit_group;" ::: "memory");
}
__device__ __forceinline__ void cp_wait0() {
    asm volatile("cp.async.wait_group 0;" ::: "memory");
}

// ---------------------------------------------------------------------------
// Weight prep: transpose + round to bf16, all 4 matrices in one launch.
// ---------------------------------------------------------------------------
__global__ void prep_all(const float* __restrict__ qkv_w,
                         const float* __restrict__ proj_w,
                         const float* __restrict__ w1,
                         const float* __restrict__ w2,
                         unsigned short* wq, unsigned short* wp,
                         unsigned short* wm1, unsigned short* wm2) {
    int idx = blockIdx.x * 256 + threadIdx.x;
    const float* W;
    unsigned short* dst;
    int K, NTOT, local;
    if (idx < 27648) {
        W = qkv_w; dst = wq; K = 96; NTOT = 288; local = idx;
    } else if (idx < 36864) {
        W = proj_w; dst = wp; K = 96; NTOT = 96; local = idx - 27648;
    } else if (idx < 73728) {
        W = w1; dst = wm1; K = 96; NTOT = 384; local = idx - 36864;
    } else if (idx < 110592) {
        W = w2; dst = wm2; K = 384; NTOT = 96; local = idx - 73728;
    } else return;
    int n = local / K, k = local - n * K;
    dst[local] = to_bf16(W[(size_t)k * NTOT + n]);
}

// ---------------------------------------------------------------------------
// Generic GEMM (qkv and mlp2): A bf16, B bf16, single-pass MMA.
// LN: 0 A bf16 gmem via cp.async | 1 LN + box gather (fp32 in)
// MODE: 0 bias, bf16 out | 3 0.5x+res, fp32 out
// ---------------------------------------------------------------------------
#define APAD 104
#define OFF_B 13312                   // B (u16 units)
#define SMEM_U16 (13312 + 9984)       // 23296
#define SMEM_BYTES (SMEM_U16 * 2)     // 46592
#define SMEM_FUSED (SMEM_BYTES + 2048)

template <int KCH, int NCH, int LN, int MODE>
__global__ void __launch_bounds__(256, 2) mma_gemm(
    const void* __restrict__ Avoid,
    const float* __restrict__ gamma,
    const float* __restrict__ beta,
    const unsigned short* __restrict__ Wt,
    const float* __restrict__ bias,
    void* __restrict__ outv,
    const float* __restrict__ res) {
    extern __shared__ __align__(16) unsigned short sm[];
    const uint32_t sb = smem_u32(sm);
    constexpr int KTOT = 96 * KCH;
    constexpr int NTOT = 96 * NCH;
    constexpr int CH = KCH * NCH;
    constexpr bool OUTBF = (MODE == 0);

    int tid = threadIdx.x, lane = tid & 31, wid = tid >> 5;
    int warpM = wid >> 1, warpN = wid & 1;
    int rowBase = blockIdx.x * 128;

    int grp = lane >> 3, rin = lane & 7;
    int lrow = (grp & 1) * 8 + rin;
    int lkof = (grp >> 1) * 8;

    auto prefetchB = [&](int c) {
        int k = (KCH > 1) ? c : 0;
        int n = (KCH > 1) ? 0 : c;
#pragma unroll
        for (int it = 0; it < 5; it++) {
            int idx = it * 256 + tid;            // 0..1151 used
            if (idx < 1152) {
                int row = idx / 12, seg = idx - row * 12;
                const unsigned short* g =
                    Wt + (size_t)(n * 96 + row) * KTOT + k * 96 + seg * 8;
                cp_async16(sb + 2 * (OFF_B + row * APAD + seg * 8), g);
            }
        }
        cp_commit();
    };

    auto loadA = [&](int kchunk) {
        if (LN == 0) {
            const unsigned short* Ab = (const unsigned short*)Avoid;
            int kc = kchunk * 96;
#pragma unroll
            for (int it = 0; it < 6; it++) {
                int idx = it * 256 + tid;
                int r = idx / 12, seg = idx - r * 12;
                const unsigned short* g =
                    Ab + (size_t)(rowBase + r) * KTOT + kc + seg * 8;
                cp_async16(sb + 2 * (r * APAD + seg * 8), g);
            }
            cp_commit();
        } else {
            const float* A = (const float*)Avoid;
#pragma unroll
            for (int rr = 0; rr < 16; rr++) {
                int r = wid * 16 + rr;
                int gr = rowBase + r;
                int s = box_to_token(gr);
                const float* src = A + (size_t)s * 96;
                float v0 = src[lane], v1 = src[lane + 32], v2 = src[lane + 64];
                float s1 = v0 + v1 + v2;
                float s2 = v0 * v0 + v1 * v1 + v2 * v2;
#pragma unroll
                for (int o = 16; o; o >>= 1) {
                    s1 += __shfl_xor_sync(0xffffffffu, s1, o);
                    s2 += __shfl_xor_sync(0xffffffffu, s2, o);
                }
                float mean = s1 * (1.0f / 96.0f);
                float var  = s2 * (1.0f / 96.0f) - mean * mean;
                float inv  = rsqrtf(var + 1e-5f);
                int ro = r * APAD;
                sm[ro + lane] =
                    to_bf16((v0 - mean) * inv * gamma[lane] + beta[lane]);
                sm[ro + lane + 32] =
                    to_bf16((v1 - mean) * inv * gamma[lane + 32] + beta[lane + 32]);
                sm[ro + lane + 64] =
                    to_bf16((v2 - mean) * inv * gamma[lane + 64] + beta[lane + 64]);
            }
        }
    };

    float acc[2][6][4];
    auto resetAcc = [&]() {
#pragma unroll
        for (int mt = 0; mt < 2; mt++)
#pragma unroll
            for (int nt = 0; nt < 6; nt++)
#pragma unroll
                for (int i = 0; i < 4; i++) acc[mt][nt][i] = 0.f;
    };

    auto kloop = [&]() {
#pragma unroll
        for (int ks = 0; ks < 96; ks += 16) {
            uint32_t af[2][4];
#pragma unroll
            for (int mt = 0; mt < 2; mt++) {
                int r = warpM * 32 + mt * 16 + lrow;
                ldmat4(af[mt], sb + (uint32_t)(r * APAD + ks + lkof) * 2);
            }
            uint32_t bf[6][2];
#pragma unroll
            for (int np = 0; np < 3; np++) {
                int n = warpN * 48 + np * 16 + lrow;
                uint32_t t4[4];
                ldmat4(t4, sb + OFF_B * 2 + (uint32_t)(n * APAD + ks + lkof) * 2);
                bf[np * 2][0] = t4[0]; bf[np * 2][1] = t4[2];
                bf[np * 2 + 1][0] = t4[1]; bf[np * 2 + 1][1] = t4[3];
            }
#pragma unroll
            for (int mt = 0; mt < 2; mt++)
#pragma unroll
                for (int nt = 0; nt < 6; nt++)
                    mma16816(acc[mt][nt], af[mt], bf[nt]);
        }
    };

    auto epilogue = [&](int nchunk) {
        int colBase = nchunk * 96;
        int qr = lane >> 2, qc = (lane & 3) * 2;
#pragma unroll
        for (int mt = 0; mt < 2; mt++) {
#pragma unroll
            for (int half = 0; half < 2; half++) {
                int row = rowBase + warpM * 32 + mt * 16 + qr + half * 8;
#pragma unroll
                for (int nt = 0; nt < 6; nt++) {
                    int col = colBase + warpN * 48 + nt * 8 + qc;
                    float v0 = acc[mt][nt][half * 2 + 0] + bias[col];
                    float v1 = acc[mt][nt][half * 2 + 1] + bias[col + 1];
                    if (OUTBF) {
                        *(uint32_t*)((unsigned short*)outv +
                                     (size_t)row * NTOT + col) = pack_bf16x2(v0, v1);
                    } else {
                        const float* rr = res + (size_t)row * 96 + col;
                        float2 v = {0.5f * v0 + rr[0], 0.5f * v1 + rr[1]};
                        *(float2*)((float*)outv + (size_t)row * 96 + col) = v;
                    }
                }
            }
        }
    };

    prefetchB(0);
    loadA(0);
    cp_wait0();
    __syncthreads();

    if (KCH > 1) resetAcc();

    for (int c = 0; c < CH; c++) {
        if (NCH > 1 || CH == 1 || c == 0) resetAcc();
        kloop();
        if (c + 1 < CH) {
            __syncthreads();
            prefetchB(c + 1);
            if (KCH > 1) loadA(c + 1);
        }
        if (NCH > 1) epilogue(c);
        if (c + 1 < CH) {
            cp_wait0();
            __syncthreads();
        }
    }
    if (NCH == 1) epilogue(0);
}

// ---------------------------------------------------------------------------
// Fused proj + residual + LN2 + mlp1(+gelu). CTA = 128 box rows, 256 threads.
// ---------------------------------------------------------------------------
__global__ void __launch_bounds__(256, 2) fused_proj_mlp1(
    const unsigned short* __restrict__ att,
    const float* __restrict__ res,
    const unsigned short* __restrict__ Wp,
    const float* __restrict__ proj_b,
    const float* __restrict__ n2g,
    const float* __restrict__ n2b,
    const unsigned short* __restrict__ W1,
    const float* __restrict__ b1,
    float* __restrict__ x,
    unsigned short* __restrict__ h1) {
    extern __shared__ __align__(16) unsigned short sm[];
    const uint32_t sb = smem_u32(sm);
    float* red = (float*)(sm + SMEM_U16);   // 128 rows * 4 floats

    int tid = threadIdx.x, lane = tid & 31, wid = tid >> 5;
    int warpM = wid >> 1, warpN = wid & 1;
    int rowBase = blockIdx.x * 128;

    int grp = lane >> 3, rin = lane & 7;
    int lrow = (grp & 1) * 8 + rin;
    int lkof = (grp >> 1) * 8;
    int qr = lane >> 2, qc = (lane & 3) * 2;

    auto prefetchB = [&](const unsigned short* Wt, int n) {
#pragma unroll
        for (int it = 0; it < 5; it++) {
            int idx = it * 256 + tid;
            if (idx < 1152) {
                int row = idx / 12, seg = idx - row * 12;
                const unsigned short* g =
                    Wt + (size_t)(n * 96 + row) * 96 + seg * 8;
                cp_async16(sb + 2 * (OFF_B + row * APAD + seg * 8), g);
            }
        }
        cp_commit();
    };

    float acc[2][6][4];
    auto resetAcc = [&]() {
#pragma unroll
        for (int mt = 0; mt < 2; mt++)
#pragma unroll
            for (int nt = 0; nt < 6; nt++)
#pragma unroll
                for (int i = 0; i < 4; i++) acc[mt][nt][i] = 0.f;
    };

    auto kloop = [&]() {
#pragma unroll
        for (int ks = 0; ks < 96; ks += 16) {
            uint32_t af[2][4];
#pragma unroll
            for (int mt = 0; mt < 2; mt++) {
                int r = warpM * 32 + mt * 16 + lrow;
                ldmat4(af[mt], sb + (uint32_t)(r * APAD + ks + lkof) * 2);
            }
            uint32_t bf[6][2];
#pragma unroll
            for (int np = 0; np < 3; np++) {
                int n = warpN * 48 + np * 16 + lrow;
                uint32_t t4[4];
                ldmat4(t4, sb + OFF_B * 2 + (uint32_t)(n * APAD + ks + lkof) * 2);
                bf[np * 2][0] = t4[0]; bf[np * 2][1] = t4[2];
                bf[np * 2 + 1][0] = t4[1]; bf[np * 2 + 1][1] = t4[3];
            }
#pragma unroll
            for (int mt = 0; mt < 2; mt++)
#pragma unroll
                for (int nt = 0; nt < 6; nt++)
                    mma16816(acc[mt][nt], af[mt], bf[nt]);
        }
    };

    // ---- phase A: proj ----
    prefetchB(Wp, 0);
    {
#pragma unroll
        for (int it = 0; it < 6; it++) {
            int idx = it * 256 + tid;
            int r = idx / 12, seg = idx - r * 12;
            cp_async16(sb + 2 * (r * APAD + seg * 8),
                       att + (size_t)(rowBase + r) * 96 + seg * 8);
        }
        cp_commit();
    }
    cp_wait0();
    __syncthreads();
    resetAcc();
    kloop();
    __syncthreads();
    prefetchB(W1, 0);

    // ---- proj epilogue: x = 0.5*(acc+b) + res; keep in acc; row sums ----
#pragma unroll
    for (int mt = 0; mt < 2; mt++) {
#pragma unroll
        for (int half = 0; half < 2; half++) {
            int rl = warpM * 32 + mt * 16 + qr + half * 8;
            int t = box_to_token(rowBase + rl);
            const float* rr = res + (size_t)t * 96;
            float* xo = x + (size_t)t * 96;
            float rs1 = 0.f, rs2 = 0.f;
#pragma unroll
            for (int nt = 0; nt < 6; nt++) {
                int col = warpN * 48 + nt * 8 + qc;
                float v0 = acc[mt][nt][half * 2 + 0] + proj_b[col];
                float v1 = acc[mt][nt][half * 2 + 1] + proj_b[col + 1];
                v0 = 0.5f * v0 + rr[col];
                v1 = 0.5f * v1 + rr[col + 1];
                float2 v = {v0, v1};
                *(float2*)(xo + col) = v;
                acc[mt][nt][half * 2 + 0] = v0;
                acc[mt][nt][half * 2 + 1] = v1;
                rs1 += v0 + v1;
                rs2 += v0 * v0 + v1 * v1;
            }
            rs1 += __shfl_xor_sync(0xffffffffu, rs1, 1);
            rs1 += __shfl_xor_sync(0xffffffffu, rs1, 2);
            rs2 += __shfl_xor_sync(0xffffffffu, rs2, 1);
            rs2 += __shfl_xor_sync(0xffffffffu, rs2, 2);
            if ((lane & 3) == 0) {
                red[rl * 4 + warpN * 2 + 0] = rs1;
                red[rl * 4 + warpN * 2 + 1] = rs2;
            }
        }
    }
    __syncthreads();

    // ---- LN2: normalize acc, write bf16 A-tile ----
#pragma unroll
    for (int mt = 0; mt < 2; mt++) {
#pragma unroll
        for (int half = 0; half < 2; half++) {
            int rl = warpM * 32 + mt * 16 + qr + half * 8;
            float s1 = red[rl * 4 + 0] + red[rl * 4 + 2];
            float s2 = red[rl * 4 + 1] + red[rl * 4 + 3];
            float mean = s1 * (1.0f / 96.0f);
            float var  = s2 * (1.0f / 96.0f) - mean * mean;
            float inv  = rsqrtf(var + 1e-5f);
#pragma unroll
            for (int nt = 0; nt < 6; nt++) {
                int col = warpN * 48 + nt * 8 + qc;
                float y0 = (acc[mt][nt][half * 2 + 0] - mean) * inv * n2g[col]
                           + n2b[col];
                float y1 = (acc[mt][nt][half * 2 + 1] - mean) * inv * n2g[col + 1]
                           + n2b[col + 1];
                *(uint32_t*)(sm + rl * APAD + col) = pack_bf16x2(y0, y1);
            }
        }
    }
    cp_wait0();
    __syncthreads();

    // ---- phase B: mlp1, 4 slabs of 96 ----
    for (int c = 0; c < 4; c++) {
        resetAcc();
        kloop();
        if (c < 3) {
            __syncthreads();
            prefetchB(W1, c + 1);
        }
#pragma unroll
        for (int mt = 0; mt < 2; mt++) {
#pragma unroll
            for (int half = 0; half < 2; half++) {
                int rl = warpM * 32 + mt * 16 + qr + half * 8;
                int t = box_to_token(rowBase + rl);
#pragma unroll
                for (int nt = 0; nt < 6; nt++) {
                    int col = c * 96 + warpN * 48 + nt * 8 + qc;
                    float v0 = gelu_tanh(acc[mt][nt][half * 2 + 0] + b1[col]);
                    float v1 = gelu_tanh(acc[mt][nt][half * 2 + 1] + b1[col + 1]);
                    *(uint32_t*)(h1 + (size_t)t * 384 + col) = pack_bf16x2(v0, v1);
                }
            }
        }
        if (c < 3) {
            cp_wait0();
            __syncthreads();
        }
    }
}

// ---------------------------------------------------------------------------
// Tensor-core windowed attention, inline mask, PV single-pass (P bf16).
// One CTA per (window, head), 128 threads.
// ---------------------------------------------------------------------------
__global__ void __launch_bounds__(128) attn_mma_kernel(
    const unsigned short* __restrict__ qkv,
    unsigned short* __restrict__ out) {
    __shared__ __align__(16) unsigned short q_s[64 * 40];
    __shared__ __align__(16) unsigned short k_s[64 * 40];
    __shared__ __align__(16) unsigned short vt[32 * 72];
    __shared__ unsigned char codes[64];

    int w = blockIdx.x >> 2, h = blockIdx.x & 3;
    int tid = threadIdx.x, lane = tid & 31, wid = tid >> 5;

    if (tid < 64) {
        int n = tid;
        int bi = (w >> 6) & 7, bj = (w >> 3) & 7, bk = w & 7;
        int wi = n >> 4, wj = (n >> 2) & 3, wk = n & 3;
        int rx = (bi == 7) ? ((wi < 2) ? 1 : 2) : 0;
        int ry = (bj == 7) ? ((wj < 2) ? 1 : 2) : 0;
        int rz = (bk == 7) ? ((wk < 2) ? 1 : 2) : 0;
        codes[n] = (unsigned char)(rx * 9 + ry * 3 + rz);
    }
#pragma unroll
    for (int it = 0; it < 16; it++) {
        int idx = it * 128 + tid;
        int t = idx >> 5, d = idx & 31;
        const unsigned short* base = qkv + (size_t)(w * 64 + t) * 288 + h * 24;
        unsigned short qv = 0, kv = 0, vv = 0;
        if (d < 24) {
            qv = base[d];
            kv = base[96 + d];
            vv = base[192 + d];
        }
        q_s[t * 40 + d] = qv;
        k_s[t * 40 + d] = kv;
        vt[d * 72 + t] = vv;
    }
    __syncthreads();

    const uint32_t sq = smem_u32(q_s), sk = smem_u32(k_s), sv = smem_u32(vt);

    int grp = lane >> 3, rin = lane & 7;
    int lrow = (grp & 1) * 8 + rin;
    int lkof = (grp >> 1) * 8;

    float sacc[8][4];
#pragma unroll
    for (int nt = 0; nt < 8; nt++)
#pragma unroll
        for (int i = 0; i < 4; i++) sacc[nt][i] = 0.f;

#pragma unroll
    for (int ks = 0; ks < 32; ks += 16) {
        uint32_t ah[4];
        ldmat4(ah, sq + (uint32_t)((wid * 16 + lrow) * 40 + ks + lkof) * 2);
#pragma unroll
        for (int np = 0; np < 4; np++) {
            uint32_t t4[4];
            ldmat4(t4, sk + (uint32_t)((np * 16 + lrow) * 40 + ks + lkof) * 2);
            uint32_t b0[2] = {t4[0], t4[2]}, b1r[2] = {t4[1], t4[3]};
            mma16816(sacc[np * 2], ah, b0);
            mma16816(sacc[np * 2 + 1], ah, b1r);
        }
    }

    const float scale = 0.2041241452319315f;
    int qr = lane >> 2, qc = (lane & 3) * 2;
    int row0 = wid * 16 + qr, row1 = row0 + 8;
    unsigned char c0 = codes[row0], c1 = codes[row1];

    float mx0 = -1e30f, mx1 = -1e30f;
#pragma unroll
    for (int nt = 0; nt < 8; nt++) {
#pragma unroll
        for (int c = 0; c < 2; c++) {
            int col = nt * 8 + qc + c;
            unsigned char cc = codes[col];
            float s0 = sacc[nt][c]     * scale + ((cc == c0) ? 0.f : -100.f);
            float s1 = sacc[nt][c + 2] * scale + ((cc == c1) ? 0.f : -100.f);
            sacc[nt][c]     = s0;
            sacc[nt][c + 2] = s1;
            mx0 = fmaxf(mx0, s0);
            mx1 = fmaxf(mx1, s1);
        }
    }
    mx0 = fmaxf(mx0, __shfl_xor_sync(0xffffffffu, mx0, 1));
    mx0 = fmaxf(mx0, __shfl_xor_sync(0xffffffffu, mx0, 2));
    mx1 = fmaxf(mx1, __shfl_xor_sync(0xffffffffu, mx1, 1));
    mx1 = fmaxf(mx1, __shfl_xor_sync(0xffffffffu, mx1, 2));

    float sum0 = 0.f, sum1 = 0.f;
    uint32_t p01[8], p23[8];
#pragma unroll
    for (int nt = 0; nt < 8; nt++) {
        float p0 = __expf(sacc[nt][0] - mx0);
        float p1 = __expf(sacc[nt][1] - mx0);
        float p2 = __expf(sacc[nt][2] - mx1);
        float p3 = __expf(sacc[nt][3] - mx1);
        sum0 += p0 + p1;
        sum1 += p2 + p3;
        p01[nt] = pack_bf16x2(p0, p1);
        p23[nt] = pack_bf16x2(p2, p3);
    }
    sum0 += __shfl_xor_sync(0xffffffffu, sum0, 1);
    sum0 += __shfl_xor_sync(0xffffffffu, sum0, 2);
    sum1 += __shfl_xor_sync(0xffffffffu, sum1, 1);
    sum1 += __shfl_xor_sync(0xffffffffu, sum1, 2);
    float inv0 = 1.f / sum0, inv1 = 1.f / sum1;

    float oacc[3][4];
#pragma unroll
    for (int nt = 0; nt < 3; nt++)
#pragma unroll
        for (int i = 0; i < 4; i++) oacc[nt][i] = 0.f;

#pragma unroll
    for (int ks = 0; ks < 4; ks++) {
        uint32_t Ap[4] = {p01[2 * ks], p23[2 * ks], p01[2 * ks + 1], p23[2 * ks + 1]};
        uint32_t boff0 = (uint32_t)(lrow * 72 + ks * 16 + lkof) * 2;
        uint32_t boff1 = (uint32_t)((16 + lrow) * 72 + ks * 16 + lkof) * 2;
        uint32_t t4[4];
        uint32_t bh[3][2];
        ldmat4(t4, sv + boff0);
        bh[0][0] = t4[0]; bh[0][1] = t4[2];
        bh[1][0] = t4[1]; bh[1][1] = t4[3];
        ldmat4(t4, sv + boff1);
        bh[2][0] = t4[0]; bh[2][1] = t4[2];
#pragma unroll
        for (int nt = 0; nt < 3; nt++)
            mma16816(oacc[nt], Ap, bh[nt]);
    }

#pragma unroll
    for (int nt = 0; nt < 3; nt++) {
        int col = h * 24 + nt * 8 + qc;
        *(uint32_t*)(out + (size_t)(w * 64 + row0) * 96 + col) =
            pack_bf16x2(oacc[nt][0] * inv0, oacc[nt][1] * inv0);
        *(uint32_t*)(out + (size_t)(w * 64 + row1) * 96 + col) =
            pack_bf16x2(oacc[nt][2] * inv1, oacc[nt][3] * inv1);
    }
}

// ---------------------------------------------------------------------------
extern "C" void kernel_launch(void* const* d_in, const int* in_sizes, int n_in,
                              void* d_out, int out_size) {
    const float* inputs = (const float*)d_in[0];
    const float* n1g    = (const float*)d_in[1];
    const float* n1b    = (const float*)d_in[2];
    const float* qkv_w  = (const float*)d_in[3];
    const float* qkv_b  = (const float*)d_in[4];
    const float* proj_w = (const float*)d_in[5];
    const float* proj_b = (const float*)d_in[6];
    const float* n2g    = (const float*)d_in[7];
    const float* n2b    = (const float*)d_in[8];
    const float* w1     = (const float*)d_in[9];
    const float* b1     = (const float*)d_in[10];
    const float* w2     = (const float*)d_in[11];
    const float* b2     = (const float*)d_in[12];
    float* out = (float*)d_out;

    unsigned short *qkv, *att, *h1;
    float* x;
    cudaGetSymbolAddress((void**)&qkv, g_qkv);
    cudaGetSymbolAddress((void**)&att, g_att);
    cudaGetSymbolAddress((void**)&x,   g_x);
    cudaGetSymbolAddress((void**)&h1,  g_h1);

    unsigned short *wq, *wp, *wm1, *wm2;
    cudaGetSymbolAddress((void**)&wq,  g_wqkv);
    cudaGetSymbolAddress((void**)&wp,  g_wproj);
    cudaGetSymbolAddress((void**)&wm1, g_wm1);
    cudaGetSymbolAddress((void**)&wm2, g_wm2);

    cudaFuncSetAttribute(mma_gemm<1, 3, 1, 0>,
                         cudaFuncAttributeMaxDynamicSharedMemorySize, SMEM_BYTES);
    cudaFuncSetAttribute(mma_gemm<4, 1, 0, 3>,
                         cudaFuncAttributeMaxDynamicSharedMemorySize, SMEM_BYTES);
    cudaFuncSetAttribute(fused_proj_mlp1,
                         cudaFuncAttributeMaxDynamicSharedMemorySize, SMEM_FUSED);

    // 0. weight prep (transpose + bf16)
    prep_all<<<432, 256>>>(qkv_w, proj_w, w1, w2, wq, wp, wm1, wm2);
    // 1. LN1 (fused) + box partition + QKV -> bf16
    mma_gemm<1, 3, 1, 0><<<1024, 256, SMEM_BYTES>>>(
        inputs, n1g, n1b, wq, qkv_b, qkv, nullptr);
    // 2. Windowed attention (inline mask)
    attn_mma_kernel<<<8192, 128>>>(qkv, att);
    // 3. Fused proj + residual + LN2 + MLP1 + gelu -> x, h1
    fused_proj_mlp1<<<1024, 256, SMEM_FUSED>>>(
        att, inputs, wp, proj_b, n2g, n2b, wm1, b1, x, h1);
    // 4. MLP2 + 0.5x + residual -> out
    mma_gemm<4, 1, 0, 3><<<1024, 256, SMEM_BYTES>>>(
        h1, nullptr, nullptr, wm2, b2, out, x);
}